// round 1
// baseline (speedup 1.0000x reference)
#include <cuda_runtime.h>
#include <cuda_bf16.h>
#include <math.h>

// Problem constants
#define BSZ 4
#define SEQ 2048
#define DM 1024
#define NH 16
#define HD 64
#define MB 32
#define ROWS_TOTAL (BSZ * SEQ)          // 8192
#define SCALE 0.17677669529663687f      // 1/sqrt(32)

// ---------------------------------------------------------------------------
// Scratch (no allocations allowed -> __device__ globals)
// ---------------------------------------------------------------------------
__device__ __align__(16) float g_Q[ROWS_TOTAL * DM];
__device__ __align__(16) float g_K[ROWS_TOTAL * DM];
__device__ __align__(16) float g_V[ROWS_TOTAL * DM];
__device__ __align__(16) float g_QE[ROWS_TOTAL * NH * MB];
__device__ __align__(16) float g_KE[ROWS_TOTAL * NH * MB];
__device__ __align__(16) float g_AO[ROWS_TOTAL * DM];

// ---------------------------------------------------------------------------
// SGEMM: C[m,n] = sum_k A[m*K+k] * B[n*K+k]   (A:[M,K], B:[N,K] both K-major)
// BM=BN=128, BK=16, 256 threads, 8x8 microtile
// ---------------------------------------------------------------------------
__global__ __launch_bounds__(256) void sgemm_abT(
    const float* __restrict__ A, const float* __restrict__ B,
    float* __restrict__ C, int M, int Nc, int K)
{
    __shared__ __align__(16) float As[16][128];
    __shared__ __align__(16) float Bs[16][128];

    const int tid  = threadIdx.x;
    const int brow = blockIdx.y * 128;
    const int bcol = blockIdx.x * 128;
    const int tr   = (tid >> 4) << 3;   // 0..120 step 8
    const int tc   = (tid & 15) << 3;   // 0..120 step 8

    float acc[8][8];
#pragma unroll
    for (int i = 0; i < 8; i++)
#pragma unroll
        for (int j = 0; j < 8; j++) acc[i][j] = 0.f;

    for (int kt = 0; kt < K; kt += 16) {
#pragma unroll
        for (int i = 0; i < 2; i++) {
            int idx = tid + i * 256;     // 0..511
            int r   = idx >> 2;          // 0..127
            int kq  = (idx & 3) << 2;    // 0,4,8,12
            float4 va = *(const float4*)&A[(size_t)(brow + r) * K + kt + kq];
            As[kq + 0][r] = va.x; As[kq + 1][r] = va.y;
            As[kq + 2][r] = va.z; As[kq + 3][r] = va.w;
            float4 vb = *(const float4*)&B[(size_t)(bcol + r) * K + kt + kq];
            Bs[kq + 0][r] = vb.x; Bs[kq + 1][r] = vb.y;
            Bs[kq + 2][r] = vb.z; Bs[kq + 3][r] = vb.w;
        }
        __syncthreads();

#pragma unroll
        for (int k = 0; k < 16; k++) {
            float a[8], b[8];
            *(float4*)&a[0] = *(const float4*)&As[k][tr];
            *(float4*)&a[4] = *(const float4*)&As[k][tr + 4];
            *(float4*)&b[0] = *(const float4*)&Bs[k][tc];
            *(float4*)&b[4] = *(const float4*)&Bs[k][tc + 4];
#pragma unroll
            for (int i = 0; i < 8; i++)
#pragma unroll
                for (int j = 0; j < 8; j++)
                    acc[i][j] = fmaf(a[i], b[j], acc[i][j]);
        }
        __syncthreads();
    }

#pragma unroll
    for (int i = 0; i < 8; i++) {
        float* cp = &C[(size_t)(brow + tr + i) * Nc + bcol + tc];
        *(float4*)&cp[0] = *(const float4*)&acc[i][0];
        *(float4*)&cp[4] = *(const float4*)&acc[i][4];
    }
}

// ---------------------------------------------------------------------------
// Witness encoder: E[row, h, m] = tanh( sum_d X[row, h*64+d] * Wenc[h, d, m] )
// block: (row chunk of 64, head). 256 threads.
// ---------------------------------------------------------------------------
__global__ __launch_bounds__(256) void enc_kernel(
    const float* __restrict__ X, const float* __restrict__ Wenc,
    float* __restrict__ E)
{
    __shared__ __align__(16) float Ws[HD][MB];   // 8 KB
    __shared__ __align__(16) float Qs[64][HD];   // 16 KB

    const int tid  = threadIdx.x;
    const int h    = blockIdx.y;
    const int row0 = blockIdx.x * 64;

    for (int i = tid; i < HD * MB; i += 256)
        Ws[i >> 5][i & 31] = Wenc[h * HD * MB + i];

#pragma unroll
    for (int i = 0; i < 4; i++) {
        int idx = tid + i * 256;     // 0..1023 float4s
        int r = idx >> 4;
        int c = (idx & 15) << 2;
        *(float4*)&Qs[r][c] =
            *(const float4*)&X[(size_t)(row0 + r) * DM + h * HD + c];
    }
    __syncthreads();

#pragma unroll
    for (int i = 0; i < 8; i++) {
        int o = tid + i * 256;       // 0..2047
        int r = o >> 5;
        int m = o & 31;
        float s = 0.f;
#pragma unroll
        for (int d = 0; d < HD; d++) s = fmaf(Qs[r][d], Ws[d][m], s);
        E[((size_t)(row0 + r) * NH + h) * MB + m] = tanhf(s);
    }
}

// ---------------------------------------------------------------------------
// Flash attention over witness scores.
// grid: (SEQ/128, NH, BSZ). 256 threads: 2 threads per q-row, each owns 32 V dims.
// ---------------------------------------------------------------------------
__global__ __launch_bounds__(256) void attn_kernel(
    const float* __restrict__ QE, const float* __restrict__ KE,
    const float* __restrict__ V, float* __restrict__ O)
{
    __shared__ __align__(16) float Ks[64][MB];   // 8 KB
    __shared__ __align__(16) float Vs[64][HD];   // 16 KB

    const int tid  = threadIdx.x;
    const int half = tid & 1;
    const int lrow = tid >> 1;                     // 0..127
    const int h = blockIdx.y;
    const int b = blockIdx.z;
    const size_t base = (size_t)b * SEQ;
    const int row = blockIdx.x * 128 + lrow;

    float qv[16];
    {
        const float* qp = &QE[((base + row) * NH + h) * MB + half * 16];
#pragma unroll
        for (int j = 0; j < 16; j++) qv[j] = qp[j];
    }

    float acc[32];
#pragma unroll
    for (int d = 0; d < 32; d++) acc[d] = 0.f;
    float mmax = -1e30f, l = 0.f;

    for (int kt = 0; kt < SEQ; kt += 64) {
        __syncthreads();
#pragma unroll
        for (int i = 0; i < 2; i++) {
            int idx = tid + i * 256;   // 0..511 float4s
            int r = idx >> 3;
            int c = (idx & 7) << 2;
            *(float4*)&Ks[r][c] =
                *(const float4*)&KE[((base + kt + r) * NH + h) * MB + c];
        }
#pragma unroll
        for (int i = 0; i < 4; i++) {
            int idx = tid + i * 256;   // 0..1023 float4s
            int r = idx >> 4;
            int c = (idx & 15) << 2;
            *(float4*)&Vs[r][c] =
                *(const float4*)&V[(base + kt + r) * DM + h * HD + c];
        }
        __syncthreads();

#pragma unroll 2
        for (int kk = 0; kk < 64; kk++) {
            float part = 0.f;
            const float* kr = &Ks[kk][half * 16];
#pragma unroll
            for (int j = 0; j < 16; j++) part = fmaf(qv[j], kr[j], part);
            float s = (part + __shfl_xor_sync(0xffffffffu, part, 1)) * SCALE;
            float mnew = fmaxf(mmax, s);
            float corr = __expf(mmax - mnew);
            float p    = __expf(s - mnew);
            l = l * corr + p;
            const float* vr = &Vs[kk][half * 32];
#pragma unroll
            for (int d = 0; d < 32; d++)
                acc[d] = fmaf(acc[d], corr, p * vr[d]);
            mmax = mnew;
        }
    }

    float inv = 1.f / l;
    float* op = &O[(base + row) * DM + h * HD + half * 32];
#pragma unroll
    for (int d = 0; d < 32; d += 4) {
        float4 v4 = make_float4(acc[d] * inv, acc[d + 1] * inv,
                                acc[d + 2] * inv, acc[d + 3] * inv);
        *(float4*)&op[d] = v4;
    }
}

// ---------------------------------------------------------------------------
// Launch
// ---------------------------------------------------------------------------
extern "C" void kernel_launch(void* const* d_in, const int* in_sizes, int n_in,
                              void* d_out, int out_size)
{
    const float* x    = (const float*)d_in[0];
    const float* Wq   = (const float*)d_in[1];
    const float* Wk   = (const float*)d_in[2];
    const float* Wv   = (const float*)d_in[3];
    const float* Wenc = (const float*)d_in[4];
    const float* Wo   = (const float*)d_in[5];
    float* out = (float*)d_out;

    float *Qp, *Kp, *Vp, *QEp, *KEp, *AOp;
    cudaGetSymbolAddress((void**)&Qp,  g_Q);
    cudaGetSymbolAddress((void**)&Kp,  g_K);
    cudaGetSymbolAddress((void**)&Vp,  g_V);
    cudaGetSymbolAddress((void**)&QEp, g_QE);
    cudaGetSymbolAddress((void**)&KEp, g_KE);
    cudaGetSymbolAddress((void**)&AOp, g_AO);

    dim3 gGemm(DM / 128, ROWS_TOTAL / 128);   // (8, 64)
    sgemm_abT<<<gGemm, 256>>>(x, Wq, Qp, ROWS_TOTAL, DM, DM);
    sgemm_abT<<<gGemm, 256>>>(x, Wk, Kp, ROWS_TOTAL, DM, DM);
    sgemm_abT<<<gGemm, 256>>>(x, Wv, Vp, ROWS_TOTAL, DM, DM);

    dim3 gEnc(ROWS_TOTAL / 64, NH);           // (128, 16)
    enc_kernel<<<gEnc, 256>>>(Qp, Wenc, QEp);
    enc_kernel<<<gEnc, 256>>>(Kp, Wenc, KEp);

    dim3 gAttn(SEQ / 128, NH, BSZ);           // (16, 16, 4)
    attn_kernel<<<gAttn, 256>>>(QEp, KEp, Vp, AOp);

    sgemm_abT<<<gGemm, 256>>>(AOp, Wo, out, ROWS_TOTAL, DM, DM);
}

// round 3
// speedup vs baseline: 1.2332x; 1.2332x over previous
#include <cuda_runtime.h>
#include <cuda_bf16.h>
#include <math.h>
#include <stdint.h>

// Problem constants
#define BSZ 4
#define SEQ 2048
#define DM 1024
#define NH 16
#define HD 64
#define MB 32
#define ROWS_TOTAL (BSZ * SEQ)          // 8192
#define SCALE 0.17677669529663687f      // 1/sqrt(32)
#define SMAX 5.656854249492380f         // 32/sqrt(32) upper bound on |score|

// ---------------------------------------------------------------------------
// Scratch (no allocations allowed -> __device__ globals)
// ---------------------------------------------------------------------------
__device__ __align__(16) float g_Q[ROWS_TOTAL * DM];
__device__ __align__(16) float g_K[ROWS_TOTAL * DM];
__device__ __align__(16) float g_V[ROWS_TOTAL * DM];
__device__ __align__(16) float g_QE[ROWS_TOTAL * NH * MB];
__device__ __align__(16) float g_KE[ROWS_TOTAL * NH * MB];
__device__ __align__(16) float g_AO[ROWS_TOTAL * DM];

// ---------------------------------------------------------------------------
// Helpers
// ---------------------------------------------------------------------------
static __device__ __forceinline__ uint32_t smem_u32(const void* p) {
    return (uint32_t)__cvta_generic_to_shared(p);
}

static __device__ __forceinline__ uint32_t pack2bf(float a, float b) {
    __nv_bfloat162 t = __floats2bfloat162_rn(a, b);
    return *(uint32_t*)&t;
}

static __device__ __forceinline__ void ldmx4(uint32_t& r0, uint32_t& r1,
                                             uint32_t& r2, uint32_t& r3,
                                             uint32_t addr) {
    asm volatile("ldmatrix.sync.aligned.m8n8.x4.shared.b16 {%0,%1,%2,%3}, [%4];"
                 : "=r"(r0), "=r"(r1), "=r"(r2), "=r"(r3) : "r"(addr));
}

static __device__ __forceinline__ void mma16816(float* d, const uint32_t* a,
                                                const uint32_t* b) {
    asm volatile(
        "mma.sync.aligned.m16n8k16.row.col.f32.bf16.bf16.f32 "
        "{%0,%1,%2,%3}, {%4,%5,%6,%7}, {%8,%9}, {%0,%1,%2,%3};"
        : "+f"(d[0]), "+f"(d[1]), "+f"(d[2]), "+f"(d[3])
        : "r"(a[0]), "r"(a[1]), "r"(a[2]), "r"(a[3]), "r"(b[0]), "r"(b[1]));
}

// convert float4 -> hi/lo bf16 pairs
static __device__ __forceinline__ void split4(float4 v, uint2& hv, uint2& lv) {
    __nv_bfloat16 h0 = __float2bfloat16(v.x), h1 = __float2bfloat16(v.y);
    __nv_bfloat16 h2 = __float2bfloat16(v.z), h3 = __float2bfloat16(v.w);
    float l0 = v.x - __bfloat162float(h0), l1 = v.y - __bfloat162float(h1);
    float l2 = v.z - __bfloat162float(h2), l3 = v.w - __bfloat162float(h3);
    hv.x = pack2bf(__bfloat162float(h0), __bfloat162float(h1));
    hv.y = pack2bf(__bfloat162float(h2), __bfloat162float(h3));
    lv.x = pack2bf(l0, l1);
    lv.y = pack2bf(l2, l3);
}

// ---------------------------------------------------------------------------
// Tensor-core GEMM via mma.sync (legacy path, works on compute_103):
// C[m,n] = sum_k A[m,k]*B[n,k];  A:[M,1024], B:[1024,1024], both K-major.
// 128x128 CTA tile, BK=32, 8 warps (4M x 2N), 3-term bf16 hi/lo split.
// ---------------------------------------------------------------------------
#define KP 40   // padded row length in bf16 elems (32 data + 8 pad)

__global__ __launch_bounds__(256, 1) void gemm_tc(
    const float* __restrict__ A, const float* __restrict__ B, float* __restrict__ C)
{
    __shared__ __align__(16) __nv_bfloat16 sAh[128 * KP];
    __shared__ __align__(16) __nv_bfloat16 sAl[128 * KP];
    __shared__ __align__(16) __nv_bfloat16 sBh[128 * KP];
    __shared__ __align__(16) __nv_bfloat16 sBl[128 * KP];

    const int tid  = threadIdx.x;
    const int wid  = tid >> 5;
    const int lane = tid & 31;
    const int brow = blockIdx.y * 128;
    const int bcol = blockIdx.x * 128;
    const int wm   = (wid & 3) * 32;     // warp M offset
    const int wn   = (wid >> 2) * 64;    // warp N offset

    float acc[2][8][4];
#pragma unroll
    for (int mi = 0; mi < 2; mi++)
#pragma unroll
        for (int ni = 0; ni < 8; ni++)
#pragma unroll
            for (int j = 0; j < 4; j++) acc[mi][ni][j] = 0.f;

    // ldmatrix base addresses (per-lane row pointers)
    const int fr = lane & 15;            // fragment row
    const int fc = (lane >> 4) << 3;     // 0 or 8 (k offset)

    for (int kt = 0; kt < 32; kt++) {
        // ---- stage tile: gmem fp32 -> smem bf16 hi/lo ----
        const float* Ab = A + (size_t)brow * DM + kt * 32;
        const float* Bb = B + (size_t)bcol * DM + kt * 32;
#pragma unroll
        for (int i = 0; i < 4; i++) {
            int idx = tid + i * 256;     // 0..1023
            int r = idx >> 3;            // 0..127
            int c = (idx & 7) << 2;      // 0..28
            uint2 hv, lv;
            split4(*(const float4*)(Ab + (size_t)r * DM + c), hv, lv);
            *(uint2*)&sAh[r * KP + c] = hv;
            *(uint2*)&sAl[r * KP + c] = lv;
            split4(*(const float4*)(Bb + (size_t)r * DM + c), hv, lv);
            *(uint2*)&sBh[r * KP + c] = hv;
            *(uint2*)&sBl[r * KP + c] = lv;
        }
        __syncthreads();

        // ---- compute: 2 k16 steps ----
#pragma unroll
        for (int ks = 0; ks < 2; ks++) {
            const int kof = ks * 16 + fc;
            uint32_t ah[2][4], al[2][4];
#pragma unroll
            for (int mi = 0; mi < 2; mi++) {
                uint32_t ra = smem_u32(&sAh[(wm + mi * 16 + fr) * KP + kof]);
                ldmx4(ah[mi][0], ah[mi][1], ah[mi][2], ah[mi][3], ra);
                uint32_t rl = smem_u32(&sAl[(wm + mi * 16 + fr) * KP + kof]);
                ldmx4(al[mi][0], al[mi][1], al[mi][2], al[mi][3], rl);
            }
            uint32_t bh[8][2], bl[8][2];
#pragma unroll
            for (int nq = 0; nq < 4; nq++) {
                uint32_t r0, r1, r2, r3;
                uint32_t rb = smem_u32(&sBh[(wn + nq * 16 + fr) * KP + kof]);
                ldmx4(r0, r1, r2, r3, rb);
                bh[nq * 2 + 0][0] = r0; bh[nq * 2 + 0][1] = r2;
                bh[nq * 2 + 1][0] = r1; bh[nq * 2 + 1][1] = r3;
                uint32_t rb2 = smem_u32(&sBl[(wn + nq * 16 + fr) * KP + kof]);
                ldmx4(r0, r1, r2, r3, rb2);
                bl[nq * 2 + 0][0] = r0; bl[nq * 2 + 0][1] = r2;
                bl[nq * 2 + 1][0] = r1; bl[nq * 2 + 1][1] = r3;
            }
#pragma unroll
            for (int mi = 0; mi < 2; mi++)
#pragma unroll
                for (int ni = 0; ni < 8; ni++) {
                    mma16816(acc[mi][ni], ah[mi], bh[ni]);
                    mma16816(acc[mi][ni], ah[mi], bl[ni]);
                    mma16816(acc[mi][ni], al[mi], bh[ni]);
                }
        }
        __syncthreads();
    }

    // ---- epilogue: d-frag layout m16n8: row=(lane>>2)(+8), col=(lane&3)*2(+1)
    const int er = lane >> 2;
    const int ec = (lane & 3) * 2;
#pragma unroll
    for (int mi = 0; mi < 2; mi++) {
#pragma unroll
        for (int ni = 0; ni < 8; ni++) {
            float* cp0 = C + (size_t)(brow + wm + mi * 16 + er) * DM + bcol + wn + ni * 8 + ec;
            *(float2*)cp0 = make_float2(acc[mi][ni][0], acc[mi][ni][1]);
            float* cp1 = cp0 + 8 * DM;
            *(float2*)cp1 = make_float2(acc[mi][ni][2], acc[mi][ni][3]);
        }
    }
}

// ---------------------------------------------------------------------------
// Witness encoder: E[row, h, m] = tanh( sum_d X[row, h*64+d] * Wenc[h, d, m] )
// ---------------------------------------------------------------------------
__global__ __launch_bounds__(256) void enc_kernel(
    const float* __restrict__ X, const float* __restrict__ Wenc,
    float* __restrict__ E)
{
    __shared__ __align__(16) float Ws[HD][MB];   // 8 KB
    __shared__ __align__(16) float Qs[64][HD];   // 16 KB

    const int tid  = threadIdx.x;
    const int h    = blockIdx.y;
    const int row0 = blockIdx.x * 64;

    for (int i = tid; i < HD * MB; i += 256)
        Ws[i >> 5][i & 31] = Wenc[h * HD * MB + i];

#pragma unroll
    for (int i = 0; i < 4; i++) {
        int idx = tid + i * 256;
        int r = idx >> 4;
        int c = (idx & 15) << 2;
        *(float4*)&Qs[r][c] =
            *(const float4*)&X[(size_t)(row0 + r) * DM + h * HD + c];
    }
    __syncthreads();

#pragma unroll
    for (int i = 0; i < 8; i++) {
        int o = tid + i * 256;
        int r = o >> 5;
        int m = o & 31;
        float s = 0.f;
#pragma unroll
        for (int d = 0; d < HD; d++) s = fmaf(Qs[r][d], Ws[d][m], s);
        E[((size_t)(row0 + r) * NH + h) * MB + m] = tanhf(s);
    }
}

// ---------------------------------------------------------------------------
// Flash attention over witness scores — fixed-max softmax (|s| <= SMAX).
// grid: (SEQ/128, NH, BSZ). 256 threads: 2 threads per q-row, 32 V dims each.
// ---------------------------------------------------------------------------
__global__ __launch_bounds__(256) void attn_kernel(
    const float* __restrict__ QE, const float* __restrict__ KE,
    const float* __restrict__ V, float* __restrict__ O)
{
    __shared__ __align__(16) float Ks[64][MB];   // 8 KB
    __shared__ __align__(16) float Vs[64][HD];   // 16 KB

    const int tid  = threadIdx.x;
    const int half = tid & 1;
    const int lrow = tid >> 1;                     // 0..127
    const int h = blockIdx.y;
    const int b = blockIdx.z;
    const size_t base = (size_t)b * SEQ;
    const int row = blockIdx.x * 128 + lrow;

    float qv[16];
    {
        const float* qp = &QE[((base + row) * NH + h) * MB + half * 16];
#pragma unroll
        for (int j = 0; j < 16; j++) qv[j] = qp[j] * SCALE;   // fold scale into q
    }

    float acc[32];
#pragma unroll
    for (int d = 0; d < 32; d++) acc[d] = 0.f;
    float l = 0.f;

    for (int kt = 0; kt < SEQ; kt += 64) {
        __syncthreads();
#pragma unroll
        for (int i = 0; i < 2; i++) {
            int idx = tid + i * 256;
            int r = idx >> 3;
            int c = (idx & 7) << 2;
            *(float4*)&Ks[r][c] =
                *(const float4*)&KE[((base + kt + r) * NH + h) * MB + c];
        }
#pragma unroll
        for (int i = 0; i < 4; i++) {
            int idx = tid + i * 256;
            int r = idx >> 4;
            int c = (idx & 15) << 2;
            *(float4*)&Vs[r][c] =
                *(const float4*)&V[(base + kt + r) * DM + h * HD + c];
        }
        __syncthreads();

#pragma unroll 4
        for (int kk = 0; kk < 64; kk++) {
            float part = 0.f;
            const float* kr = &Ks[kk][half * 16];
#pragma unroll
            for (int j = 0; j < 16; j++) part = fmaf(qv[j], kr[j], part);
            float s = part + __shfl_xor_sync(0xffffffffu, part, 1);
            float p = __expf(s - SMAX);     // bounded: no online max needed
            l += p;
            const float* vr = &Vs[kk][half * 32];
#pragma unroll
            for (int d = 0; d < 32; d++)
                acc[d] = fmaf(p, vr[d], acc[d]);
        }
    }

    float inv = 1.f / l;
    float* op = &O[(base + row) * DM + h * HD + half * 32];
#pragma unroll
    for (int d = 0; d < 32; d += 4) {
        float4 v4 = make_float4(acc[d] * inv, acc[d + 1] * inv,
                                acc[d + 2] * inv, acc[d + 3] * inv);
        *(float4*)&op[d] = v4;
    }
}

// ---------------------------------------------------------------------------
// Launch
// ---------------------------------------------------------------------------
extern "C" void kernel_launch(void* const* d_in, const int* in_sizes, int n_in,
                              void* d_out, int out_size)
{
    const float* x    = (const float*)d_in[0];
    const float* Wq   = (const float*)d_in[1];
    const float* Wk   = (const float*)d_in[2];
    const float* Wv   = (const float*)d_in[3];
    const float* Wenc = (const float*)d_in[4];
    const float* Wo   = (const float*)d_in[5];
    float* out = (float*)d_out;

    float *Qp, *Kp, *Vp, *QEp, *KEp, *AOp;
    cudaGetSymbolAddress((void**)&Qp,  g_Q);
    cudaGetSymbolAddress((void**)&Kp,  g_K);
    cudaGetSymbolAddress((void**)&Vp,  g_V);
    cudaGetSymbolAddress((void**)&QEp, g_QE);
    cudaGetSymbolAddress((void**)&KEp, g_KE);
    cudaGetSymbolAddress((void**)&AOp, g_AO);

    dim3 gGemm(DM / 128, ROWS_TOTAL / 128);   // (8, 64)
    gemm_tc<<<gGemm, 256>>>(x, Wq, Qp);
    gemm_tc<<<gGemm, 256>>>(x, Wk, Kp);
    gemm_tc<<<gGemm, 256>>>(x, Wv, Vp);

    dim3 gEnc(ROWS_TOTAL / 64, NH);           // (128, 16)
    enc_kernel<<<gEnc, 256>>>(Qp, Wenc, QEp);
    enc_kernel<<<gEnc, 256>>>(Kp, Wenc, KEp);

    dim3 gAttn(SEQ / 128, NH, BSZ);           // (16, 16, 4)
    attn_kernel<<<gAttn, 256>>>(QEp, KEp, Vp, AOp);

    gemm_tc<<<gGemm, 256>>>(AOp, Wo, out);
}

// round 4
// speedup vs baseline: 2.8929x; 2.3459x over previous
#include <cuda_runtime.h>
#include <cuda_bf16.h>
#include <math.h>
#include <stdint.h>

// Problem constants
#define BSZ 4
#define SEQ 2048
#define DM 1024
#define NH 16
#define HD 64
#define MB 32
#define ROWS_TOTAL (BSZ * SEQ)          // 8192
#define SCALE 0.17677669529663687f      // 1/sqrt(32)
#define SMAX 5.656854249492380f         // 32/sqrt(32) upper bound on |score|

// ---------------------------------------------------------------------------
// Scratch (no allocations allowed -> __device__ globals)
// ---------------------------------------------------------------------------
__device__ __align__(16) float g_Q[ROWS_TOTAL * DM];
__device__ __align__(16) float g_K[ROWS_TOTAL * DM];
__device__ __align__(16) float g_V[ROWS_TOTAL * DM];
__device__ __align__(16) __nv_bfloat16 g_xh[ROWS_TOTAL * DM];
__device__ __align__(16) __nv_bfloat16 g_xl[ROWS_TOTAL * DM];
__device__ __align__(16) __nv_bfloat16 g_Vh[ROWS_TOTAL * DM];
__device__ __align__(16) __nv_bfloat16 g_Vl[ROWS_TOTAL * DM];
__device__ __align__(16) __nv_bfloat16 g_AOh[ROWS_TOTAL * DM];
__device__ __align__(16) __nv_bfloat16 g_AOl[ROWS_TOTAL * DM];
__device__ __align__(16) __nv_bfloat16 g_QEh[ROWS_TOTAL * NH * MB];
__device__ __align__(16) __nv_bfloat16 g_QEl[ROWS_TOTAL * NH * MB];
__device__ __align__(16) __nv_bfloat16 g_KEh[ROWS_TOTAL * NH * MB];
__device__ __align__(16) __nv_bfloat16 g_KEl[ROWS_TOTAL * NH * MB];
__device__ __align__(16) __nv_bfloat16 g_Wqh[DM * DM];
__device__ __align__(16) __nv_bfloat16 g_Wql[DM * DM];
__device__ __align__(16) __nv_bfloat16 g_Wkh[DM * DM];
__device__ __align__(16) __nv_bfloat16 g_Wkl[DM * DM];
__device__ __align__(16) __nv_bfloat16 g_Wvh[DM * DM];
__device__ __align__(16) __nv_bfloat16 g_Wvl[DM * DM];
__device__ __align__(16) __nv_bfloat16 g_Woh[DM * DM];
__device__ __align__(16) __nv_bfloat16 g_Wol[DM * DM];

// ---------------------------------------------------------------------------
// Helpers
// ---------------------------------------------------------------------------
static __device__ __forceinline__ uint32_t smem_u32(const void* p) {
    return (uint32_t)__cvta_generic_to_shared(p);
}

static __device__ __forceinline__ uint32_t pack2bf(float a, float b) {
    __nv_bfloat162 t = __floats2bfloat162_rn(a, b);
    return *(uint32_t*)&t;
}

static __device__ __forceinline__ void ldmx4(uint32_t& r0, uint32_t& r1,
                                             uint32_t& r2, uint32_t& r3,
                                             uint32_t addr) {
    asm volatile("ldmatrix.sync.aligned.m8n8.x4.shared.b16 {%0,%1,%2,%3}, [%4];"
                 : "=r"(r0), "=r"(r1), "=r"(r2), "=r"(r3) : "r"(addr));
}

static __device__ __forceinline__ void ldmx4t(uint32_t& r0, uint32_t& r1,
                                              uint32_t& r2, uint32_t& r3,
                                              uint32_t addr) {
    asm volatile("ldmatrix.sync.aligned.m8n8.x4.trans.shared.b16 {%0,%1,%2,%3}, [%4];"
                 : "=r"(r0), "=r"(r1), "=r"(r2), "=r"(r3) : "r"(addr));
}

static __device__ __forceinline__ void mma16816(float* d, const uint32_t* a,
                                                const uint32_t* b) {
    asm volatile(
        "mma.sync.aligned.m16n8k16.row.col.f32.bf16.bf16.f32 "
        "{%0,%1,%2,%3}, {%4,%5,%6,%7}, {%8,%9}, {%0,%1,%2,%3};"
        : "+f"(d[0]), "+f"(d[1]), "+f"(d[2]), "+f"(d[3])
        : "r"(a[0]), "r"(a[1]), "r"(a[2]), "r"(a[3]), "r"(b[0]), "r"(b[1]));
}

static __device__ __forceinline__ void split4(float4 v, uint2& hv, uint2& lv) {
    float h0 = __bfloat162float(__float2bfloat16(v.x));
    float h1 = __bfloat162float(__float2bfloat16(v.y));
    float h2 = __bfloat162float(__float2bfloat16(v.z));
    float h3 = __bfloat162float(__float2bfloat16(v.w));
    hv.x = pack2bf(h0, h1);
    hv.y = pack2bf(h2, h3);
    lv.x = pack2bf(v.x - h0, v.y - h1);
    lv.y = pack2bf(v.z - h2, v.w - h3);
}

static __device__ __forceinline__ void splitpack(float a, float b,
                                                 uint32_t& h, uint32_t& l) {
    float ha = __bfloat162float(__float2bfloat16(a));
    float hb = __bfloat162float(__float2bfloat16(b));
    h = pack2bf(ha, hb);
    l = pack2bf(a - ha, b - hb);
}

static __device__ __forceinline__ void cp16(uint32_t dst, const void* src) {
    asm volatile("cp.async.cg.shared.global [%0], [%1], 16;" :: "r"(dst), "l"(src));
}
static __device__ __forceinline__ void cp_commit() {
    asm volatile("cp.async.commit_group;");
}
template<int N> static __device__ __forceinline__ void cp_wait() {
    asm volatile("cp.async.wait_group %0;" :: "n"(N));
}

// ---------------------------------------------------------------------------
// split kernel: fp32 -> bf16 hi/lo (elementwise)
// ---------------------------------------------------------------------------
__global__ __launch_bounds__(256) void split_kernel(
    const float* __restrict__ src, __nv_bfloat16* __restrict__ dh,
    __nv_bfloat16* __restrict__ dl, int n4)
{
    int i = blockIdx.x * 256 + threadIdx.x;
    if (i < n4) {
        float4 v = ((const float4*)src)[i];
        uint2 hv, lv;
        split4(v, hv, lv);
        ((uint2*)dh)[i] = hv;
        ((uint2*)dl)[i] = lv;
    }
}

// ---------------------------------------------------------------------------
// bf16 tensor-core GEMM: C[m,n] = sum_k A[m,k]*B[n,k]
// A = Ah+Al, B = Bh+Bl (pre-split bf16, K-major, K=1024).
// 128x128 CTA tile, BK=32, 8 warps (4M x 2N), 3-term, cp.async double buffer.
// ---------------------------------------------------------------------------
#define GKP 40
#define GEMM_SMEM (2 * 4 * 128 * GKP * 2)   // 81920 bytes

__global__ __launch_bounds__(256, 1) void gemm_tc2(
    const __nv_bfloat16* __restrict__ Ah, const __nv_bfloat16* __restrict__ Al,
    const __nv_bfloat16* __restrict__ Bh, const __nv_bfloat16* __restrict__ Bl,
    float* __restrict__ C)
{
    extern __shared__ __align__(16) char smem[];
    const int tid  = threadIdx.x;
    const int wid  = tid >> 5;
    const int lane = tid & 31;
    const int brow = blockIdx.y * 128;
    const int bcol = blockIdx.x * 128;
    const int wm   = (wid & 3) * 32;
    const int wn   = (wid >> 2) * 64;

    const __nv_bfloat16* srcs[4] = {Ah, Al, Bh, Bl};

    auto buf = [&](int s, int a) -> __nv_bfloat16* {
        return (__nv_bfloat16*)smem + (size_t)(s * 4 + a) * 128 * GKP;
    };
    auto stage = [&](int s, int kt) {
#pragma unroll
        for (int i = 0; i < 8; i++) {
            int c = tid + i * 256;          // 0..2047
            int a = c >> 9;                 // array 0..3
            int cc = c & 511;
            int row = cc >> 2;
            int part = (cc & 3) << 3;       // halves
            int rbase = (a < 2) ? brow : bcol;
            const __nv_bfloat16* g = srcs[a] + (size_t)(rbase + row) * DM + kt * 32 + part;
            cp16(smem_u32(buf(s, a) + row * GKP + part), g);
        }
    };

    float acc[2][8][4];
#pragma unroll
    for (int mi = 0; mi < 2; mi++)
#pragma unroll
        for (int ni = 0; ni < 8; ni++)
#pragma unroll
            for (int j = 0; j < 4; j++) acc[mi][ni][j] = 0.f;

    const int fr = lane & 15;
    const int fc = (lane >> 4) << 3;

    stage(0, 0);
    cp_commit();

    for (int kt = 0; kt < 32; kt++) {
        const int cur = kt & 1;
        if (kt < 31) {
            stage(1 - cur, kt + 1);
            cp_commit();
            cp_wait<1>();
        } else {
            cp_wait<0>();
        }
        __syncthreads();

        const __nv_bfloat16* pAh = buf(cur, 0);
        const __nv_bfloat16* pAl = buf(cur, 1);
        const __nv_bfloat16* pBh = buf(cur, 2);
        const __nv_bfloat16* pBl = buf(cur, 3);

#pragma unroll
        for (int ks = 0; ks < 2; ks++) {
            const int kof = ks * 16 + fc;
            uint32_t ah[2][4], al[2][4];
#pragma unroll
            for (int mi = 0; mi < 2; mi++) {
                ldmx4(ah[mi][0], ah[mi][1], ah[mi][2], ah[mi][3],
                      smem_u32(pAh + (wm + mi * 16 + fr) * GKP + kof));
                ldmx4(al[mi][0], al[mi][1], al[mi][2], al[mi][3],
                      smem_u32(pAl + (wm + mi * 16 + fr) * GKP + kof));
            }
            uint32_t bh[8][2], bl[8][2];
#pragma unroll
            for (int nq = 0; nq < 4; nq++) {
                uint32_t r0, r1, r2, r3;
                ldmx4(r0, r1, r2, r3, smem_u32(pBh + (wn + nq * 16 + fr) * GKP + kof));
                bh[nq * 2 + 0][0] = r0; bh[nq * 2 + 0][1] = r2;
                bh[nq * 2 + 1][0] = r1; bh[nq * 2 + 1][1] = r3;
                ldmx4(r0, r1, r2, r3, smem_u32(pBl + (wn + nq * 16 + fr) * GKP + kof));
                bl[nq * 2 + 0][0] = r0; bl[nq * 2 + 0][1] = r2;
                bl[nq * 2 + 1][0] = r1; bl[nq * 2 + 1][1] = r3;
            }
#pragma unroll
            for (int mi = 0; mi < 2; mi++)
#pragma unroll
                for (int ni = 0; ni < 8; ni++) {
                    mma16816(acc[mi][ni], ah[mi], bh[ni]);
                    mma16816(acc[mi][ni], ah[mi], bl[ni]);
                    mma16816(acc[mi][ni], al[mi], bh[ni]);
                }
        }
        __syncthreads();
    }

    const int er = lane >> 2;
    const int ec = (lane & 3) * 2;
#pragma unroll
    for (int mi = 0; mi < 2; mi++) {
#pragma unroll
        for (int ni = 0; ni < 8; ni++) {
            float* cp0 = C + (size_t)(brow + wm + mi * 16 + er) * DM + bcol + wn + ni * 8 + ec;
            *(float2*)cp0 = make_float2(acc[mi][ni][0], acc[mi][ni][1]);
            float* cp1 = cp0 + 8 * DM;
            *(float2*)cp1 = make_float2(acc[mi][ni][2], acc[mi][ni][3]);
        }
    }
}

// ---------------------------------------------------------------------------
// Witness encoder: E = tanh(X_h @ Wenc_h) * scale, written as bf16 hi/lo.
// ---------------------------------------------------------------------------
__global__ __launch_bounds__(256) void enc_kernel(
    const float* __restrict__ X, const float* __restrict__ Wenc,
    __nv_bfloat16* __restrict__ Eh, __nv_bfloat16* __restrict__ El, float scale)
{
    __shared__ __align__(16) float Ws[HD][MB];
    __shared__ __align__(16) float Qs[64][HD];

    const int tid  = threadIdx.x;
    const int h    = blockIdx.y;
    const int row0 = blockIdx.x * 64;

    for (int i = tid; i < HD * MB; i += 256)
        Ws[i >> 5][i & 31] = Wenc[h * HD * MB + i];

#pragma unroll
    for (int i = 0; i < 4; i++) {
        int idx = tid + i * 256;
        int r = idx >> 4;
        int c = (idx & 15) << 2;
        *(float4*)&Qs[r][c] =
            *(const float4*)&X[(size_t)(row0 + r) * DM + h * HD + c];
    }
    __syncthreads();

#pragma unroll
    for (int i = 0; i < 8; i++) {
        int o = tid + i * 256;
        int r = o >> 5;
        int m = o & 31;
        float s = 0.f;
#pragma unroll
        for (int d = 0; d < HD; d++) s = fmaf(Qs[r][d], Ws[d][m], s);
        float e = tanhf(s) * scale;
        float eh = __bfloat162float(__float2bfloat16(e));
        size_t off = ((size_t)(row0 + r) * NH + h) * MB + m;
        Eh[off] = __float2bfloat16(eh);
        El[off] = __float2bfloat16(e - eh);
    }
}

// ---------------------------------------------------------------------------
// Tensor-core flash attention (fixed-max softmax, 3-term hi/lo MMA).
// grid (SEQ/128, NH, BSZ), 8 warps; warp = 16 q rows; key tiles of 128.
// ---------------------------------------------------------------------------
#define ATTN_SMEM ((2 * 128 * 40 + 2 * 128 * 72) * 2)   // 57344 bytes

__global__ __launch_bounds__(256, 1) void attn_tc(
    const __nv_bfloat16* __restrict__ QEh, const __nv_bfloat16* __restrict__ QEl,
    const __nv_bfloat16* __restrict__ KEh, const __nv_bfloat16* __restrict__ KEl,
    const __nv_bfloat16* __restrict__ Vh,  const __nv_bfloat16* __restrict__ Vl,
    __nv_bfloat16* __restrict__ AOh, __nv_bfloat16* __restrict__ AOl)
{
    extern __shared__ __align__(16) char smem[];
    __nv_bfloat16* sKh = (__nv_bfloat16*)smem;       // 128 x 40
    __nv_bfloat16* sKl = sKh + 128 * 40;
    __nv_bfloat16* sVh = sKl + 128 * 40;             // 128 x 72
    __nv_bfloat16* sVl = sVh + 128 * 72;

    const int tid  = threadIdx.x;
    const int wid  = tid >> 5;
    const int lane = tid & 31;
    const int h = blockIdx.y;
    const int b = blockIdx.z;
    const size_t base = (size_t)b * SEQ;
    const int q0 = blockIdx.x * 128;
    const int wm = wid * 16;
    const int fr = lane & 15;
    const int fc = (lane >> 4) << 3;
    const int gid = lane >> 2;
    const int tig = lane & 3;

    // ---- stage Q (hi/lo), load A fragments ----
#pragma unroll
    for (int i = 0; i < 2; i++) {
        int c = tid + i * 256;
        int row = c >> 2;
        int part = (c & 3) << 3;
        size_t g = (base + q0 + row) * (NH * MB) + h * MB + part;
        *(uint4*)&sKh[row * 40 + part] = *(const uint4*)&QEh[g];
        *(uint4*)&sKl[row * 40 + part] = *(const uint4*)&QEl[g];
    }
    __syncthreads();
    uint32_t qh[2][4], ql[2][4];
#pragma unroll
    for (int kc = 0; kc < 2; kc++) {
        ldmx4(qh[kc][0], qh[kc][1], qh[kc][2], qh[kc][3],
              smem_u32(&sKh[(wm + fr) * 40 + kc * 16 + fc]));
        ldmx4(ql[kc][0], ql[kc][1], ql[kc][2], ql[kc][3],
              smem_u32(&sKl[(wm + fr) * 40 + kc * 16 + fc]));
    }
    __syncthreads();

    float oacc[8][4];
#pragma unroll
    for (int nt = 0; nt < 8; nt++)
#pragma unroll
        for (int j = 0; j < 4; j++) oacc[nt][j] = 0.f;
    float lr = 0.f, lr8 = 0.f;

    for (int kt = 0; kt < 16; kt++) {
        const int k0 = kt * 128;
#pragma unroll
        for (int i = 0; i < 2; i++) {
            int c = tid + i * 256;
            int row = c >> 2;
            int part = (c & 3) << 3;
            size_t g = (base + k0 + row) * (NH * MB) + h * MB + part;
            *(uint4*)&sKh[row * 40 + part] = *(const uint4*)&KEh[g];
            *(uint4*)&sKl[row * 40 + part] = *(const uint4*)&KEl[g];
        }
#pragma unroll
        for (int i = 0; i < 4; i++) {
            int c = tid + i * 256;
            int row = c >> 3;
            int part = (c & 7) << 3;
            size_t g = (base + k0 + row) * DM + h * HD + part;
            *(uint4*)&sVh[row * 72 + part] = *(const uint4*)&Vh[g];
            *(uint4*)&sVl[row * 72 + part] = *(const uint4*)&Vl[g];
        }
        __syncthreads();

#pragma unroll
        for (int g8 = 0; g8 < 8; g8++) {
            // ---- scores for 16 keys (2 n-tiles) ----
            float sa0[4] = {0.f, 0.f, 0.f, 0.f};
            float sa1[4] = {0.f, 0.f, 0.f, 0.f};
#pragma unroll
            for (int kc = 0; kc < 2; kc++) {
                uint32_t r0, r1, r2, r3;
                uint32_t bh0[2], bh1[2], bl0[2], bl1[2];
                ldmx4(r0, r1, r2, r3,
                      smem_u32(&sKh[(g8 * 16 + fr) * 40 + kc * 16 + fc]));
                bh0[0] = r0; bh0[1] = r2; bh1[0] = r1; bh1[1] = r3;
                ldmx4(r0, r1, r2, r3,
                      smem_u32(&sKl[(g8 * 16 + fr) * 40 + kc * 16 + fc]));
                bl0[0] = r0; bl0[1] = r2; bl1[0] = r1; bl1[1] = r3;
                mma16816(sa0, qh[kc], bh0);
                mma16816(sa0, qh[kc], bl0);
                mma16816(sa0, ql[kc], bh0);
                mma16816(sa1, qh[kc], bh1);
                mma16816(sa1, qh[kc], bl1);
                mma16816(sa1, ql[kc], bh1);
            }
            // ---- softmax (fixed max) + P fragment build ----
            float p0 = __expf(sa0[0] - SMAX), p1 = __expf(sa0[1] - SMAX);
            float p2 = __expf(sa0[2] - SMAX), p3 = __expf(sa0[3] - SMAX);
            float p4 = __expf(sa1[0] - SMAX), p5 = __expf(sa1[1] - SMAX);
            float p6 = __expf(sa1[2] - SMAX), p7 = __expf(sa1[3] - SMAX);
            lr  += p0 + p1 + p4 + p5;
            lr8 += p2 + p3 + p6 + p7;
            uint32_t pah[4], pal[4];
            splitpack(p0, p1, pah[0], pal[0]);
            splitpack(p2, p3, pah[1], pal[1]);
            splitpack(p4, p5, pah[2], pal[2]);
            splitpack(p6, p7, pah[3], pal[3]);
            // ---- P x V for this 16-key chunk ----
#pragma unroll
            for (int nb = 0; nb < 4; nb++) {
                uint32_t r0, r1, r2, r3;
                uint32_t vh0[2], vh1[2], vl0[2], vl1[2];
                ldmx4t(r0, r1, r2, r3,
                       smem_u32(&sVh[(g8 * 16 + fr) * 72 + nb * 16 + fc]));
                vh0[0] = r0; vh0[1] = r1; vh1[0] = r2; vh1[1] = r3;
                ldmx4t(r0, r1, r2, r3,
                       smem_u32(&sVl[(g8 * 16 + fr) * 72 + nb * 16 + fc]));
                vl0[0] = r0; vl0[1] = r1; vl1[0] = r2; vl1[1] = r3;
                mma16816(oacc[nb * 2 + 0], pah, vh0);
                mma16816(oacc[nb * 2 + 0], pah, vl0);
                mma16816(oacc[nb * 2 + 0], pal, vh0);
                mma16816(oacc[nb * 2 + 1], pah, vh1);
                mma16816(oacc[nb * 2 + 1], pah, vl1);
                mma16816(oacc[nb * 2 + 1], pal, vh1);
            }
        }
        __syncthreads();
    }

    lr  += __shfl_xor_sync(0xffffffffu, lr, 1);
    lr  += __shfl_xor_sync(0xffffffffu, lr, 2);
    lr8 += __shfl_xor_sync(0xffffffffu, lr8, 1);
    lr8 += __shfl_xor_sync(0xffffffffu, lr8, 2);
    const float inv  = 1.f / lr;
    const float inv8 = 1.f / lr8;

    const size_t row0 = base + q0 + wm + gid;
#pragma unroll
    for (int nt = 0; nt < 8; nt++) {
        int col = h * HD + nt * 8 + tig * 2;
        uint32_t hh, ll;
        splitpack(oacc[nt][0] * inv, oacc[nt][1] * inv, hh, ll);
        *(uint32_t*)&AOh[row0 * DM + col] = hh;
        *(uint32_t*)&AOl[row0 * DM + col] = ll;
        splitpack(oacc[nt][2] * inv8, oacc[nt][3] * inv8, hh, ll);
        *(uint32_t*)&AOh[(row0 + 8) * DM + col] = hh;
        *(uint32_t*)&AOl[(row0 + 8) * DM + col] = ll;
    }
}

// ---------------------------------------------------------------------------
// Launch
// ---------------------------------------------------------------------------
extern "C" void kernel_launch(void* const* d_in, const int* in_sizes, int n_in,
                              void* d_out, int out_size)
{
    const float* x    = (const float*)d_in[0];
    const float* Wq   = (const float*)d_in[1];
    const float* Wk   = (const float*)d_in[2];
    const float* Wv   = (const float*)d_in[3];
    const float* Wenc = (const float*)d_in[4];
    const float* Wo   = (const float*)d_in[5];
    float* out = (float*)d_out;

    float *Qp, *Kp, *Vp;
    __nv_bfloat16 *xh, *xl, *Vhp, *Vlp, *AOh, *AOl;
    __nv_bfloat16 *QEh, *QEl, *KEh, *KEl;
    __nv_bfloat16 *Wqh, *Wql, *Wkh, *Wkl, *Wvh, *Wvl, *Woh, *Wol;
    cudaGetSymbolAddress((void**)&Qp,  g_Q);
    cudaGetSymbolAddress((void**)&Kp,  g_K);
    cudaGetSymbolAddress((void**)&Vp,  g_V);
    cudaGetSymbolAddress((void**)&xh,  g_xh);
    cudaGetSymbolAddress((void**)&xl,  g_xl);
    cudaGetSymbolAddress((void**)&Vhp, g_Vh);
    cudaGetSymbolAddress((void**)&Vlp, g_Vl);
    cudaGetSymbolAddress((void**)&AOh, g_AOh);
    cudaGetSymbolAddress((void**)&AOl, g_AOl);
    cudaGetSymbolAddress((void**)&QEh, g_QEh);
    cudaGetSymbolAddress((void**)&QEl, g_QEl);
    cudaGetSymbolAddress((void**)&KEh, g_KEh);
    cudaGetSymbolAddress((void**)&KEl, g_KEl);
    cudaGetSymbolAddress((void**)&Wqh, g_Wqh);
    cudaGetSymbolAddress((void**)&Wql, g_Wql);
    cudaGetSymbolAddress((void**)&Wkh, g_Wkh);
    cudaGetSymbolAddress((void**)&Wkl, g_Wkl);
    cudaGetSymbolAddress((void**)&Wvh, g_Wvh);
    cudaGetSymbolAddress((void**)&Wvl, g_Wvl);
    cudaGetSymbolAddress((void**)&Woh, g_Woh);
    cudaGetSymbolAddress((void**)&Wol, g_Wol);

    static bool init = false;
    if (!init) {
        cudaFuncSetAttribute(gemm_tc2, cudaFuncAttributeMaxDynamicSharedMemorySize,
                             GEMM_SMEM);
        cudaFuncSetAttribute(attn_tc, cudaFuncAttributeMaxDynamicSharedMemorySize,
                             ATTN_SMEM);
        init = true;
    }

    const int nx4 = ROWS_TOTAL * DM / 4;     // 2097152
    const int nw4 = DM * DM / 4;             // 262144

    // pre-split x and weights
    split_kernel<<<nx4 / 256, 256>>>(x, xh, xl, nx4);
    split_kernel<<<nw4 / 256, 256>>>(Wq, Wqh, Wql, nw4);
    split_kernel<<<nw4 / 256, 256>>>(Wk, Wkh, Wkl, nw4);
    split_kernel<<<nw4 / 256, 256>>>(Wv, Wvh, Wvl, nw4);
    split_kernel<<<nw4 / 256, 256>>>(Wo, Woh, Wol, nw4);

    dim3 gGemm(DM / 128, ROWS_TOTAL / 128);   // (8, 64)
    gemm_tc2<<<gGemm, 256, GEMM_SMEM>>>(xh, xl, Wqh, Wql, Qp);
    gemm_tc2<<<gGemm, 256, GEMM_SMEM>>>(xh, xl, Wkh, Wkl, Kp);
    gemm_tc2<<<gGemm, 256, GEMM_SMEM>>>(xh, xl, Wvh, Wvl, Vp);

    split_kernel<<<nx4 / 256, 256>>>(Vp, Vhp, Vlp, nx4);

    dim3 gEnc(ROWS_TOTAL / 64, NH);           // (128, 16)
    enc_kernel<<<gEnc, 256>>>(Qp, Wenc, QEh, QEl, SCALE);
    enc_kernel<<<gEnc, 256>>>(Kp, Wenc, KEh, KEl, 1.0f);

    dim3 gAttn(SEQ / 128, NH, BSZ);           // (16, 16, 4)
    attn_tc<<<gAttn, 256, ATTN_SMEM>>>(QEh, QEl, KEh, KEl, Vhp, Vlp, AOh, AOl);

    gemm_tc2<<<gGemm, 256, GEMM_SMEM>>>(AOh, AOl, Woh, Wol, out);
}

// round 5
// speedup vs baseline: 3.5837x; 1.2388x over previous
#include <cuda_runtime.h>
#include <cuda_bf16.h>
#include <cuda_fp16.h>
#include <math.h>
#include <stdint.h>

// Problem constants
#define BSZ 4
#define SEQ 2048
#define DM 1024
#define NH 16
#define HD 64
#define MB 32
#define ROWS_TOTAL (BSZ * SEQ)          // 8192
#define SCALE 0.17677669529663687f      // 1/sqrt(32)
#define SMAX 5.656854249492380f         // 32/sqrt(32) upper bound on |score|

// ---------------------------------------------------------------------------
// Scratch (no allocations allowed -> __device__ globals)
// ---------------------------------------------------------------------------
__device__ __align__(16) float g_Q[ROWS_TOTAL * DM];
__device__ __align__(16) float g_K[ROWS_TOTAL * DM];
__device__ __align__(16) float g_V[ROWS_TOTAL * DM];
__device__ __align__(16) __half g_Vf[ROWS_TOTAL * DM];
__device__ __align__(16) __nv_bfloat16 g_xh[ROWS_TOTAL * DM];
__device__ __align__(16) __nv_bfloat16 g_xl[ROWS_TOTAL * DM];
__device__ __align__(16) __nv_bfloat16 g_AOh[ROWS_TOTAL * DM];
__device__ __align__(16) __nv_bfloat16 g_AOl[ROWS_TOTAL * DM];
__device__ __align__(16) __nv_bfloat16 g_QEh[ROWS_TOTAL * NH * MB];
__device__ __align__(16) __nv_bfloat16 g_QEl[ROWS_TOTAL * NH * MB];
__device__ __align__(16) __nv_bfloat16 g_KEh[ROWS_TOTAL * NH * MB];
__device__ __align__(16) __nv_bfloat16 g_KEl[ROWS_TOTAL * NH * MB];
__device__ __align__(16) __nv_bfloat16 g_Wqh[DM * DM];
__device__ __align__(16) __nv_bfloat16 g_Wql[DM * DM];
__device__ __align__(16) __nv_bfloat16 g_Wkh[DM * DM];
__device__ __align__(16) __nv_bfloat16 g_Wkl[DM * DM];
__device__ __align__(16) __nv_bfloat16 g_Wvh[DM * DM];
__device__ __align__(16) __nv_bfloat16 g_Wvl[DM * DM];
__device__ __align__(16) __nv_bfloat16 g_Woh[DM * DM];
__device__ __align__(16) __nv_bfloat16 g_Wol[DM * DM];

// ---------------------------------------------------------------------------
// Helpers
// ---------------------------------------------------------------------------
static __device__ __forceinline__ uint32_t smem_u32(const void* p) {
    return (uint32_t)__cvta_generic_to_shared(p);
}

static __device__ __forceinline__ uint32_t pack2bf(float a, float b) {
    __nv_bfloat162 t = __floats2bfloat162_rn(a, b);
    return *(uint32_t*)&t;
}

static __device__ __forceinline__ uint32_t pack2h(float a, float b) {
    __half2 t = __floats2half2_rn(a, b);
    return *(uint32_t*)&t;
}

static __device__ __forceinline__ void ldmx4(uint32_t& r0, uint32_t& r1,
                                             uint32_t& r2, uint32_t& r3,
                                             uint32_t addr) {
    asm volatile("ldmatrix.sync.aligned.m8n8.x4.shared.b16 {%0,%1,%2,%3}, [%4];"
                 : "=r"(r0), "=r"(r1), "=r"(r2), "=r"(r3) : "r"(addr));
}

static __device__ __forceinline__ void ldmx4t(uint32_t& r0, uint32_t& r1,
                                              uint32_t& r2, uint32_t& r3,
                                              uint32_t addr) {
    asm volatile("ldmatrix.sync.aligned.m8n8.x4.trans.shared.b16 {%0,%1,%2,%3}, [%4];"
                 : "=r"(r0), "=r"(r1), "=r"(r2), "=r"(r3) : "r"(addr));
}

static __device__ __forceinline__ void mma16816(float* d, const uint32_t* a,
                                                const uint32_t* b) {
    asm volatile(
        "mma.sync.aligned.m16n8k16.row.col.f32.bf16.bf16.f32 "
        "{%0,%1,%2,%3}, {%4,%5,%6,%7}, {%8,%9}, {%0,%1,%2,%3};"
        : "+f"(d[0]), "+f"(d[1]), "+f"(d[2]), "+f"(d[3])
        : "r"(a[0]), "r"(a[1]), "r"(a[2]), "r"(a[3]), "r"(b[0]), "r"(b[1]));
}

static __device__ __forceinline__ void mma16816h(float* d, const uint32_t* a,
                                                 const uint32_t* b) {
    asm volatile(
        "mma.sync.aligned.m16n8k16.row.col.f32.f16.f16.f32 "
        "{%0,%1,%2,%3}, {%4,%5,%6,%7}, {%8,%9}, {%0,%1,%2,%3};"
        : "+f"(d[0]), "+f"(d[1]), "+f"(d[2]), "+f"(d[3])
        : "r"(a[0]), "r"(a[1]), "r"(a[2]), "r"(a[3]), "r"(b[0]), "r"(b[1]));
}

static __device__ __forceinline__ void split4(float4 v, uint2& hv, uint2& lv) {
    float h0 = __bfloat162float(__float2bfloat16(v.x));
    float h1 = __bfloat162float(__float2bfloat16(v.y));
    float h2 = __bfloat162float(__float2bfloat16(v.z));
    float h3 = __bfloat162float(__float2bfloat16(v.w));
    hv.x = pack2bf(h0, h1);
    hv.y = pack2bf(h2, h3);
    lv.x = pack2bf(v.x - h0, v.y - h1);
    lv.y = pack2bf(v.z - h2, v.w - h3);
}

static __device__ __forceinline__ void splitpack(float a, float b,
                                                 uint32_t& h, uint32_t& l) {
    float ha = __bfloat162float(__float2bfloat16(a));
    float hb = __bfloat162float(__float2bfloat16(b));
    h = pack2bf(ha, hb);
    l = pack2bf(a - ha, b - hb);
}

static __device__ __forceinline__ void cp16(uint32_t dst, const void* src) {
    asm volatile("cp.async.cg.shared.global [%0], [%1], 16;" :: "r"(dst), "l"(src));
}
static __device__ __forceinline__ void cp_commit() {
    asm volatile("cp.async.commit_group;");
}
template<int N> static __device__ __forceinline__ void cp_wait() {
    asm volatile("cp.async.wait_group %0;" :: "n"(N));
}

// ---------------------------------------------------------------------------
// split kernel: fp32 -> bf16 hi/lo (elementwise)
// ---------------------------------------------------------------------------
__global__ __launch_bounds__(256) void split_kernel(
    const float* __restrict__ src, __nv_bfloat16* __restrict__ dh,
    __nv_bfloat16* __restrict__ dl, int n4)
{
    int i = blockIdx.x * 256 + threadIdx.x;
    if (i < n4) {
        float4 v = ((const float4*)src)[i];
        uint2 hv, lv;
        split4(v, hv, lv);
        ((uint2*)dh)[i] = hv;
        ((uint2*)dl)[i] = lv;
    }
}

// fp32 -> fp16 (elementwise)
__global__ __launch_bounds__(256) void conv_half(
    const float* __restrict__ src, __half* __restrict__ dst, int n4)
{
    int i = blockIdx.x * 256 + threadIdx.x;
    if (i < n4) {
        float4 v = ((const float4*)src)[i];
        uint2 o;
        o.x = pack2h(v.x, v.y);
        o.y = pack2h(v.z, v.w);
        ((uint2*)dst)[i] = o;
    }
}

// ---------------------------------------------------------------------------
// bf16 tensor-core GEMM: C[m,n] = sum_k A[m,k]*B[n,k]
// A = Ah+Al, B = Bh+Bl (pre-split bf16, K-major, K=1024).
// 128x128 CTA tile, BK=32, 8 warps (4M x 2N), 3-term, cp.async double buffer.
// ---------------------------------------------------------------------------
#define GKP 40
#define GEMM_SMEM (2 * 4 * 128 * GKP * 2)   // 81920 bytes

__global__ __launch_bounds__(256, 1) void gemm_tc2(
    const __nv_bfloat16* __restrict__ Ah, const __nv_bfloat16* __restrict__ Al,
    const __nv_bfloat16* __restrict__ Bh, const __nv_bfloat16* __restrict__ Bl,
    float* __restrict__ C)
{
    extern __shared__ __align__(16) char smem[];
    const int tid  = threadIdx.x;
    const int wid  = tid >> 5;
    const int lane = tid & 31;
    const int brow = blockIdx.y * 128;
    const int bcol = blockIdx.x * 128;
    const int wm   = (wid & 3) * 32;
    const int wn   = (wid >> 2) * 64;

    const __nv_bfloat16* srcs[4] = {Ah, Al, Bh, Bl};

    auto buf = [&](int s, int a) -> __nv_bfloat16* {
        return (__nv_bfloat16*)smem + (size_t)(s * 4 + a) * 128 * GKP;
    };
    auto stage = [&](int s, int kt) {
#pragma unroll
        for (int i = 0; i < 8; i++) {
            int c = tid + i * 256;          // 0..2047
            int a = c >> 9;                 // array 0..3
            int cc = c & 511;
            int row = cc >> 2;
            int part = (cc & 3) << 3;       // halves
            int rbase = (a < 2) ? brow : bcol;
            const __nv_bfloat16* g = srcs[a] + (size_t)(rbase + row) * DM + kt * 32 + part;
            cp16(smem_u32(buf(s, a) + row * GKP + part), g);
        }
    };

    float acc[2][8][4];
#pragma unroll
    for (int mi = 0; mi < 2; mi++)
#pragma unroll
        for (int ni = 0; ni < 8; ni++)
#pragma unroll
            for (int j = 0; j < 4; j++) acc[mi][ni][j] = 0.f;

    const int fr = lane & 15;
    const int fc = (lane >> 4) << 3;

    stage(0, 0);
    cp_commit();

    for (int kt = 0; kt < 32; kt++) {
        const int cur = kt & 1;
        if (kt < 31) {
            stage(1 - cur, kt + 1);
            cp_commit();
            cp_wait<1>();
        } else {
            cp_wait<0>();
        }
        __syncthreads();

        const __nv_bfloat16* pAh = buf(cur, 0);
        const __nv_bfloat16* pAl = buf(cur, 1);
        const __nv_bfloat16* pBh = buf(cur, 2);
        const __nv_bfloat16* pBl = buf(cur, 3);

#pragma unroll
        for (int ks = 0; ks < 2; ks++) {
            const int kof = ks * 16 + fc;
            uint32_t ah[2][4], al[2][4];
#pragma unroll
            for (int mi = 0; mi < 2; mi++) {
                ldmx4(ah[mi][0], ah[mi][1], ah[mi][2], ah[mi][3],
                      smem_u32(pAh + (wm + mi * 16 + fr) * GKP + kof));
                ldmx4(al[mi][0], al[mi][1], al[mi][2], al[mi][3],
                      smem_u32(pAl + (wm + mi * 16 + fr) * GKP + kof));
            }
            uint32_t bh[8][2], bl[8][2];
#pragma unroll
            for (int nq = 0; nq < 4; nq++) {
                uint32_t r0, r1, r2, r3;
                ldmx4(r0, r1, r2, r3, smem_u32(pBh + (wn + nq * 16 + fr) * GKP + kof));
                bh[nq * 2 + 0][0] = r0; bh[nq * 2 + 0][1] = r2;
                bh[nq * 2 + 1][0] = r1; bh[nq * 2 + 1][1] = r3;
                ldmx4(r0, r1, r2, r3, smem_u32(pBl + (wn + nq * 16 + fr) * GKP + kof));
                bl[nq * 2 + 0][0] = r0; bl[nq * 2 + 0][1] = r2;
                bl[nq * 2 + 1][0] = r1; bl[nq * 2 + 1][1] = r3;
            }
#pragma unroll
            for (int mi = 0; mi < 2; mi++)
#pragma unroll
                for (int ni = 0; ni < 8; ni++) {
                    mma16816(acc[mi][ni], ah[mi], bh[ni]);
                    mma16816(acc[mi][ni], ah[mi], bl[ni]);
                    mma16816(acc[mi][ni], al[mi], bh[ni]);
                }
        }
        __syncthreads();
    }

    const int er = lane >> 2;
    const int ec = (lane & 3) * 2;
#pragma unroll
    for (int mi = 0; mi < 2; mi++) {
#pragma unroll
        for (int ni = 0; ni < 8; ni++) {
            float* cp0 = C + (size_t)(brow + wm + mi * 16 + er) * DM + bcol + wn + ni * 8 + ec;
            *(float2*)cp0 = make_float2(acc[mi][ni][0], acc[mi][ni][1]);
            float* cp1 = cp0 + 8 * DM;
            *(float2*)cp1 = make_float2(acc[mi][ni][2], acc[mi][ni][3]);
        }
    }
}

// ---------------------------------------------------------------------------
// Witness encoder v2: register-blocked 4 rows x 4 bits per thread.
// grid (ROWS/128, NH), 256 threads.
// ---------------------------------------------------------------------------
__global__ __launch_bounds__(256) void enc2_kernel(
    const float* __restrict__ X, const float* __restrict__ Wenc,
    __nv_bfloat16* __restrict__ Eh, __nv_bfloat16* __restrict__ El, float scale)
{
    __shared__ float Ws[HD * MB];          // [d][m], 8 KB
    __shared__ float Qs[128 * 65];         // padded rows, 33.3 KB

    const int tid  = threadIdx.x;
    const int h    = blockIdx.y;
    const int row0 = blockIdx.x * 128;

    for (int i = tid; i < HD * MB; i += 256)
        Ws[i] = Wenc[h * HD * MB + i];
    for (int i = tid; i < 128 * HD; i += 256) {
        int r = i >> 6;
        int d = i & 63;
        Qs[r * 65 + d] = X[(size_t)(row0 + r) * DM + h * HD + d];
    }
    __syncthreads();

    const int r0 = (tid >> 3) * 4;         // 0..124
    const int m0 = (tid & 7) * 4;          // 0..28

    float s[4][4];
#pragma unroll
    for (int i = 0; i < 4; i++)
#pragma unroll
        for (int j = 0; j < 4; j++) s[i][j] = 0.f;

#pragma unroll 8
    for (int d = 0; d < HD; d++) {
        float q0 = Qs[(r0 + 0) * 65 + d];
        float q1 = Qs[(r0 + 1) * 65 + d];
        float q2 = Qs[(r0 + 2) * 65 + d];
        float q3 = Qs[(r0 + 3) * 65 + d];
        float w0 = Ws[d * MB + m0 + 0];
        float w1 = Ws[d * MB + m0 + 1];
        float w2 = Ws[d * MB + m0 + 2];
        float w3 = Ws[d * MB + m0 + 3];
        s[0][0] = fmaf(q0, w0, s[0][0]); s[0][1] = fmaf(q0, w1, s[0][1]);
        s[0][2] = fmaf(q0, w2, s[0][2]); s[0][3] = fmaf(q0, w3, s[0][3]);
        s[1][0] = fmaf(q1, w0, s[1][0]); s[1][1] = fmaf(q1, w1, s[1][1]);
        s[1][2] = fmaf(q1, w2, s[1][2]); s[1][3] = fmaf(q1, w3, s[1][3]);
        s[2][0] = fmaf(q2, w0, s[2][0]); s[2][1] = fmaf(q2, w1, s[2][1]);
        s[2][2] = fmaf(q2, w2, s[2][2]); s[2][3] = fmaf(q2, w3, s[2][3]);
        s[3][0] = fmaf(q3, w0, s[3][0]); s[3][1] = fmaf(q3, w1, s[3][1]);
        s[3][2] = fmaf(q3, w2, s[3][2]); s[3][3] = fmaf(q3, w3, s[3][3]);
    }

#pragma unroll
    for (int i = 0; i < 4; i++) {
        float e0 = tanhf(s[i][0]) * scale;
        float e1 = tanhf(s[i][1]) * scale;
        float e2 = tanhf(s[i][2]) * scale;
        float e3 = tanhf(s[i][3]) * scale;
        uint2 hv, lv;
        split4(make_float4(e0, e1, e2, e3), hv, lv);
        size_t off = ((size_t)(row0 + r0 + i) * NH + h) * MB + m0;
        *(uint2*)&Eh[off] = hv;
        *(uint2*)&El[off] = lv;
    }
}

// ---------------------------------------------------------------------------
// Tensor-core flash attention: scores = 3-term bf16, PV = 1-term fp16.
// grid (SEQ/128, NH, BSZ), 8 warps; warp = 16 q rows; key tiles of 128.
// ---------------------------------------------------------------------------
#define ATTN_SMEM (2 * 128 * 40 * 2 + 128 * 72 * 2)   // 38912 bytes

__global__ __launch_bounds__(256, 2) void attn_tc(
    const __nv_bfloat16* __restrict__ QEh, const __nv_bfloat16* __restrict__ QEl,
    const __nv_bfloat16* __restrict__ KEh, const __nv_bfloat16* __restrict__ KEl,
    const __half* __restrict__ Vf,
    __nv_bfloat16* __restrict__ AOh, __nv_bfloat16* __restrict__ AOl)
{
    extern __shared__ __align__(16) char smem[];
    __nv_bfloat16* sKh = (__nv_bfloat16*)smem;       // 128 x 40
    __nv_bfloat16* sKl = sKh + 128 * 40;
    __half*        sV  = (__half*)(sKl + 128 * 40);  // 128 x 72

    const int tid  = threadIdx.x;
    const int wid  = tid >> 5;
    const int lane = tid & 31;
    const int h = blockIdx.y;
    const int b = blockIdx.z;
    const size_t base = (size_t)b * SEQ;
    const int q0 = blockIdx.x * 128;
    const int wm = wid * 16;
    const int fr = lane & 15;
    const int fc = (lane >> 4) << 3;
    const int gid = lane >> 2;
    const int tig = lane & 3;

    // ---- stage Q (hi/lo), load A fragments ----
#pragma unroll
    for (int i = 0; i < 2; i++) {
        int c = tid + i * 256;
        int row = c >> 2;
        int part = (c & 3) << 3;
        size_t g = (base + q0 + row) * (NH * MB) + h * MB + part;
        *(uint4*)&sKh[row * 40 + part] = *(const uint4*)&QEh[g];
        *(uint4*)&sKl[row * 40 + part] = *(const uint4*)&QEl[g];
    }
    __syncthreads();
    uint32_t qh[2][4], ql[2][4];
#pragma unroll
    for (int kc = 0; kc < 2; kc++) {
        ldmx4(qh[kc][0], qh[kc][1], qh[kc][2], qh[kc][3],
              smem_u32(&sKh[(wm + fr) * 40 + kc * 16 + fc]));
        ldmx4(ql[kc][0], ql[kc][1], ql[kc][2], ql[kc][3],
              smem_u32(&sKl[(wm + fr) * 40 + kc * 16 + fc]));
    }
    __syncthreads();

    float oacc[8][4];
#pragma unroll
    for (int nt = 0; nt < 8; nt++)
#pragma unroll
        for (int j = 0; j < 4; j++) oacc[nt][j] = 0.f;
    float lr = 0.f, lr8 = 0.f;

    for (int kt = 0; kt < 16; kt++) {
        const int k0 = kt * 128;
#pragma unroll
        for (int i = 0; i < 2; i++) {
            int c = tid + i * 256;
            int row = c >> 2;
            int part = (c & 3) << 3;
            size_t g = (base + k0 + row) * (NH * MB) + h * MB + part;
            *(uint4*)&sKh[row * 40 + part] = *(const uint4*)&KEh[g];
            *(uint4*)&sKl[row * 40 + part] = *(const uint4*)&KEl[g];
        }
#pragma unroll
        for (int i = 0; i < 4; i++) {
            int c = tid + i * 256;          // 0..1023
            int row = c >> 3;
            int part = (c & 7) << 3;
            size_t g = (base + k0 + row) * DM + h * HD + part;
            *(uint4*)&sV[row * 72 + part] = *(const uint4*)&Vf[g];
        }
        __syncthreads();

#pragma unroll
        for (int g8 = 0; g8 < 8; g8++) {
            // ---- scores for 16 keys (2 n-tiles), 3-term bf16 ----
            float sa0[4] = {0.f, 0.f, 0.f, 0.f};
            float sa1[4] = {0.f, 0.f, 0.f, 0.f};
#pragma unroll
            for (int kc = 0; kc < 2; kc++) {
                uint32_t r0, r1, r2, r3;
                uint32_t bh0[2], bh1[2], bl0[2], bl1[2];
                ldmx4(r0, r1, r2, r3,
                      smem_u32(&sKh[(g8 * 16 + fr) * 40 + kc * 16 + fc]));
                bh0[0] = r0; bh0[1] = r2; bh1[0] = r1; bh1[1] = r3;
                ldmx4(r0, r1, r2, r3,
                      smem_u32(&sKl[(g8 * 16 + fr) * 40 + kc * 16 + fc]));
                bl0[0] = r0; bl0[1] = r2; bl1[0] = r1; bl1[1] = r3;
                mma16816(sa0, qh[kc], bh0);
                mma16816(sa0, qh[kc], bl0);
                mma16816(sa0, ql[kc], bh0);
                mma16816(sa1, qh[kc], bh1);
                mma16816(sa1, qh[kc], bl1);
                mma16816(sa1, ql[kc], bh1);
            }
            // ---- softmax (fixed max) + fp16 P fragment ----
            float p0 = __expf(sa0[0] - SMAX), p1 = __expf(sa0[1] - SMAX);
            float p2 = __expf(sa0[2] - SMAX), p3 = __expf(sa0[3] - SMAX);
            float p4 = __expf(sa1[0] - SMAX), p5 = __expf(sa1[1] - SMAX);
            float p6 = __expf(sa1[2] - SMAX), p7 = __expf(sa1[3] - SMAX);
            lr  += p0 + p1 + p4 + p5;
            lr8 += p2 + p3 + p6 + p7;
            uint32_t ph[4];
            ph[0] = pack2h(p0, p1);
            ph[1] = pack2h(p2, p3);
            ph[2] = pack2h(p4, p5);
            ph[3] = pack2h(p6, p7);
            // ---- P x V, single-term fp16 ----
#pragma unroll
            for (int nb = 0; nb < 4; nb++) {
                uint32_t r0, r1, r2, r3;
                uint32_t v0[2], v1[2];
                ldmx4t(r0, r1, r2, r3,
                       smem_u32(&sV[(g8 * 16 + fr) * 72 + nb * 16 + fc]));
                v0[0] = r0; v0[1] = r1; v1[0] = r2; v1[1] = r3;
                mma16816h(oacc[nb * 2 + 0], ph, v0);
                mma16816h(oacc[nb * 2 + 1], ph, v1);
            }
        }
        __syncthreads();
    }

    lr  += __shfl_xor_sync(0xffffffffu, lr, 1);
    lr  += __shfl_xor_sync(0xffffffffu, lr, 2);
    lr8 += __shfl_xor_sync(0xffffffffu, lr8, 1);
    lr8 += __shfl_xor_sync(0xffffffffu, lr8, 2);
    const float inv  = 1.f / lr;
    const float inv8 = 1.f / lr8;

    const size_t row0 = base + q0 + wm + gid;
#pragma unroll
    for (int nt = 0; nt < 8; nt++) {
        int col = h * HD + nt * 8 + tig * 2;
        uint32_t hh, ll;
        splitpack(oacc[nt][0] * inv, oacc[nt][1] * inv, hh, ll);
        *(uint32_t*)&AOh[row0 * DM + col] = hh;
        *(uint32_t*)&AOl[row0 * DM + col] = ll;
        splitpack(oacc[nt][2] * inv8, oacc[nt][3] * inv8, hh, ll);
        *(uint32_t*)&AOh[(row0 + 8) * DM + col] = hh;
        *(uint32_t*)&AOl[(row0 + 8) * DM + col] = ll;
    }
}

// ---------------------------------------------------------------------------
// Launch
// ---------------------------------------------------------------------------
extern "C" void kernel_launch(void* const* d_in, const int* in_sizes, int n_in,
                              void* d_out, int out_size)
{
    const float* x    = (const float*)d_in[0];
    const float* Wq   = (const float*)d_in[1];
    const float* Wk   = (const float*)d_in[2];
    const float* Wv   = (const float*)d_in[3];
    const float* Wenc = (const float*)d_in[4];
    const float* Wo   = (const float*)d_in[5];
    float* out = (float*)d_out;

    float *Qp, *Kp, *Vp;
    __half* Vf;
    __nv_bfloat16 *xh, *xl, *AOh, *AOl;
    __nv_bfloat16 *QEh, *QEl, *KEh, *KEl;
    __nv_bfloat16 *Wqh, *Wql, *Wkh, *Wkl, *Wvh, *Wvl, *Woh, *Wol;
    cudaGetSymbolAddress((void**)&Qp,  g_Q);
    cudaGetSymbolAddress((void**)&Kp,  g_K);
    cudaGetSymbolAddress((void**)&Vp,  g_V);
    cudaGetSymbolAddress((void**)&Vf,  g_Vf);
    cudaGetSymbolAddress((void**)&xh,  g_xh);
    cudaGetSymbolAddress((void**)&xl,  g_xl);
    cudaGetSymbolAddress((void**)&AOh, g_AOh);
    cudaGetSymbolAddress((void**)&AOl, g_AOl);
    cudaGetSymbolAddress((void**)&QEh, g_QEh);
    cudaGetSymbolAddress((void**)&QEl, g_QEl);
    cudaGetSymbolAddress((void**)&KEh, g_KEh);
    cudaGetSymbolAddress((void**)&KEl, g_KEl);
    cudaGetSymbolAddress((void**)&Wqh, g_Wqh);
    cudaGetSymbolAddress((void**)&Wql, g_Wql);
    cudaGetSymbolAddress((void**)&Wkh, g_Wkh);
    cudaGetSymbolAddress((void**)&Wkl, g_Wkl);
    cudaGetSymbolAddress((void**)&Wvh, g_Wvh);
    cudaGetSymbolAddress((void**)&Wvl, g_Wvl);
    cudaGetSymbolAddress((void**)&Woh, g_Woh);
    cudaGetSymbolAddress((void**)&Wol, g_Wol);

    static bool init = false;
    if (!init) {
        cudaFuncSetAttribute(gemm_tc2, cudaFuncAttributeMaxDynamicSharedMemorySize,
                             GEMM_SMEM);
        cudaFuncSetAttribute(attn_tc, cudaFuncAttributeMaxDynamicSharedMemorySize,
                             ATTN_SMEM);
        init = true;
    }

    const int nx4 = ROWS_TOTAL * DM / 4;     // 2097152
    const int nw4 = DM * DM / 4;             // 262144

    // pre-split x and weights
    split_kernel<<<nx4 / 256, 256>>>(x, xh, xl, nx4);
    split_kernel<<<nw4 / 256, 256>>>(Wq, Wqh, Wql, nw4);
    split_kernel<<<nw4 / 256, 256>>>(Wk, Wkh, Wkl, nw4);
    split_kernel<<<nw4 / 256, 256>>>(Wv, Wvh, Wvl, nw4);
    split_kernel<<<nw4 / 256, 256>>>(Wo, Woh, Wol, nw4);

    dim3 gGemm(DM / 128, ROWS_TOTAL / 128);   // (8, 64)
    gemm_tc2<<<gGemm, 256, GEMM_SMEM>>>(xh, xl, Wqh, Wql, Qp);
    gemm_tc2<<<gGemm, 256, GEMM_SMEM>>>(xh, xl, Wkh, Wkl, Kp);
    gemm_tc2<<<gGemm, 256, GEMM_SMEM>>>(xh, xl, Wvh, Wvl, Vp);

    conv_half<<<nx4 / 256, 256>>>(Vp, Vf, nx4);

    dim3 gEnc(ROWS_TOTAL / 128, NH);          // (64, 16)
    enc2_kernel<<<gEnc, 256>>>(Qp, Wenc, QEh, QEl, SCALE);
    enc2_kernel<<<gEnc, 256>>>(Kp, Wenc, KEh, KEl, 1.0f);

    dim3 gAttn(SEQ / 128, NH, BSZ);           // (16, 16, 4)
    attn_tc<<<gAttn, 256, ATTN_SMEM>>>(QEh, QEl, KEh, KEl, Vf, AOh, AOl);

    gemm_tc2<<<gGemm, 256, GEMM_SMEM>>>(AOh, AOl, Woh, Wol, out);
}

// round 6
// speedup vs baseline: 5.1480x; 1.4365x over previous
#include <cuda_runtime.h>
#include <cuda_bf16.h>
#include <cuda_fp16.h>
#include <math.h>
#include <stdint.h>

// Problem constants
#define BSZ 4
#define SEQ 2048
#define DM 1024
#define NH 16
#define HD 64
#define MB 32
#define ROWS_TOTAL (BSZ * SEQ)          // 8192
#define SCALE 0.17677669529663687f      // 1/sqrt(32)

// ---------------------------------------------------------------------------
// Scratch (no allocations allowed -> __device__ globals)
// ---------------------------------------------------------------------------
__device__ __align__(16) float g_Q[ROWS_TOTAL * DM];
__device__ __align__(16) float g_K[ROWS_TOTAL * DM];
__device__ __align__(16) float g_V[ROWS_TOTAL * DM];
__device__ __align__(16) __half g_Vf[ROWS_TOTAL * DM];
__device__ __align__(16) __half g_xh[ROWS_TOTAL * DM];
__device__ __align__(16) __half g_xl[ROWS_TOTAL * DM];
__device__ __align__(16) __half g_AOh[ROWS_TOTAL * DM];
__device__ __align__(16) __half g_AOl[ROWS_TOTAL * DM];
__device__ __align__(16) __half g_QEh[ROWS_TOTAL * NH * MB];
__device__ __align__(16) __half g_QEl[ROWS_TOTAL * NH * MB];
__device__ __align__(16) __half g_KEf[ROWS_TOTAL * NH * MB];
__device__ __align__(16) __half g_Wqf[DM * DM];
__device__ __align__(16) __half g_Wkf[DM * DM];
__device__ __align__(16) __half g_Wvf[DM * DM];
__device__ __align__(16) __half g_Wof[DM * DM];

// ---------------------------------------------------------------------------
// Helpers
// ---------------------------------------------------------------------------
static __device__ __forceinline__ uint32_t smem_u32(const void* p) {
    return (uint32_t)__cvta_generic_to_shared(p);
}

static __device__ __forceinline__ uint32_t pack2h(float a, float b) {
    __half2 t = __floats2half2_rn(a, b);
    return *(uint32_t*)&t;
}

static __device__ __forceinline__ void ldmx4(uint32_t& r0, uint32_t& r1,
                                             uint32_t& r2, uint32_t& r3,
                                             uint32_t addr) {
    asm volatile("ldmatrix.sync.aligned.m8n8.x4.shared.b16 {%0,%1,%2,%3}, [%4];"
                 : "=r"(r0), "=r"(r1), "=r"(r2), "=r"(r3) : "r"(addr));
}

static __device__ __forceinline__ void ldmx4t(uint32_t& r0, uint32_t& r1,
                                              uint32_t& r2, uint32_t& r3,
                                              uint32_t addr) {
    asm volatile("ldmatrix.sync.aligned.m8n8.x4.trans.shared.b16 {%0,%1,%2,%3}, [%4];"
                 : "=r"(r0), "=r"(r1), "=r"(r2), "=r"(r3) : "r"(addr));
}

static __device__ __forceinline__ void mma16816h(float* d, const uint32_t* a,
                                                 const uint32_t* b) {
    asm volatile(
        "mma.sync.aligned.m16n8k16.row.col.f32.f16.f16.f32 "
        "{%0,%1,%2,%3}, {%4,%5,%6,%7}, {%8,%9}, {%0,%1,%2,%3};"
        : "+f"(d[0]), "+f"(d[1]), "+f"(d[2]), "+f"(d[3])
        : "r"(a[0]), "r"(a[1]), "r"(a[2]), "r"(a[3]), "r"(b[0]), "r"(b[1]));
}

// fp16 hi/lo split of 4 floats
static __device__ __forceinline__ void split4h(float4 v, uint2& hv, uint2& lv) {
    float h0 = __half2float(__float2half_rn(v.x));
    float h1 = __half2float(__float2half_rn(v.y));
    float h2 = __half2float(__float2half_rn(v.z));
    float h3 = __half2float(__float2half_rn(v.w));
    hv.x = pack2h(h0, h1);
    hv.y = pack2h(h2, h3);
    lv.x = pack2h(v.x - h0, v.y - h1);
    lv.y = pack2h(v.z - h2, v.w - h3);
}

static __device__ __forceinline__ void splitpackh(float a, float b,
                                                  uint32_t& h, uint32_t& l) {
    float ha = __half2float(__float2half_rn(a));
    float hb = __half2float(__float2half_rn(b));
    h = pack2h(ha, hb);
    l = pack2h(a - ha, b - hb);
}

static __device__ __forceinline__ void cp16(uint32_t dst, const void* src) {
    asm volatile("cp.async.cg.shared.global [%0], [%1], 16;" :: "r"(dst), "l"(src));
}
static __device__ __forceinline__ void cp_commit() {
    asm volatile("cp.async.commit_group;");
}
template<int N> static __device__ __forceinline__ void cp_wait() {
    asm volatile("cp.async.wait_group %0;" :: "n"(N));
}

// ---------------------------------------------------------------------------
// split kernel: fp32 -> fp16 hi/lo
// ---------------------------------------------------------------------------
__global__ __launch_bounds__(256) void split_h(
    const float* __restrict__ src, __half* __restrict__ dh,
    __half* __restrict__ dl, int n4)
{
    int i = blockIdx.x * 256 + threadIdx.x;
    if (i < n4) {
        float4 v = ((const float4*)src)[i];
        uint2 hv, lv;
        split4h(v, hv, lv);
        ((uint2*)dh)[i] = hv;
        ((uint2*)dl)[i] = lv;
    }
}

// fp32 -> fp16 single
__global__ __launch_bounds__(256) void conv_half(
    const float* __restrict__ src, __half* __restrict__ dst, int n4)
{
    int i = blockIdx.x * 256 + threadIdx.x;
    if (i < n4) {
        float4 v = ((const float4*)src)[i];
        uint2 o;
        o.x = pack2h(v.x, v.y);
        o.y = pack2h(v.z, v.w);
        ((uint2*)dst)[i] = o;
    }
}

// ---------------------------------------------------------------------------
// fp16 2-term tensor-core GEMM: C[m,n] = sum_k (Ah+Al)[m,k] * B[n,k]
// 128x128 CTA tile, BK=32, 8 warps (4M x 2N), cp.async double buffer.
// ---------------------------------------------------------------------------
#define GKP 40
#define GEMM_SMEM (2 * 3 * 128 * GKP * 2)   // 61440 bytes

__global__ __launch_bounds__(256, 1) void gemm_tc2(
    const __half* __restrict__ Ah, const __half* __restrict__ Al,
    const __half* __restrict__ B, float* __restrict__ C)
{
    extern __shared__ __align__(16) char smem[];
    const int tid  = threadIdx.x;
    const int wid  = tid >> 5;
    const int lane = tid & 31;
    const int brow = blockIdx.y * 128;
    const int bcol = blockIdx.x * 128;
    const int wm   = (wid & 3) * 32;
    const int wn   = (wid >> 2) * 64;

    const __half* srcs[3] = {Ah, Al, B};

    auto buf = [&](int s, int a) -> __half* {
        return (__half*)smem + (size_t)(s * 3 + a) * 128 * GKP;
    };
    auto stage = [&](int s, int kt) {
#pragma unroll
        for (int i = 0; i < 6; i++) {
            int c = tid + i * 256;          // 0..1535
            int a = c >> 9;                 // 0..2
            int cc = c & 511;
            int row = cc >> 2;
            int part = (cc & 3) << 3;
            int rbase = (a < 2) ? brow : bcol;
            const __half* g = srcs[a] + (size_t)(rbase + row) * DM + kt * 32 + part;
            cp16(smem_u32(buf(s, a) + row * GKP + part), g);
        }
    };

    float acc[2][8][4];
#pragma unroll
    for (int mi = 0; mi < 2; mi++)
#pragma unroll
        for (int ni = 0; ni < 8; ni++)
#pragma unroll
            for (int j = 0; j < 4; j++) acc[mi][ni][j] = 0.f;

    const int fr = lane & 15;
    const int fc = (lane >> 4) << 3;

    stage(0, 0);
    cp_commit();

    for (int kt = 0; kt < 32; kt++) {
        const int cur = kt & 1;
        if (kt < 31) {
            stage(1 - cur, kt + 1);
            cp_commit();
            cp_wait<1>();
        } else {
            cp_wait<0>();
        }
        __syncthreads();

        const __half* pAh = buf(cur, 0);
        const __half* pAl = buf(cur, 1);
        const __half* pB  = buf(cur, 2);

#pragma unroll
        for (int ks = 0; ks < 2; ks++) {
            const int kof = ks * 16 + fc;
            uint32_t ah[2][4], al[2][4];
#pragma unroll
            for (int mi = 0; mi < 2; mi++) {
                ldmx4(ah[mi][0], ah[mi][1], ah[mi][2], ah[mi][3],
                      smem_u32(pAh + (wm + mi * 16 + fr) * GKP + kof));
                ldmx4(al[mi][0], al[mi][1], al[mi][2], al[mi][3],
                      smem_u32(pAl + (wm + mi * 16 + fr) * GKP + kof));
            }
            uint32_t b[8][2];
#pragma unroll
            for (int nq = 0; nq < 4; nq++) {
                uint32_t r0, r1, r2, r3;
                ldmx4(r0, r1, r2, r3, smem_u32(pB + (wn + nq * 16 + fr) * GKP + kof));
                b[nq * 2 + 0][0] = r0; b[nq * 2 + 0][1] = r2;
                b[nq * 2 + 1][0] = r1; b[nq * 2 + 1][1] = r3;
            }
#pragma unroll
            for (int mi = 0; mi < 2; mi++)
#pragma unroll
                for (int ni = 0; ni < 8; ni++) {
                    mma16816h(acc[mi][ni], ah[mi], b[ni]);
                    mma16816h(acc[mi][ni], al[mi], b[ni]);
                }
        }
        __syncthreads();
    }

    const int er = lane >> 2;
    const int ec = (lane & 3) * 2;
#pragma unroll
    for (int mi = 0; mi < 2; mi++) {
#pragma unroll
        for (int ni = 0; ni < 8; ni++) {
            float* cp0 = C + (size_t)(brow + wm + mi * 16 + er) * DM + bcol + wn + ni * 8 + ec;
            *(float2*)cp0 = make_float2(acc[mi][ni][0], acc[mi][ni][1]);
            float* cp1 = cp0 + 8 * DM;
            *(float2*)cp1 = make_float2(acc[mi][ni][2], acc[mi][ni][3]);
        }
    }
}

// ---------------------------------------------------------------------------
// Witness encoder: register-blocked 4 rows x 4 bits per thread.
// write_lo=1: E split fp16 hi/lo (Q path). write_lo=0: single fp16 (K path).
// ---------------------------------------------------------------------------
__global__ __launch_bounds__(256) void enc2_kernel(
    const float* __restrict__ X, const float* __restrict__ Wenc,
    __half* __restrict__ Eh, __half* __restrict__ El, float scale, int write_lo)
{
    __shared__ float Ws[HD * MB];          // 8 KB
    __shared__ float Qs[128 * 65];         // 33.3 KB

    const int tid  = threadIdx.x;
    const int h    = blockIdx.y;
    const int row0 = blockIdx.x * 128;

    for (int i = tid; i < HD * MB; i += 256)
        Ws[i] = Wenc[h * HD * MB + i];
    for (int i = tid; i < 128 * HD; i += 256) {
        int r = i >> 6;
        int d = i & 63;
        Qs[r * 65 + d] = X[(size_t)(row0 + r) * DM + h * HD + d];
    }
    __syncthreads();

    const int r0 = (tid >> 3) * 4;
    const int m0 = (tid & 7) * 4;

    float s[4][4];
#pragma unroll
    for (int i = 0; i < 4; i++)
#pragma unroll
        for (int j = 0; j < 4; j++) s[i][j] = 0.f;

#pragma unroll 8
    for (int d = 0; d < HD; d++) {
        float q0 = Qs[(r0 + 0) * 65 + d];
        float q1 = Qs[(r0 + 1) * 65 + d];
        float q2 = Qs[(r0 + 2) * 65 + d];
        float q3 = Qs[(r0 + 3) * 65 + d];
        float w0 = Ws[d * MB + m0 + 0];
        float w1 = Ws[d * MB + m0 + 1];
        float w2 = Ws[d * MB + m0 + 2];
        float w3 = Ws[d * MB + m0 + 3];
        s[0][0] = fmaf(q0, w0, s[0][0]); s[0][1] = fmaf(q0, w1, s[0][1]);
        s[0][2] = fmaf(q0, w2, s[0][2]); s[0][3] = fmaf(q0, w3, s[0][3]);
        s[1][0] = fmaf(q1, w0, s[1][0]); s[1][1] = fmaf(q1, w1, s[1][1]);
        s[1][2] = fmaf(q1, w2, s[1][2]); s[1][3] = fmaf(q1, w3, s[1][3]);
        s[2][0] = fmaf(q2, w0, s[2][0]); s[2][1] = fmaf(q2, w1, s[2][1]);
        s[2][2] = fmaf(q2, w2, s[2][2]); s[2][3] = fmaf(q2, w3, s[2][3]);
        s[3][0] = fmaf(q3, w0, s[3][0]); s[3][1] = fmaf(q3, w1, s[3][1]);
        s[3][2] = fmaf(q3, w2, s[3][2]); s[3][3] = fmaf(q3, w3, s[3][3]);
    }

#pragma unroll
    for (int i = 0; i < 4; i++) {
        float e0 = tanhf(s[i][0]) * scale;
        float e1 = tanhf(s[i][1]) * scale;
        float e2 = tanhf(s[i][2]) * scale;
        float e3 = tanhf(s[i][3]) * scale;
        size_t off = ((size_t)(row0 + r0 + i) * NH + h) * MB + m0;
        uint2 hv, lv;
        split4h(make_float4(e0, e1, e2, e3), hv, lv);
        *(uint2*)&Eh[off] = hv;
        if (write_lo) *(uint2*)&El[off] = lv;
    }
}

// ---------------------------------------------------------------------------
// Tensor-core flash attention: scores = 2-term fp16, PV = 1-term fp16.
// p = exp(s) directly (|s| <= 5.66 -> p in [3.5e-3, 287], fp16-normal range).
// grid (SEQ/128, NH, BSZ), 8 warps; warp = 16 q rows; key tiles of 128.
// ---------------------------------------------------------------------------
#define ATTN_SMEM (128 * 40 * 2 + 128 * 72 * 2)   // 28672 bytes

__global__ __launch_bounds__(256, 2) void attn_tc(
    const __half* __restrict__ QEh, const __half* __restrict__ QEl,
    const __half* __restrict__ KEf, const __half* __restrict__ Vf,
    __half* __restrict__ AOh, __half* __restrict__ AOl)
{
    extern __shared__ __align__(16) char smem[];
    __half* sK = (__half*)smem;              // 128 x 40
    __half* sV = sK + 128 * 40;              // 128 x 72

    const int tid  = threadIdx.x;
    const int wid  = tid >> 5;
    const int lane = tid & 31;
    const int h = blockIdx.y;
    const int b = blockIdx.z;
    const size_t base = (size_t)b * SEQ;
    const int q0 = blockIdx.x * 128;
    const int wm = wid * 16;
    const int fr = lane & 15;
    const int fc = (lane >> 4) << 3;
    const int gid = lane >> 2;
    const int tig = lane & 3;

    // ---- stage Q hi -> sK, Q lo -> sV (stride 40), load A fragments ----
#pragma unroll
    for (int i = 0; i < 2; i++) {
        int c = tid + i * 256;
        int row = c >> 2;
        int part = (c & 3) << 3;
        size_t g = (base + q0 + row) * (NH * MB) + h * MB + part;
        *(uint4*)&sK[row * 40 + part] = *(const uint4*)&QEh[g];
        *(uint4*)&sV[row * 40 + part] = *(const uint4*)&QEl[g];
    }
    __syncthreads();
    uint32_t qh[2][4], ql[2][4];
#pragma unroll
    for (int kc = 0; kc < 2; kc++) {
        ldmx4(qh[kc][0], qh[kc][1], qh[kc][2], qh[kc][3],
              smem_u32(&sK[(wm + fr) * 40 + kc * 16 + fc]));
        ldmx4(ql[kc][0], ql[kc][1], ql[kc][2], ql[kc][3],
              smem_u32(&sV[(wm + fr) * 40 + kc * 16 + fc]));
    }
    __syncthreads();

    float oacc[8][4];
#pragma unroll
    for (int nt = 0; nt < 8; nt++)
#pragma unroll
        for (int j = 0; j < 4; j++) oacc[nt][j] = 0.f;
    float lr = 0.f, lr8 = 0.f;

    for (int kt = 0; kt < 16; kt++) {
        const int k0 = kt * 128;
#pragma unroll
        for (int i = 0; i < 2; i++) {
            int c = tid + i * 256;
            int row = c >> 2;
            int part = (c & 3) << 3;
            size_t g = (base + k0 + row) * (NH * MB) + h * MB + part;
            *(uint4*)&sK[row * 40 + part] = *(const uint4*)&KEf[g];
        }
#pragma unroll
        for (int i = 0; i < 4; i++) {
            int c = tid + i * 256;
            int row = c >> 3;
            int part = (c & 7) << 3;
            size_t g = (base + k0 + row) * DM + h * HD + part;
            *(uint4*)&sV[row * 72 + part] = *(const uint4*)&Vf[g];
        }
        __syncthreads();

#pragma unroll
        for (int g8 = 0; g8 < 8; g8++) {
            // ---- scores for 16 keys (2 n-tiles), 2-term fp16 ----
            float sa0[4] = {0.f, 0.f, 0.f, 0.f};
            float sa1[4] = {0.f, 0.f, 0.f, 0.f};
#pragma unroll
            for (int kc = 0; kc < 2; kc++) {
                uint32_t r0, r1, r2, r3;
                uint32_t b0[2], b1[2];
                ldmx4(r0, r1, r2, r3,
                      smem_u32(&sK[(g8 * 16 + fr) * 40 + kc * 16 + fc]));
                b0[0] = r0; b0[1] = r2; b1[0] = r1; b1[1] = r3;
                mma16816h(sa0, qh[kc], b0);
                mma16816h(sa0, ql[kc], b0);
                mma16816h(sa1, qh[kc], b1);
                mma16816h(sa1, ql[kc], b1);
            }
            // ---- softmax: p = exp(s), fp16-normal range ----
            float p0 = __expf(sa0[0]), p1 = __expf(sa0[1]);
            float p2 = __expf(sa0[2]), p3 = __expf(sa0[3]);
            float p4 = __expf(sa1[0]), p5 = __expf(sa1[1]);
            float p6 = __expf(sa1[2]), p7 = __expf(sa1[3]);
            lr  += p0 + p1 + p4 + p5;
            lr8 += p2 + p3 + p6 + p7;
            uint32_t ph[4];
            ph[0] = pack2h(p0, p1);
            ph[1] = pack2h(p2, p3);
            ph[2] = pack2h(p4, p5);
            ph[3] = pack2h(p6, p7);
            // ---- P x V, single-term fp16 ----
#pragma unroll
            for (int nb = 0; nb < 4; nb++) {
                uint32_t r0, r1, r2, r3;
                uint32_t v0[2], v1[2];
                ldmx4t(r0, r1, r2, r3,
                       smem_u32(&sV[(g8 * 16 + fr) * 72 + nb * 16 + fc]));
                v0[0] = r0; v0[1] = r1; v1[0] = r2; v1[1] = r3;
                mma16816h(oacc[nb * 2 + 0], ph, v0);
                mma16816h(oacc[nb * 2 + 1], ph, v1);
            }
        }
        __syncthreads();
    }

    lr  += __shfl_xor_sync(0xffffffffu, lr, 1);
    lr  += __shfl_xor_sync(0xffffffffu, lr, 2);
    lr8 += __shfl_xor_sync(0xffffffffu, lr8, 1);
    lr8 += __shfl_xor_sync(0xffffffffu, lr8, 2);
    const float inv  = 1.f / lr;
    const float inv8 = 1.f / lr8;

    const size_t row0 = base + q0 + wm + gid;
#pragma unroll
    for (int nt = 0; nt < 8; nt++) {
        int col = h * HD + nt * 8 + tig * 2;
        uint32_t hh, ll;
        splitpackh(oacc[nt][0] * inv, oacc[nt][1] * inv, hh, ll);
        *(uint32_t*)&AOh[row0 * DM + col] = hh;
        *(uint32_t*)&AOl[row0 * DM + col] = ll;
        splitpackh(oacc[nt][2] * inv8, oacc[nt][3] * inv8, hh, ll);
        *(uint32_t*)&AOh[(row0 + 8) * DM + col] = hh;
        *(uint32_t*)&AOl[(row0 + 8) * DM + col] = ll;
    }
}

// ---------------------------------------------------------------------------
// Launch
// ---------------------------------------------------------------------------
extern "C" void kernel_launch(void* const* d_in, const int* in_sizes, int n_in,
                              void* d_out, int out_size)
{
    const float* x    = (const float*)d_in[0];
    const float* Wq   = (const float*)d_in[1];
    const float* Wk   = (const float*)d_in[2];
    const float* Wv   = (const float*)d_in[3];
    const float* Wenc = (const float*)d_in[4];
    const float* Wo   = (const float*)d_in[5];
    float* out = (float*)d_out;

    float *Qp, *Kp, *Vp;
    __half *Vf, *xh, *xl, *AOh, *AOl, *QEh, *QEl, *KEf;
    __half *Wqf, *Wkf, *Wvf, *Wof;
    cudaGetSymbolAddress((void**)&Qp,  g_Q);
    cudaGetSymbolAddress((void**)&Kp,  g_K);
    cudaGetSymbolAddress((void**)&Vp,  g_V);
    cudaGetSymbolAddress((void**)&Vf,  g_Vf);
    cudaGetSymbolAddress((void**)&xh,  g_xh);
    cudaGetSymbolAddress((void**)&xl,  g_xl);
    cudaGetSymbolAddress((void**)&AOh, g_AOh);
    cudaGetSymbolAddress((void**)&AOl, g_AOl);
    cudaGetSymbolAddress((void**)&QEh, g_QEh);
    cudaGetSymbolAddress((void**)&QEl, g_QEl);
    cudaGetSymbolAddress((void**)&KEf, g_KEf);
    cudaGetSymbolAddress((void**)&Wqf, g_Wqf);
    cudaGetSymbolAddress((void**)&Wkf, g_Wkf);
    cudaGetSymbolAddress((void**)&Wvf, g_Wvf);
    cudaGetSymbolAddress((void**)&Wof, g_Wof);

    static bool init = false;
    if (!init) {
        cudaFuncSetAttribute(gemm_tc2, cudaFuncAttributeMaxDynamicSharedMemorySize,
                             GEMM_SMEM);
        cudaFuncSetAttribute(attn_tc, cudaFuncAttributeMaxDynamicSharedMemorySize,
                             ATTN_SMEM);
        init = true;
    }

    const int nx4 = ROWS_TOTAL * DM / 4;     // 2097152
    const int nw4 = DM * DM / 4;             // 262144

    split_h<<<nx4 / 256, 256>>>(x, xh, xl, nx4);
    conv_half<<<nw4 / 256, 256>>>(Wq, Wqf, nw4);
    conv_half<<<nw4 / 256, 256>>>(Wk, Wkf, nw4);
    conv_half<<<nw4 / 256, 256>>>(Wv, Wvf, nw4);
    conv_half<<<nw4 / 256, 256>>>(Wo, Wof, nw4);

    dim3 gGemm(DM / 128, ROWS_TOTAL / 128);   // (8, 64)
    gemm_tc2<<<gGemm, 256, GEMM_SMEM>>>(xh, xl, Wqf, Qp);
    gemm_tc2<<<gGemm, 256, GEMM_SMEM>>>(xh, xl, Wkf, Kp);
    gemm_tc2<<<gGemm, 256, GEMM_SMEM>>>(xh, xl, Wvf, Vp);

    conv_half<<<nx4 / 256, 256>>>(Vp, Vf, nx4);

    dim3 gEnc(ROWS_TOTAL / 128, NH);          // (64, 16)
    enc2_kernel<<<gEnc, 256>>>(Qp, Wenc, QEh, QEl, SCALE, 1);
    enc2_kernel<<<gEnc, 256>>>(Kp, Wenc, KEf, nullptr, 1.0f, 0);

    dim3 gAttn(SEQ / 128, NH, BSZ);           // (16, 16, 4)
    attn_tc<<<gAttn, 256, ATTN_SMEM>>>(QEh, QEl, KEf, Vf, AOh, AOl);

    gemm_tc2<<<gGemm, 256, GEMM_SMEM>>>(AOh, AOl, Wof, out);
}

// round 8
// speedup vs baseline: 5.5280x; 1.0738x over previous
#include <cuda_runtime.h>
#include <cuda_bf16.h>
#include <cuda_fp16.h>
#include <math.h>
#include <stdint.h>

// Problem constants
#define BSZ 4
#define SEQ 2048
#define DM 1024
#define NH 16
#define HD 64
#define MB 32
#define ROWS_TOTAL (BSZ * SEQ)          // 8192
#define SCALE 0.17677669529663687f      // 1/sqrt(32)

// ---------------------------------------------------------------------------
// Scratch (no allocations allowed -> __device__ globals)
// ---------------------------------------------------------------------------
__device__ __align__(16) float g_Q[ROWS_TOTAL * DM];
__device__ __align__(16) float g_K[ROWS_TOTAL * DM];
__device__ __align__(16) __half g_Vf[ROWS_TOTAL * DM];
__device__ __align__(16) __half g_xh[ROWS_TOTAL * DM];
__device__ __align__(16) __half g_xl[ROWS_TOTAL * DM];
__device__ __align__(16) __half g_AOh[ROWS_TOTAL * DM];
__device__ __align__(16) __half g_AOl[ROWS_TOTAL * DM];
__device__ __align__(16) __half g_QEf[ROWS_TOTAL * NH * MB];
__device__ __align__(16) __half g_KEf[ROWS_TOTAL * NH * MB];
__device__ __align__(16) __half g_Wqf[DM * DM];
__device__ __align__(16) __half g_Wkf[DM * DM];
__device__ __align__(16) __half g_Wvf[DM * DM];
__device__ __align__(16) __half g_Wof[DM * DM];

// ---------------------------------------------------------------------------
// Helpers
// ---------------------------------------------------------------------------
static __device__ __forceinline__ uint32_t smem_u32(const void* p) {
    return (uint32_t)__cvta_generic_to_shared(p);
}

static __device__ __forceinline__ uint32_t pack2h(float a, float b) {
    __half2 t = __floats2half2_rn(a, b);
    return *(uint32_t*)&t;
}

static __device__ __forceinline__ void ldmx4(uint32_t& r0, uint32_t& r1,
                                             uint32_t& r2, uint32_t& r3,
                                             uint32_t addr) {
    asm volatile("ldmatrix.sync.aligned.m8n8.x4.shared.b16 {%0,%1,%2,%3}, [%4];"
                 : "=r"(r0), "=r"(r1), "=r"(r2), "=r"(r3) : "r"(addr));
}

static __device__ __forceinline__ void ldmx4t(uint32_t& r0, uint32_t& r1,
                                              uint32_t& r2, uint32_t& r3,
                                              uint32_t addr) {
    asm volatile("ldmatrix.sync.aligned.m8n8.x4.trans.shared.b16 {%0,%1,%2,%3}, [%4];"
                 : "=r"(r0), "=r"(r1), "=r"(r2), "=r"(r3) : "r"(addr));
}

static __device__ __forceinline__ void mma16816h(float* d, const uint32_t* a,
                                                 const uint32_t* b) {
    asm volatile(
        "mma.sync.aligned.m16n8k16.row.col.f32.f16.f16.f32 "
        "{%0,%1,%2,%3}, {%4,%5,%6,%7}, {%8,%9}, {%0,%1,%2,%3};"
        : "+f"(d[0]), "+f"(d[1]), "+f"(d[2]), "+f"(d[3])
        : "r"(a[0]), "r"(a[1]), "r"(a[2]), "r"(a[3]), "r"(b[0]), "r"(b[1]));
}

// fp16 hi/lo split of 4 floats
static __device__ __forceinline__ void split4h(float4 v, uint2& hv, uint2& lv) {
    float h0 = __half2float(__float2half_rn(v.x));
    float h1 = __half2float(__float2half_rn(v.y));
    float h2 = __half2float(__float2half_rn(v.z));
    float h3 = __half2float(__float2half_rn(v.w));
    hv.x = pack2h(h0, h1);
    hv.y = pack2h(h2, h3);
    lv.x = pack2h(v.x - h0, v.y - h1);
    lv.y = pack2h(v.z - h2, v.w - h3);
}

static __device__ __forceinline__ void splitpackh(float a, float b,
                                                  uint32_t& h, uint32_t& l) {
    float ha = __half2float(__float2half_rn(a));
    float hb = __half2float(__float2half_rn(b));
    h = pack2h(ha, hb);
    l = pack2h(a - ha, b - hb);
}

static __device__ __forceinline__ void cp16(uint32_t dst, const void* src) {
    asm volatile("cp.async.cg.shared.global [%0], [%1], 16;" :: "r"(dst), "l"(src));
}
static __device__ __forceinline__ void cp_commit() {
    asm volatile("cp.async.commit_group;");
}
template<int N> static __device__ __forceinline__ void cp_wait() {
    asm volatile("cp.async.wait_group %0;" :: "n"(N));
}

// ---------------------------------------------------------------------------
// split kernel: fp32 -> fp16 hi/lo
// ---------------------------------------------------------------------------
__global__ __launch_bounds__(256) void split_h(
    const float* __restrict__ src, __half* __restrict__ dh,
    __half* __restrict__ dl, int n4)
{
    int i = blockIdx.x * 256 + threadIdx.x;
    if (i < n4) {
        float4 v = ((const float4*)src)[i];
        uint2 hv, lv;
        split4h(v, hv, lv);
        ((uint2*)dh)[i] = hv;
        ((uint2*)dl)[i] = lv;
    }
}

// 4 weight matrices fp32 -> fp16 in one launch (blockIdx.y selects)
__global__ __launch_bounds__(256) void conv_half4(
    const float* __restrict__ s0, const float* __restrict__ s1,
    const float* __restrict__ s2, const float* __restrict__ s3,
    __half* __restrict__ d0, __half* __restrict__ d1,
    __half* __restrict__ d2, __half* __restrict__ d3, int n4)
{
    const float* s; __half* d;
    switch (blockIdx.y) {
        case 0: s = s0; d = d0; break;
        case 1: s = s1; d = d1; break;
        case 2: s = s2; d = d2; break;
        default: s = s3; d = d3; break;
    }
    int i = blockIdx.x * 256 + threadIdx.x;
    if (i < n4) {
        float4 v = ((const float4*)s)[i];
        uint2 o;
        o.x = pack2h(v.x, v.y);
        o.y = pack2h(v.z, v.w);
        ((uint2*)d)[i] = o;
    }
}

// ---------------------------------------------------------------------------
// fp16 2-term tensor-core GEMM: C[m,n] = sum_k (Ah+Al)[m,k] * B[n,k]
// 128x128 CTA tile, BK=32, 8 warps (4M x 2N), cp.async double buffer,
// 2 CTAs/SM. Output: fp32 (Cf) or fp16 (Ch) - exactly one non-null.
// ---------------------------------------------------------------------------
#define GKP 40
#define GEMM_SMEM (2 * 3 * 128 * GKP * 2)   // 61440 bytes

__global__ __launch_bounds__(256, 2) void gemm_tc2(
    const __half* __restrict__ Ah, const __half* __restrict__ Al,
    const __half* __restrict__ B, float* __restrict__ Cf,
    __half* __restrict__ Ch)
{
    extern __shared__ __align__(16) char smem[];
    const int tid  = threadIdx.x;
    const int wid  = tid >> 5;
    const int lane = tid & 31;
    const int brow = blockIdx.y * 128;
    const int bcol = blockIdx.x * 128;
    const int wm   = (wid & 3) * 32;
    const int wn   = (wid >> 2) * 64;

    const __half* srcs[3] = {Ah, Al, B};

    auto buf = [&](int s, int a) -> __half* {
        return (__half*)smem + (size_t)(s * 3 + a) * 128 * GKP;
    };
    auto stage = [&](int s, int kt) {
#pragma unroll
        for (int i = 0; i < 6; i++) {
            int c = tid + i * 256;          // 0..1535
            int a = c >> 9;                 // 0..2
            int cc = c & 511;
            int row = cc >> 2;
            int part = (cc & 3) << 3;
            int rbase = (a < 2) ? brow : bcol;
            const __half* g = srcs[a] + (size_t)(rbase + row) * DM + kt * 32 + part;
            cp16(smem_u32(buf(s, a) + row * GKP + part), g);
        }
    };

    float acc[2][8][4];
#pragma unroll
    for (int mi = 0; mi < 2; mi++)
#pragma unroll
        for (int ni = 0; ni < 8; ni++)
#pragma unroll
            for (int j = 0; j < 4; j++) acc[mi][ni][j] = 0.f;

    const int fr = lane & 15;
    const int fc = (lane >> 4) << 3;

    stage(0, 0);
    cp_commit();

    for (int kt = 0; kt < 32; kt++) {
        const int cur = kt & 1;
        if (kt < 31) {
            stage(1 - cur, kt + 1);
            cp_commit();
            cp_wait<1>();
        } else {
            cp_wait<0>();
        }
        __syncthreads();

        const __half* pAh = buf(cur, 0);
        const __half* pAl = buf(cur, 1);
        const __half* pB  = buf(cur, 2);

#pragma unroll
        for (int ks = 0; ks < 2; ks++) {
            const int kof = ks * 16 + fc;
            uint32_t ah[2][4], al[2][4];
#pragma unroll
            for (int mi = 0; mi < 2; mi++) {
                ldmx4(ah[mi][0], ah[mi][1], ah[mi][2], ah[mi][3],
                      smem_u32(pAh + (wm + mi * 16 + fr) * GKP + kof));
                ldmx4(al[mi][0], al[mi][1], al[mi][2], al[mi][3],
                      smem_u32(pAl + (wm + mi * 16 + fr) * GKP + kof));
            }
            uint32_t b[8][2];
#pragma unroll
            for (int nq = 0; nq < 4; nq++) {
                uint32_t r0, r1, r2, r3;
                ldmx4(r0, r1, r2, r3, smem_u32(pB + (wn + nq * 16 + fr) * GKP + kof));
                b[nq * 2 + 0][0] = r0; b[nq * 2 + 0][1] = r2;
                b[nq * 2 + 1][0] = r1; b[nq * 2 + 1][1] = r3;
            }
#pragma unroll
            for (int mi = 0; mi < 2; mi++)
#pragma unroll
                for (int ni = 0; ni < 8; ni++) {
                    mma16816h(acc[mi][ni], ah[mi], b[ni]);
                    mma16816h(acc[mi][ni], al[mi], b[ni]);
                }
        }
        __syncthreads();
    }

    const int er = lane >> 2;
    const int ec = (lane & 3) * 2;
    if (Cf) {
#pragma unroll
        for (int mi = 0; mi < 2; mi++) {
#pragma unroll
            for (int ni = 0; ni < 8; ni++) {
                float* cp0 = Cf + (size_t)(brow + wm + mi * 16 + er) * DM + bcol + wn + ni * 8 + ec;
                *(float2*)cp0 = make_float2(acc[mi][ni][0], acc[mi][ni][1]);
                float* cp1 = cp0 + 8 * DM;
                *(float2*)cp1 = make_float2(acc[mi][ni][2], acc[mi][ni][3]);
            }
        }
    } else {
#pragma unroll
        for (int mi = 0; mi < 2; mi++) {
#pragma unroll
            for (int ni = 0; ni < 8; ni++) {
                __half* cp0 = Ch + (size_t)(brow + wm + mi * 16 + er) * DM + bcol + wn + ni * 8 + ec;
                *(uint32_t*)cp0 = pack2h(acc[mi][ni][0], acc[mi][ni][1]);
                __half* cp1 = cp0 + 8 * DM;
                *(uint32_t*)cp1 = pack2h(acc[mi][ni][2], acc[mi][ni][3]);
            }
        }
    }
}

// ---------------------------------------------------------------------------
// Witness encoder: register-blocked 4 rows x 4 bits per thread.
// Writes single fp16 E (scale folded for Q path).
// ---------------------------------------------------------------------------
__global__ __launch_bounds__(256) void enc2_kernel(
    const float* __restrict__ X, const float* __restrict__ Wenc,
    __half* __restrict__ E, float scale)
{
    __shared__ float Ws[HD * MB];          // 8 KB
    __shared__ float Qs[128 * 65];         // 33.3 KB

    const int tid  = threadIdx.x;
    const int h    = blockIdx.y;
    const int row0 = blockIdx.x * 128;

    for (int i = tid; i < HD * MB; i += 256)
        Ws[i] = Wenc[h * HD * MB + i];
    for (int i = tid; i < 128 * HD; i += 256) {
        int r = i >> 6;
        int d = i & 63;
        Qs[r * 65 + d] = X[(size_t)(row0 + r) * DM + h * HD + d];
    }
    __syncthreads();

    const int r0 = (tid >> 3) * 4;
    const int m0 = (tid & 7) * 4;

    float s[4][4];
#pragma unroll
    for (int i = 0; i < 4; i++)
#pragma unroll
        for (int j = 0; j < 4; j++) s[i][j] = 0.f;

#pragma unroll 8
    for (int d = 0; d < HD; d++) {
        float q0 = Qs[(r0 + 0) * 65 + d];
        float q1 = Qs[(r0 + 1) * 65 + d];
        float q2 = Qs[(r0 + 2) * 65 + d];
        float q3 = Qs[(r0 + 3) * 65 + d];
        float w0 = Ws[d * MB + m0 + 0];
        float w1 = Ws[d * MB + m0 + 1];
        float w2 = Ws[d * MB + m0 + 2];
        float w3 = Ws[d * MB + m0 + 3];
        s[0][0] = fmaf(q0, w0, s[0][0]); s[0][1] = fmaf(q0, w1, s[0][1]);
        s[0][2] = fmaf(q0, w2, s[0][2]); s[0][3] = fmaf(q0, w3, s[0][3]);
        s[1][0] = fmaf(q1, w0, s[1][0]); s[1][1] = fmaf(q1, w1, s[1][1]);
        s[1][2] = fmaf(q1, w2, s[1][2]); s[1][3] = fmaf(q1, w3, s[1][3]);
        s[2][0] = fmaf(q2, w0, s[2][0]); s[2][1] = fmaf(q2, w1, s[2][1]);
        s[2][2] = fmaf(q2, w2, s[2][2]); s[2][3] = fmaf(q2, w3, s[2][3]);
        s[3][0] = fmaf(q3, w0, s[3][0]); s[3][1] = fmaf(q3, w1, s[3][1]);
        s[3][2] = fmaf(q3, w2, s[3][2]); s[3][3] = fmaf(q3, w3, s[3][3]);
    }

#pragma unroll
    for (int i = 0; i < 4; i++) {
        float e0 = tanhf(s[i][0]) * scale;
        float e1 = tanhf(s[i][1]) * scale;
        float e2 = tanhf(s[i][2]) * scale;
        float e3 = tanhf(s[i][3]) * scale;
        size_t off = ((size_t)(row0 + r0 + i) * NH + h) * MB + m0;
        uint2 o;
        o.x = pack2h(e0, e1);
        o.y = pack2h(e2, e3);
        *(uint2*)&E[off] = o;
    }
}

// ---------------------------------------------------------------------------
// Tensor-core flash attention: scores = 1-term fp16, PV = 1-term fp16.
// p = exp(s) directly (|s| <= 5.66 -> p in [3.5e-3, 287], fp16-normal range).
// grid (SEQ/128, NH, BSZ), 8 warps; warp = 16 q rows; key tiles of 128.
// ---------------------------------------------------------------------------
#define ATTN_SMEM (128 * 40 * 2 + 128 * 72 * 2)   // 28672 bytes

__global__ __launch_bounds__(256, 2) void attn_tc(
    const __half* __restrict__ QEf, const __half* __restrict__ KEf,
    const __half* __restrict__ Vf,
    __half* __restrict__ AOh, __half* __restrict__ AOl)
{
    extern __shared__ __align__(16) char smem[];
    __half* sK = (__half*)smem;              // 128 x 40
    __half* sV = sK + 128 * 40;              // 128 x 72

    const int tid  = threadIdx.x;
    const int wid  = tid >> 5;
    const int lane = tid & 31;
    const int h = blockIdx.y;
    const int b = blockIdx.z;
    const size_t base = (size_t)b * SEQ;
    const int q0 = blockIdx.x * 128;
    const int wm = wid * 16;
    const int fr = lane & 15;
    const int fc = (lane >> 4) << 3;
    const int gid = lane >> 2;
    const int tig = lane & 3;

    // ---- stage Q -> sK, load A fragments ----
#pragma unroll
    for (int i = 0; i < 2; i++) {
        int c = tid + i * 256;
        int row = c >> 2;
        int part = (c & 3) << 3;
        size_t g = (base + q0 + row) * (NH * MB) + h * MB + part;
        *(uint4*)&sK[row * 40 + part] = *(const uint4*)&QEf[g];
    }
    __syncthreads();
    uint32_t qh[2][4];
#pragma unroll
    for (int kc = 0; kc < 2; kc++) {
        ldmx4(qh[kc][0], qh[kc][1], qh[kc][2], qh[kc][3],
              smem_u32(&sK[(wm + fr) * 40 + kc * 16 + fc]));
    }
    __syncthreads();

    float oacc[8][4];
#pragma unroll
    for (int nt = 0; nt < 8; nt++)
#pragma unroll
        for (int j = 0; j < 4; j++) oacc[nt][j] = 0.f;
    float lr = 0.f, lr8 = 0.f;

    for (int kt = 0; kt < 16; kt++) {
        const int k0 = kt * 128;
#pragma unroll
        for (int i = 0; i < 2; i++) {
            int c = tid + i * 256;
            int row = c >> 2;
            int part = (c & 3) << 3;
            size_t g = (base + k0 + row) * (NH * MB) + h * MB + part;
            *(uint4*)&sK[row * 40 + part] = *(const uint4*)&KEf[g];
        }
#pragma unroll
        for (int i = 0; i < 4; i++) {
            int c = tid + i * 256;
            int row = c >> 3;
            int part = (c & 7) << 3;
            size_t g = (base + k0 + row) * DM + h * HD + part;
            *(uint4*)&sV[row * 72 + part] = *(const uint4*)&Vf[g];
        }
        __syncthreads();

#pragma unroll
        for (int g8 = 0; g8 < 8; g8++) {
            // ---- scores for 16 keys (2 n-tiles), 1-term fp16 ----
            float sa0[4] = {0.f, 0.f, 0.f, 0.f};
            float sa1[4] = {0.f, 0.f, 0.f, 0.f};
#pragma unroll
            for (int kc = 0; kc < 2; kc++) {
                uint32_t r0, r1, r2, r3;
                uint32_t b0[2], b1[2];
                ldmx4(r0, r1, r2, r3,
                      smem_u32(&sK[(g8 * 16 + fr) * 40 + kc * 16 + fc]));
                b0[0] = r0; b0[1] = r2; b1[0] = r1; b1[1] = r3;
                mma16816h(sa0, qh[kc], b0);
                mma16816h(sa1, qh[kc], b1);
            }
            // ---- softmax: p = exp(s), fp16-normal range ----
            float p0 = __expf(sa0[0]), p1 = __expf(sa0[1]);
            float p2 = __expf(sa0[2]), p3 = __expf(sa0[3]);
            float p4 = __expf(sa1[0]), p5 = __expf(sa1[1]);
            float p6 = __expf(sa1[2]), p7 = __expf(sa1[3]);
            lr  += p0 + p1 + p4 + p5;
            lr8 += p2 + p3 + p6 + p7;
            uint32_t ph[4];
            ph[0] = pack2h(p0, p1);
            ph[1] = pack2h(p2, p3);
            ph[2] = pack2h(p4, p5);
            ph[3] = pack2h(p6, p7);
            // ---- P x V, single-term fp16 ----
#pragma unroll
            for (int nb = 0; nb < 4; nb++) {
                uint32_t r0, r1, r2, r3;
                uint32_t v0[2], v1[2];
                ldmx4t(r0, r1, r2, r3,
                       smem_u32(&sV[(g8 * 16 + fr) * 72 + nb * 16 + fc]));
                v0[0] = r0; v0[1] = r1; v1[0] = r2; v1[1] = r3;
                mma16816h(oacc[nb * 2 + 0], ph, v0);
                mma16816h(oacc[nb * 2 + 1], ph, v1);
            }
        }
        __syncthreads();
    }

    lr  += __shfl_xor_sync(0xffffffffu, lr, 1);
    lr  += __shfl_xor_sync(0xffffffffu, lr, 2);
    lr8 += __shfl_xor_sync(0xffffffffu, lr8, 1);
    lr8 += __shfl_xor_sync(0xffffffffu, lr8, 2);
    const float inv  = 1.f / lr;
    const float inv8 = 1.f / lr8;

    const size_t row0 = base + q0 + wm + gid;
#pragma unroll
    for (int nt = 0; nt < 8; nt++) {
        int col = h * HD + nt * 8 + tig * 2;
        uint32_t hh, ll;
        splitpackh(oacc[nt][0] * inv, oacc[nt][1] * inv, hh, ll);
        *(uint32_t*)&AOh[row0 * DM + col] = hh;
        *(uint32_t*)&AOl[row0 * DM + col] = ll;
        splitpackh(oacc[nt][2] * inv8, oacc[nt][3] * inv8, hh, ll);
        *(uint32_t*)&AOh[(row0 + 8) * DM + col] = hh;
        *(uint32_t*)&AOl[(row0 + 8) * DM + col] = ll;
    }
}

// ---------------------------------------------------------------------------
// Launch
// ---------------------------------------------------------------------------
extern "C" void kernel_launch(void* const* d_in, const int* in_sizes, int n_in,
                              void* d_out, int out_size)
{
    const float* x    = (const float*)d_in[0];
    const float* Wq   = (const float*)d_in[1];
    const float* Wk   = (const float*)d_in[2];
    const float* Wv   = (const float*)d_in[3];
    const float* Wenc = (const float*)d_in[4];
    const float* Wo   = (const float*)d_in[5];
    float* out = (float*)d_out;

    float *Qp, *Kp;
    __half *Vf, *xh, *xl, *AOh, *AOl, *QEf, *KEf;
    __half *Wqf, *Wkf, *Wvf, *Wof;
    cudaGetSymbolAddress((void**)&Qp,  g_Q);
    cudaGetSymbolAddress((void**)&Kp,  g_K);
    cudaGetSymbolAddress((void**)&Vf,  g_Vf);
    cudaGetSymbolAddress((void**)&xh,  g_xh);
    cudaGetSymbolAddress((void**)&xl,  g_xl);
    cudaGetSymbolAddress((void**)&AOh, g_AOh);
    cudaGetSymbolAddress((void**)&AOl, g_AOl);
    cudaGetSymbolAddress((void**)&QEf, g_QEf);
    cudaGetSymbolAddress((void**)&KEf, g_KEf);
    cudaGetSymbolAddress((void**)&Wqf, g_Wqf);
    cudaGetSymbolAddress((void**)&Wkf, g_Wkf);
    cudaGetSymbolAddress((void**)&Wvf, g_Wvf);
    cudaGetSymbolAddress((void**)&Wof, g_Wof);

    static bool init = false;
    if (!init) {
        cudaFuncSetAttribute(gemm_tc2, cudaFuncAttributeMaxDynamicSharedMemorySize,
                             GEMM_SMEM);
        cudaFuncSetAttribute(attn_tc, cudaFuncAttributeMaxDynamicSharedMemorySize,
                             ATTN_SMEM);
        init = true;
    }

    const int nx4 = ROWS_TOTAL * DM / 4;     // 2097152
    const int nw4 = DM * DM / 4;             // 262144

    split_h<<<nx4 / 256, 256>>>(x, xh, xl, nx4);
    dim3 gConv(nw4 / 256, 4);
    conv_half4<<<gConv, 256>>>(Wq, Wk, Wv, Wo, Wqf, Wkf, Wvf, Wof, nw4);

    dim3 gGemm(DM / 128, ROWS_TOTAL / 128);   // (8, 64)
    gemm_tc2<<<gGemm, 256, GEMM_SMEM>>>(xh, xl, Wqf, Qp, nullptr);
    gemm_tc2<<<gGemm, 256, GEMM_SMEM>>>(xh, xl, Wkf, Kp, nullptr);
    gemm_tc2<<<gGemm, 256, GEMM_SMEM>>>(xh, xl, Wvf, nullptr, Vf);

    dim3 gEnc(ROWS_TOTAL / 128, NH);          // (64, 16)
    enc2_kernel<<<gEnc, 256>>>(Qp, Wenc, QEf, SCALE);
    enc2_kernel<<<gEnc, 256>>>(Kp, Wenc, KEf, 1.0f);

    dim3 gAttn(SEQ / 128, NH, BSZ);           // (16, 16, 4)
    attn_tc<<<gAttn, 256, ATTN_SMEM>>>(QEf, KEf, Vf, AOh, AOl);

    gemm_tc2<<<gGemm, 256, GEMM_SMEM>>>(AOh, AOl, Wof, out, nullptr);
}

// round 9
// speedup vs baseline: 7.1977x; 1.3020x over previous
#include <cuda_runtime.h>
#include <cuda_bf16.h>
#include <cuda_fp16.h>
#include <math.h>
#include <stdint.h>

// Problem constants
#define BSZ 4
#define SEQ 2048
#define DM 1024
#define NH 16
#define HD 64
#define MB 32
#define ROWS_TOTAL (BSZ * SEQ)          // 8192
#define SCALE 0.17677669529663687f      // 1/sqrt(32)

// ---------------------------------------------------------------------------
// Scratch (no allocations allowed -> __device__ globals)
// ---------------------------------------------------------------------------
__device__ __align__(16) float g_Q[ROWS_TOTAL * DM];
__device__ __align__(16) float g_K[ROWS_TOTAL * DM];
__device__ __align__(16) __half g_Vf[ROWS_TOTAL * DM];
__device__ __align__(16) __half g_xf[ROWS_TOTAL * DM];
__device__ __align__(16) __half g_AOh[ROWS_TOTAL * DM];
__device__ __align__(16) __half g_AOl[ROWS_TOTAL * DM];
__device__ __align__(16) __half g_QEf[ROWS_TOTAL * NH * MB];
__device__ __align__(16) __half g_KEf[ROWS_TOTAL * NH * MB];
__device__ __align__(16) __half g_Wqf[DM * DM];
__device__ __align__(16) __half g_Wkf[DM * DM];
__device__ __align__(16) __half g_Wvf[DM * DM];
__device__ __align__(16) __half g_Wof[DM * DM];

// ---------------------------------------------------------------------------
// Helpers
// ---------------------------------------------------------------------------
static __device__ __forceinline__ uint32_t smem_u32(const void* p) {
    return (uint32_t)__cvta_generic_to_shared(p);
}

static __device__ __forceinline__ uint32_t pack2h(float a, float b) {
    __half2 t = __floats2half2_rn(a, b);
    return *(uint32_t*)&t;
}

static __device__ __forceinline__ void ldmx4(uint32_t& r0, uint32_t& r1,
                                             uint32_t& r2, uint32_t& r3,
                                             uint32_t addr) {
    asm volatile("ldmatrix.sync.aligned.m8n8.x4.shared.b16 {%0,%1,%2,%3}, [%4];"
                 : "=r"(r0), "=r"(r1), "=r"(r2), "=r"(r3) : "r"(addr));
}

static __device__ __forceinline__ void ldmx4t(uint32_t& r0, uint32_t& r1,
                                              uint32_t& r2, uint32_t& r3,
                                              uint32_t addr) {
    asm volatile("ldmatrix.sync.aligned.m8n8.x4.trans.shared.b16 {%0,%1,%2,%3}, [%4];"
                 : "=r"(r0), "=r"(r1), "=r"(r2), "=r"(r3) : "r"(addr));
}

static __device__ __forceinline__ void mma16816h(float* d, const uint32_t* a,
                                                 const uint32_t* b) {
    asm volatile(
        "mma.sync.aligned.m16n8k16.row.col.f32.f16.f16.f32 "
        "{%0,%1,%2,%3}, {%4,%5,%6,%7}, {%8,%9}, {%0,%1,%2,%3};"
        : "+f"(d[0]), "+f"(d[1]), "+f"(d[2]), "+f"(d[3])
        : "r"(a[0]), "r"(a[1]), "r"(a[2]), "r"(a[3]), "r"(b[0]), "r"(b[1]));
}

static __device__ __forceinline__ void splitpackh(float a, float b,
                                                  uint32_t& h, uint32_t& l) {
    float ha = __half2float(__float2half_rn(a));
    float hb = __half2float(__float2half_rn(b));
    h = pack2h(ha, hb);
    l = pack2h(a - ha, b - hb);
}

static __device__ __forceinline__ void cp16(uint32_t dst, const void* src) {
    asm volatile("cp.async.cg.shared.global [%0], [%1], 16;" :: "r"(dst), "l"(src));
}
static __device__ __forceinline__ void cp_commit() {
    asm volatile("cp.async.commit_group;");
}
template<int N> static __device__ __forceinline__ void cp_wait() {
    asm volatile("cp.async.wait_group %0;" :: "n"(N));
}

// ---------------------------------------------------------------------------
// fp32 -> fp16 conversions
// ---------------------------------------------------------------------------
__global__ __launch_bounds__(256) void conv_half(
    const float* __restrict__ src, __half* __restrict__ dst, int n4)
{
    int i = blockIdx.x * 256 + threadIdx.x;
    if (i < n4) {
        float4 v = ((const float4*)src)[i];
        uint2 o;
        o.x = pack2h(v.x, v.y);
        o.y = pack2h(v.z, v.w);
        ((uint2*)dst)[i] = o;
    }
}

// 4 weight matrices fp32 -> fp16 in one launch (blockIdx.y selects)
__global__ __launch_bounds__(256) void conv_half4(
    const float* __restrict__ s0, const float* __restrict__ s1,
    const float* __restrict__ s2, const float* __restrict__ s3,
    __half* __restrict__ d0, __half* __restrict__ d1,
    __half* __restrict__ d2, __half* __restrict__ d3, int n4)
{
    const float* s; __half* d;
    switch (blockIdx.y) {
        case 0: s = s0; d = d0; break;
        case 1: s = s1; d = d1; break;
        case 2: s = s2; d = d2; break;
        default: s = s3; d = d3; break;
    }
    int i = blockIdx.x * 256 + threadIdx.x;
    if (i < n4) {
        float4 v = ((const float4*)s)[i];
        uint2 o;
        o.x = pack2h(v.x, v.y);
        o.y = pack2h(v.z, v.w);
        ((uint2*)d)[i] = o;
    }
}

// ---------------------------------------------------------------------------
// Fused QKV GEMM, 1-term fp16. C[m,n] = sum_k x[m,k] * W[n,k].
// grid (24, 64): blockIdx.x>>3 selects {Wq->Q(f32), Wk->K(f32), Wv->V(f16)}.
// 128x128 CTA tile, BK=32, 8 warps (4M x 2N), 3-stage cp.async ring,
// ONE __syncthreads per K-iteration.
// ---------------------------------------------------------------------------
#define GKP 40
#define QKV_SMEM (3 * 2 * 128 * GKP * 2)   // 61440 bytes

__global__ __launch_bounds__(256, 2) void gemm_qkv(
    const __half* __restrict__ Ax,
    const __half* __restrict__ Bq, const __half* __restrict__ Bk,
    const __half* __restrict__ Bv,
    float* __restrict__ Cq, float* __restrict__ Ck, __half* __restrict__ Cv)
{
    extern __shared__ __align__(16) char smem[];
    const int tid  = threadIdx.x;
    const int wid  = tid >> 5;
    const int lane = tid & 31;
    const int which = blockIdx.x >> 3;
    const int bcol  = (blockIdx.x & 7) * 128;
    const int brow  = blockIdx.y * 128;
    const int wm   = (wid & 3) * 32;
    const int wn   = (wid >> 2) * 64;

    const __half* B = (which == 0) ? Bq : ((which == 1) ? Bk : Bv);

    auto buf = [&](int s, int a) -> __half* {
        return (__half*)smem + (size_t)(s * 2 + a) * 128 * GKP;
    };
    auto stage = [&](int s, int kt) {
#pragma unroll
        for (int i = 0; i < 4; i++) {
            int c = tid + i * 256;          // 0..1023
            int a = c >> 9;                 // 0..1
            int cc = c & 511;
            int row = cc >> 2;
            int part = (cc & 3) << 3;
            const __half* g = (a == 0)
                ? Ax + (size_t)(brow + row) * DM + kt * 32 + part
                : B  + (size_t)(bcol + row) * DM + kt * 32 + part;
            cp16(smem_u32(buf(s, a) + row * GKP + part), g);
        }
    };

    float acc[2][8][4];
#pragma unroll
    for (int mi = 0; mi < 2; mi++)
#pragma unroll
        for (int ni = 0; ni < 8; ni++)
#pragma unroll
            for (int j = 0; j < 4; j++) acc[mi][ni][j] = 0.f;

    const int fr = lane & 15;
    const int fc = (lane >> 4) << 3;

    stage(0, 0); cp_commit();
    stage(1, 1); cp_commit();

    for (int kt = 0; kt < 32; kt++) {
        if (kt < 31) cp_wait<1>(); else cp_wait<0>();
        __syncthreads();
        if (kt < 30) { stage((kt + 2) % 3, kt + 2); cp_commit(); }

        const int cur = kt % 3;
        const __half* pA = buf(cur, 0);
        const __half* pB = buf(cur, 1);

#pragma unroll
        for (int ks = 0; ks < 2; ks++) {
            const int kof = ks * 16 + fc;
            uint32_t a[2][4];
#pragma unroll
            for (int mi = 0; mi < 2; mi++)
                ldmx4(a[mi][0], a[mi][1], a[mi][2], a[mi][3],
                      smem_u32(pA + (wm + mi * 16 + fr) * GKP + kof));
            uint32_t b[8][2];
#pragma unroll
            for (int nq = 0; nq < 4; nq++) {
                uint32_t r0, r1, r2, r3;
                ldmx4(r0, r1, r2, r3, smem_u32(pB + (wn + nq * 16 + fr) * GKP + kof));
                b[nq * 2 + 0][0] = r0; b[nq * 2 + 0][1] = r2;
                b[nq * 2 + 1][0] = r1; b[nq * 2 + 1][1] = r3;
            }
#pragma unroll
            for (int mi = 0; mi < 2; mi++)
#pragma unroll
                for (int ni = 0; ni < 8; ni++)
                    mma16816h(acc[mi][ni], a[mi], b[ni]);
        }
    }

    const int er = lane >> 2;
    const int ec = (lane & 3) * 2;
    if (which < 2) {
        float* Cf = (which == 0) ? Cq : Ck;
#pragma unroll
        for (int mi = 0; mi < 2; mi++) {
#pragma unroll
            for (int ni = 0; ni < 8; ni++) {
                float* cp0 = Cf + (size_t)(brow + wm + mi * 16 + er) * DM + bcol + wn + ni * 8 + ec;
                *(float2*)cp0 = make_float2(acc[mi][ni][0], acc[mi][ni][1]);
                float* cp1 = cp0 + 8 * DM;
                *(float2*)cp1 = make_float2(acc[mi][ni][2], acc[mi][ni][3]);
            }
        }
    } else {
#pragma unroll
        for (int mi = 0; mi < 2; mi++) {
#pragma unroll
            for (int ni = 0; ni < 8; ni++) {
                __half* cp0 = Cv + (size_t)(brow + wm + mi * 16 + er) * DM + bcol + wn + ni * 8 + ec;
                *(uint32_t*)cp0 = pack2h(acc[mi][ni][0], acc[mi][ni][1]);
                __half* cp1 = cp0 + 8 * DM;
                *(uint32_t*)cp1 = pack2h(acc[mi][ni][2], acc[mi][ni][3]);
            }
        }
    }
}

// ---------------------------------------------------------------------------
// Wo GEMM, 2-term (A = AOh + AOl): out = (AOh+AOl) @ Wo^T, fp32 out.
// Same 3-stage single-barrier structure, 3 staged arrays.
// ---------------------------------------------------------------------------
#define WO_SMEM (3 * 3 * 128 * GKP * 2)   // 92160 bytes

__global__ __launch_bounds__(256, 2) void gemm_wo(
    const __half* __restrict__ Ah, const __half* __restrict__ Al,
    const __half* __restrict__ B, float* __restrict__ Cf)
{
    extern __shared__ __align__(16) char smem[];
    const int tid  = threadIdx.x;
    const int wid  = tid >> 5;
    const int lane = tid & 31;
    const int brow = blockIdx.y * 128;
    const int bcol = blockIdx.x * 128;
    const int wm   = (wid & 3) * 32;
    const int wn   = (wid >> 2) * 64;

    const __half* srcs[3] = {Ah, Al, B};

    auto buf = [&](int s, int a) -> __half* {
        return (__half*)smem + (size_t)(s * 3 + a) * 128 * GKP;
    };
    auto stage = [&](int s, int kt) {
#pragma unroll
        for (int i = 0; i < 6; i++) {
            int c = tid + i * 256;          // 0..1535
            int a = c >> 9;                 // 0..2
            int cc = c & 511;
            int row = cc >> 2;
            int part = (cc & 3) << 3;
            int rbase = (a < 2) ? brow : bcol;
            const __half* g = srcs[a] + (size_t)(rbase + row) * DM + kt * 32 + part;
            cp16(smem_u32(buf(s, a) + row * GKP + part), g);
        }
    };

    float acc[2][8][4];
#pragma unroll
    for (int mi = 0; mi < 2; mi++)
#pragma unroll
        for (int ni = 0; ni < 8; ni++)
#pragma unroll
            for (int j = 0; j < 4; j++) acc[mi][ni][j] = 0.f;

    const int fr = lane & 15;
    const int fc = (lane >> 4) << 3;

    stage(0, 0); cp_commit();
    stage(1, 1); cp_commit();

    for (int kt = 0; kt < 32; kt++) {
        if (kt < 31) cp_wait<1>(); else cp_wait<0>();
        __syncthreads();
        if (kt < 30) { stage((kt + 2) % 3, kt + 2); cp_commit(); }

        const int cur = kt % 3;
        const __half* pAh = buf(cur, 0);
        const __half* pAl = buf(cur, 1);
        const __half* pB  = buf(cur, 2);

#pragma unroll
        for (int ks = 0; ks < 2; ks++) {
            const int kof = ks * 16 + fc;
            uint32_t ah[2][4], al[2][4];
#pragma unroll
            for (int mi = 0; mi < 2; mi++) {
                ldmx4(ah[mi][0], ah[mi][1], ah[mi][2], ah[mi][3],
                      smem_u32(pAh + (wm + mi * 16 + fr) * GKP + kof));
                ldmx4(al[mi][0], al[mi][1], al[mi][2], al[mi][3],
                      smem_u32(pAl + (wm + mi * 16 + fr) * GKP + kof));
            }
            uint32_t b[8][2];
#pragma unroll
            for (int nq = 0; nq < 4; nq++) {
                uint32_t r0, r1, r2, r3;
                ldmx4(r0, r1, r2, r3, smem_u32(pB + (wn + nq * 16 + fr) * GKP + kof));
                b[nq * 2 + 0][0] = r0; b[nq * 2 + 0][1] = r2;
                b[nq * 2 + 1][0] = r1; b[nq * 2 + 1][1] = r3;
            }
#pragma unroll
            for (int mi = 0; mi < 2; mi++)
#pragma unroll
                for (int ni = 0; ni < 8; ni++) {
                    mma16816h(acc[mi][ni], ah[mi], b[ni]);
                    mma16816h(acc[mi][ni], al[mi], b[ni]);
                }
        }
    }

    const int er = lane >> 2;
    const int ec = (lane & 3) * 2;
#pragma unroll
    for (int mi = 0; mi < 2; mi++) {
#pragma unroll
        for (int ni = 0; ni < 8; ni++) {
            float* cp0 = Cf + (size_t)(brow + wm + mi * 16 + er) * DM + bcol + wn + ni * 8 + ec;
            *(float2*)cp0 = make_float2(acc[mi][ni][0], acc[mi][ni][1]);
            float* cp1 = cp0 + 8 * DM;
            *(float2*)cp1 = make_float2(acc[mi][ni][2], acc[mi][ni][3]);
        }
    }
}

// ---------------------------------------------------------------------------
// Witness encoder: register-blocked 4 rows x 4 bits per thread.
// ---------------------------------------------------------------------------
__global__ __launch_bounds__(256) void enc2_kernel(
    const float* __restrict__ X, const float* __restrict__ Wenc,
    __half* __restrict__ E, float scale)
{
    __shared__ float Ws[HD * MB];          // 8 KB
    __shared__ float Qs[128 * 65];         // 33.3 KB

    const int tid  = threadIdx.x;
    const int h    = blockIdx.y;
    const int row0 = blockIdx.x * 128;

    for (int i = tid; i < HD * MB; i += 256)
        Ws[i] = Wenc[h * HD * MB + i];
    for (int i = tid; i < 128 * HD; i += 256) {
        int r = i >> 6;
        int d = i & 63;
        Qs[r * 65 + d] = X[(size_t)(row0 + r) * DM + h * HD + d];
    }
    __syncthreads();

    const int r0 = (tid >> 3) * 4;
    const int m0 = (tid & 7) * 4;

    float s[4][4];
#pragma unroll
    for (int i = 0; i < 4; i++)
#pragma unroll
        for (int j = 0; j < 4; j++) s[i][j] = 0.f;

#pragma unroll 8
    for (int d = 0; d < HD; d++) {
        float q0 = Qs[(r0 + 0) * 65 + d];
        float q1 = Qs[(r0 + 1) * 65 + d];
        float q2 = Qs[(r0 + 2) * 65 + d];
        float q3 = Qs[(r0 + 3) * 65 + d];
        float w0 = Ws[d * MB + m0 + 0];
        float w1 = Ws[d * MB + m0 + 1];
        float w2 = Ws[d * MB + m0 + 2];
        float w3 = Ws[d * MB + m0 + 3];
        s[0][0] = fmaf(q0, w0, s[0][0]); s[0][1] = fmaf(q0, w1, s[0][1]);
        s[0][2] = fmaf(q0, w2, s[0][2]); s[0][3] = fmaf(q0, w3, s[0][3]);
        s[1][0] = fmaf(q1, w0, s[1][0]); s[1][1] = fmaf(q1, w1, s[1][1]);
        s[1][2] = fmaf(q1, w2, s[1][2]); s[1][3] = fmaf(q1, w3, s[1][3]);
        s[2][0] = fmaf(q2, w0, s[2][0]); s[2][1] = fmaf(q2, w1, s[2][1]);
        s[2][2] = fmaf(q2, w2, s[2][2]); s[2][3] = fmaf(q2, w3, s[2][3]);
        s[3][0] = fmaf(q3, w0, s[3][0]); s[3][1] = fmaf(q3, w1, s[3][1]);
        s[3][2] = fmaf(q3, w2, s[3][2]); s[3][3] = fmaf(q3, w3, s[3][3]);
    }

#pragma unroll
    for (int i = 0; i < 4; i++) {
        float e0 = tanhf(s[i][0]) * scale;
        float e1 = tanhf(s[i][1]) * scale;
        float e2 = tanhf(s[i][2]) * scale;
        float e3 = tanhf(s[i][3]) * scale;
        size_t off = ((size_t)(row0 + r0 + i) * NH + h) * MB + m0;
        uint2 o;
        o.x = pack2h(e0, e1);
        o.y = pack2h(e2, e3);
        *(uint2*)&E[off] = o;
    }
}

// ---------------------------------------------------------------------------
// Tensor-core flash attention: scores = 1-term fp16, PV = 1-term fp16.
// p = exp(s) directly (|s| <= 5.66 -> p in [3.5e-3, 287], fp16-normal range).
// grid (SEQ/128, NH, BSZ), 8 warps; warp = 16 q rows; key tiles of 128.
// ---------------------------------------------------------------------------
#define ATTN_SMEM (128 * 40 * 2 + 128 * 72 * 2)   // 28672 bytes

__global__ __launch_bounds__(256, 2) void attn_tc(
    const __half* __restrict__ QEf, const __half* __restrict__ KEf,
    const __half* __restrict__ Vf,
    __half* __restrict__ AOh, __half* __restrict__ AOl)
{
    extern __shared__ __align__(16) char smem[];
    __half* sK = (__half*)smem;              // 128 x 40
    __half* sV = sK + 128 * 40;              // 128 x 72

    const int tid  = threadIdx.x;
    const int wid  = tid >> 5;
    const int lane = tid & 31;
    const int h = blockIdx.y;
    const int b = blockIdx.z;
    const size_t base = (size_t)b * SEQ;
    const int q0 = blockIdx.x * 128;
    const int wm = wid * 16;
    const int fr = lane & 15;
    const int fc = (lane >> 4) << 3;
    const int gid = lane >> 2;
    const int tig = lane & 3;

    // ---- stage Q -> sK, load A fragments ----
#pragma unroll
    for (int i = 0; i < 2; i++) {
        int c = tid + i * 256;
        int row = c >> 2;
        int part = (c & 3) << 3;
        size_t g = (base + q0 + row) * (NH * MB) + h * MB + part;
        *(uint4*)&sK[row * 40 + part] = *(const uint4*)&QEf[g];
    }
    __syncthreads();
    uint32_t qh[2][4];
#pragma unroll
    for (int kc = 0; kc < 2; kc++) {
        ldmx4(qh[kc][0], qh[kc][1], qh[kc][2], qh[kc][3],
              smem_u32(&sK[(wm + fr) * 40 + kc * 16 + fc]));
    }
    __syncthreads();

    float oacc[8][4];
#pragma unroll
    for (int nt = 0; nt < 8; nt++)
#pragma unroll
        for (int j = 0; j < 4; j++) oacc[nt][j] = 0.f;
    float lr = 0.f, lr8 = 0.f;

    for (int kt = 0; kt < 16; kt++) {
        const int k0 = kt * 128;
#pragma unroll
        for (int i = 0; i < 2; i++) {
            int c = tid + i * 256;
            int row = c >> 2;
            int part = (c & 3) << 3;
            size_t g = (base + k0 + row) * (NH * MB) + h * MB + part;
            *(uint4*)&sK[row * 40 + part] = *(const uint4*)&KEf[g];
        }
#pragma unroll
        for (int i = 0; i < 4; i++) {
            int c = tid + i * 256;
            int row = c >> 3;
            int part = (c & 7) << 3;
            size_t g = (base + k0 + row) * DM + h * HD + part;
            *(uint4*)&sV[row * 72 + part] = *(const uint4*)&Vf[g];
        }
        __syncthreads();

#pragma unroll
        for (int g8 = 0; g8 < 8; g8++) {
            // ---- scores for 16 keys (2 n-tiles), 1-term fp16 ----
            float sa0[4] = {0.f, 0.f, 0.f, 0.f};
            float sa1[4] = {0.f, 0.f, 0.f, 0.f};
#pragma unroll
            for (int kc = 0; kc < 2; kc++) {
                uint32_t r0, r1, r2, r3;
                uint32_t b0[2], b1[2];
                ldmx4(r0, r1, r2, r3,
                      smem_u32(&sK[(g8 * 16 + fr) * 40 + kc * 16 + fc]));
                b0[0] = r0; b0[1] = r2; b1[0] = r1; b1[1] = r3;
                mma16816h(sa0, qh[kc], b0);
                mma16816h(sa1, qh[kc], b1);
            }
            // ---- softmax: p = exp(s), fp16-normal range ----
            float p0 = __expf(sa0[0]), p1 = __expf(sa0[1]);
            float p2 = __expf(sa0[2]), p3 = __expf(sa0[3]);
            float p4 = __expf(sa1[0]), p5 = __expf(sa1[1]);
            float p6 = __expf(sa1[2]), p7 = __expf(sa1[3]);
            lr  += p0 + p1 + p4 + p5;
            lr8 += p2 + p3 + p6 + p7;
            uint32_t ph[4];
            ph[0] = pack2h(p0, p1);
            ph[1] = pack2h(p2, p3);
            ph[2] = pack2h(p4, p5);
            ph[3] = pack2h(p6, p7);
            // ---- P x V, single-term fp16 ----
#pragma unroll
            for (int nb = 0; nb < 4; nb++) {
                uint32_t r0, r1, r2, r3;
                uint32_t v0[2], v1[2];
                ldmx4t(r0, r1, r2, r3,
                       smem_u32(&sV[(g8 * 16 + fr) * 72 + nb * 16 + fc]));
                v0[0] = r0; v0[1] = r1; v1[0] = r2; v1[1] = r3;
                mma16816h(oacc[nb * 2 + 0], ph, v0);
                mma16816h(oacc[nb * 2 + 1], ph, v1);
            }
        }
        __syncthreads();
    }

    lr  += __shfl_xor_sync(0xffffffffu, lr, 1);
    lr  += __shfl_xor_sync(0xffffffffu, lr, 2);
    lr8 += __shfl_xor_sync(0xffffffffu, lr8, 1);
    lr8 += __shfl_xor_sync(0xffffffffu, lr8, 2);
    const float inv  = 1.f / lr;
    const float inv8 = 1.f / lr8;

    const size_t row0 = base + q0 + wm + gid;
#pragma unroll
    for (int nt = 0; nt < 8; nt++) {
        int col = h * HD + nt * 8 + tig * 2;
        uint32_t hh, ll;
        splitpackh(oacc[nt][0] * inv, oacc[nt][1] * inv, hh, ll);
        *(uint32_t*)&AOh[row0 * DM + col] = hh;
        *(uint32_t*)&AOl[row0 * DM + col] = ll;
        splitpackh(oacc[nt][2] * inv8, oacc[nt][3] * inv8, hh, ll);
        *(uint32_t*)&AOh[(row0 + 8) * DM + col] = hh;
        *(uint32_t*)&AOl[(row0 + 8) * DM + col] = ll;
    }
}

// ---------------------------------------------------------------------------
// Launch
// ---------------------------------------------------------------------------
extern "C" void kernel_launch(void* const* d_in, const int* in_sizes, int n_in,
                              void* d_out, int out_size)
{
    const float* x    = (const float*)d_in[0];
    const float* Wq   = (const float*)d_in[1];
    const float* Wk   = (const float*)d_in[2];
    const float* Wv   = (const float*)d_in[3];
    const float* Wenc = (const float*)d_in[4];
    const float* Wo   = (const float*)d_in[5];
    float* out = (float*)d_out;

    float *Qp, *Kp;
    __half *Vf, *xf, *AOh, *AOl, *QEf, *KEf;
    __half *Wqf, *Wkf, *Wvf, *Wof;
    cudaGetSymbolAddress((void**)&Qp,  g_Q);
    cudaGetSymbolAddress((void**)&Kp,  g_K);
    cudaGetSymbolAddress((void**)&Vf,  g_Vf);
    cudaGetSymbolAddress((void**)&xf,  g_xf);
    cudaGetSymbolAddress((void**)&AOh, g_AOh);
    cudaGetSymbolAddress((void**)&AOl, g_AOl);
    cudaGetSymbolAddress((void**)&QEf, g_QEf);
    cudaGetSymbolAddress((void**)&KEf, g_KEf);
    cudaGetSymbolAddress((void**)&Wqf, g_Wqf);
    cudaGetSymbolAddress((void**)&Wkf, g_Wkf);
    cudaGetSymbolAddress((void**)&Wvf, g_Wvf);
    cudaGetSymbolAddress((void**)&Wof, g_Wof);

    static bool init = false;
    if (!init) {
        cudaFuncSetAttribute(gemm_qkv, cudaFuncAttributeMaxDynamicSharedMemorySize,
                             QKV_SMEM);
        cudaFuncSetAttribute(gemm_wo, cudaFuncAttributeMaxDynamicSharedMemorySize,
                             WO_SMEM);
        cudaFuncSetAttribute(attn_tc, cudaFuncAttributeMaxDynamicSharedMemorySize,
                             ATTN_SMEM);
        init = true;
    }

    const int nx4 = ROWS_TOTAL * DM / 4;     // 2097152
    const int nw4 = DM * DM / 4;             // 262144

    conv_half<<<nx4 / 256, 256>>>(x, xf, nx4);
    dim3 gConv(nw4 / 256, 4);
    conv_half4<<<gConv, 256>>>(Wq, Wk, Wv, Wo, Wqf, Wkf, Wvf, Wof, nw4);

    dim3 gQKV(3 * DM / 128, ROWS_TOTAL / 128);   // (24, 64)
    gemm_qkv<<<gQKV, 256, QKV_SMEM>>>(xf, Wqf, Wkf, Wvf, Qp, Kp, Vf);

    dim3 gEnc(ROWS_TOTAL / 128, NH);             // (64, 16)
    enc2_kernel<<<gEnc, 256>>>(Qp, Wenc, QEf, SCALE);
    enc2_kernel<<<gEnc, 256>>>(Kp, Wenc, KEf, 1.0f);

    dim3 gAttn(SEQ / 128, NH, BSZ);              // (16, 16, 4)
    attn_tc<<<gAttn, 256, ATTN_SMEM>>>(QEf, KEf, Vf, AOh, AOl);

    dim3 gWo(DM / 128, ROWS_TOTAL / 128);        // (8, 64)
    gemm_wo<<<gWo, 256, WO_SMEM>>>(AOh, AOl, Wof, out);
}

// round 10
// speedup vs baseline: 8.5645x; 1.1899x over previous
#include <cuda_runtime.h>
#include <cuda_bf16.h>
#include <cuda_fp16.h>
#include <math.h>
#include <stdint.h>

// Problem constants
#define BSZ 4
#define SEQ 2048
#define DM 1024
#define NH 16
#define HD 64
#define MB 32
#define ROWS_TOTAL (BSZ * SEQ)          // 8192
#define SCALE 0.17677669529663687f      // 1/sqrt(32)

// ---------------------------------------------------------------------------
// Scratch (no allocations allowed -> __device__ globals)
// ---------------------------------------------------------------------------
__device__ __align__(16) __half g_Qh[ROWS_TOTAL * DM];
__device__ __align__(16) __half g_Kh[ROWS_TOTAL * DM];
__device__ __align__(16) __half g_Vf[ROWS_TOTAL * DM];
__device__ __align__(16) __half g_xf[ROWS_TOTAL * DM];
__device__ __align__(16) __half g_AOf[ROWS_TOTAL * DM];
__device__ __align__(16) __half g_QEf[ROWS_TOTAL * NH * MB];
__device__ __align__(16) __half g_KEf[ROWS_TOTAL * NH * MB];
__device__ __align__(16) __half g_Wqf[DM * DM];
__device__ __align__(16) __half g_Wkf[DM * DM];
__device__ __align__(16) __half g_Wvf[DM * DM];
__device__ __align__(16) __half g_Wof[DM * DM];

// ---------------------------------------------------------------------------
// Helpers
// ---------------------------------------------------------------------------
static __device__ __forceinline__ uint32_t smem_u32(const void* p) {
    return (uint32_t)__cvta_generic_to_shared(p);
}

static __device__ __forceinline__ uint32_t pack2h(float a, float b) {
    __half2 t = __floats2half2_rn(a, b);
    return *(uint32_t*)&t;
}

static __device__ __forceinline__ void ldmx4(uint32_t& r0, uint32_t& r1,
                                             uint32_t& r2, uint32_t& r3,
                                             uint32_t addr) {
    asm volatile("ldmatrix.sync.aligned.m8n8.x4.shared.b16 {%0,%1,%2,%3}, [%4];"
                 : "=r"(r0), "=r"(r1), "=r"(r2), "=r"(r3) : "r"(addr));
}

static __device__ __forceinline__ void ldmx4t(uint32_t& r0, uint32_t& r1,
                                              uint32_t& r2, uint32_t& r3,
                                              uint32_t addr) {
    asm volatile("ldmatrix.sync.aligned.m8n8.x4.trans.shared.b16 {%0,%1,%2,%3}, [%4];"
                 : "=r"(r0), "=r"(r1), "=r"(r2), "=r"(r3) : "r"(addr));
}

static __device__ __forceinline__ void mma16816h(float* d, const uint32_t* a,
                                                 const uint32_t* b) {
    asm volatile(
        "mma.sync.aligned.m16n8k16.row.col.f32.f16.f16.f32 "
        "{%0,%1,%2,%3}, {%4,%5,%6,%7}, {%8,%9}, {%0,%1,%2,%3};"
        : "+f"(d[0]), "+f"(d[1]), "+f"(d[2]), "+f"(d[3])
        : "r"(a[0]), "r"(a[1]), "r"(a[2]), "r"(a[3]), "r"(b[0]), "r"(b[1]));
}

static __device__ __forceinline__ void cp16(uint32_t dst, const void* src) {
    asm volatile("cp.async.cg.shared.global [%0], [%1], 16;" :: "r"(dst), "l"(src));
}
static __device__ __forceinline__ void cp_commit() {
    asm volatile("cp.async.commit_group;");
}
template<int N> static __device__ __forceinline__ void cp_wait() {
    asm volatile("cp.async.wait_group %0;" :: "n"(N));
}

// ---------------------------------------------------------------------------
// fp32 -> fp16 conversions
// ---------------------------------------------------------------------------
__global__ __launch_bounds__(256) void conv_half(
    const float* __restrict__ src, __half* __restrict__ dst, int n4)
{
    int i = blockIdx.x * 256 + threadIdx.x;
    if (i < n4) {
        float4 v = ((const float4*)src)[i];
        uint2 o;
        o.x = pack2h(v.x, v.y);
        o.y = pack2h(v.z, v.w);
        ((uint2*)dst)[i] = o;
    }
}

__global__ __launch_bounds__(256) void conv_half4(
    const float* __restrict__ s0, const float* __restrict__ s1,
    const float* __restrict__ s2, const float* __restrict__ s3,
    __half* __restrict__ d0, __half* __restrict__ d1,
    __half* __restrict__ d2, __half* __restrict__ d3, int n4)
{
    const float* s; __half* d;
    switch (blockIdx.y) {
        case 0: s = s0; d = d0; break;
        case 1: s = s1; d = d1; break;
        case 2: s = s2; d = d2; break;
        default: s = s3; d = d3; break;
    }
    int i = blockIdx.x * 256 + threadIdx.x;
    if (i < n4) {
        float4 v = ((const float4*)s)[i];
        uint2 o;
        o.x = pack2h(v.x, v.y);
        o.y = pack2h(v.z, v.w);
        ((uint2*)d)[i] = o;
    }
}

// ---------------------------------------------------------------------------
// Fused QKV GEMM, 1-term fp16, fp16 outputs.
// grid (24, 64): blockIdx.x>>3 selects {Wq->Q, Wk->K, Wv->V}.
// 128x128 tile, BK=32, 8 warps, 3-stage cp.async ring, one barrier/iter.
// ---------------------------------------------------------------------------
#define GKP 40
#define QKV_SMEM (3 * 2 * 128 * GKP * 2)   // 61440 bytes

__global__ __launch_bounds__(256, 2) void gemm_qkv(
    const __half* __restrict__ Ax,
    const __half* __restrict__ Bq, const __half* __restrict__ Bk,
    const __half* __restrict__ Bv,
    __half* __restrict__ Cq, __half* __restrict__ Ck, __half* __restrict__ Cv)
{
    extern __shared__ __align__(16) char smem[];
    const int tid  = threadIdx.x;
    const int wid  = tid >> 5;
    const int lane = tid & 31;
    const int which = blockIdx.x >> 3;
    const int bcol  = (blockIdx.x & 7) * 128;
    const int brow  = blockIdx.y * 128;
    const int wm   = (wid & 3) * 32;
    const int wn   = (wid >> 2) * 64;

    const __half* B = (which == 0) ? Bq : ((which == 1) ? Bk : Bv);
    __half* Co = (which == 0) ? Cq : ((which == 1) ? Ck : Cv);

    auto buf = [&](int s, int a) -> __half* {
        return (__half*)smem + (size_t)(s * 2 + a) * 128 * GKP;
    };
    auto stage = [&](int s, int kt) {
#pragma unroll
        for (int i = 0; i < 4; i++) {
            int c = tid + i * 256;
            int a = c >> 9;
            int cc = c & 511;
            int row = cc >> 2;
            int part = (cc & 3) << 3;
            const __half* g = (a == 0)
                ? Ax + (size_t)(brow + row) * DM + kt * 32 + part
                : B  + (size_t)(bcol + row) * DM + kt * 32 + part;
            cp16(smem_u32(buf(s, a) + row * GKP + part), g);
        }
    };

    float acc[2][8][4];
#pragma unroll
    for (int mi = 0; mi < 2; mi++)
#pragma unroll
        for (int ni = 0; ni < 8; ni++)
#pragma unroll
            for (int j = 0; j < 4; j++) acc[mi][ni][j] = 0.f;

    const int fr = lane & 15;
    const int fc = (lane >> 4) << 3;

    stage(0, 0); cp_commit();
    stage(1, 1); cp_commit();

    for (int kt = 0; kt < 32; kt++) {
        if (kt < 31) cp_wait<1>(); else cp_wait<0>();
        __syncthreads();
        if (kt < 30) { stage((kt + 2) % 3, kt + 2); cp_commit(); }

        const int cur = kt % 3;
        const __half* pA = buf(cur, 0);
        const __half* pB = buf(cur, 1);

#pragma unroll
        for (int ks = 0; ks < 2; ks++) {
            const int kof = ks * 16 + fc;
            uint32_t a[2][4];
#pragma unroll
            for (int mi = 0; mi < 2; mi++)
                ldmx4(a[mi][0], a[mi][1], a[mi][2], a[mi][3],
                      smem_u32(pA + (wm + mi * 16 + fr) * GKP + kof));
            uint32_t b[8][2];
#pragma unroll
            for (int nq = 0; nq < 4; nq++) {
                uint32_t r0, r1, r2, r3;
                ldmx4(r0, r1, r2, r3, smem_u32(pB + (wn + nq * 16 + fr) * GKP + kof));
                b[nq * 2 + 0][0] = r0; b[nq * 2 + 0][1] = r2;
                b[nq * 2 + 1][0] = r1; b[nq * 2 + 1][1] = r3;
            }
#pragma unroll
            for (int mi = 0; mi < 2; mi++)
#pragma unroll
                for (int ni = 0; ni < 8; ni++)
                    mma16816h(acc[mi][ni], a[mi], b[ni]);
        }
    }

    const int er = lane >> 2;
    const int ec = (lane & 3) * 2;
#pragma unroll
    for (int mi = 0; mi < 2; mi++) {
#pragma unroll
        for (int ni = 0; ni < 8; ni++) {
            __half* cp0 = Co + (size_t)(brow + wm + mi * 16 + er) * DM + bcol + wn + ni * 8 + ec;
            *(uint32_t*)cp0 = pack2h(acc[mi][ni][0], acc[mi][ni][1]);
            __half* cp1 = cp0 + 8 * DM;
            *(uint32_t*)cp1 = pack2h(acc[mi][ni][2], acc[mi][ni][3]);
        }
    }
}

// ---------------------------------------------------------------------------
// AO @ Wo^T GEMM, 1-term fp16, fp32 out. Same 3-stage single-barrier ring.
// ---------------------------------------------------------------------------
__global__ __launch_bounds__(256, 2) void gemm_ao(
    const __half* __restrict__ Aa, const __half* __restrict__ B,
    float* __restrict__ Cf)
{
    extern __shared__ __align__(16) char smem[];
    const int tid  = threadIdx.x;
    const int wid  = tid >> 5;
    const int lane = tid & 31;
    const int brow = blockIdx.y * 128;
    const int bcol = blockIdx.x * 128;
    const int wm   = (wid & 3) * 32;
    const int wn   = (wid >> 2) * 64;

    auto buf = [&](int s, int a) -> __half* {
        return (__half*)smem + (size_t)(s * 2 + a) * 128 * GKP;
    };
    auto stage = [&](int s, int kt) {
#pragma unroll
        for (int i = 0; i < 4; i++) {
            int c = tid + i * 256;
            int a = c >> 9;
            int cc = c & 511;
            int row = cc >> 2;
            int part = (cc & 3) << 3;
            const __half* g = (a == 0)
                ? Aa + (size_t)(brow + row) * DM + kt * 32 + part
                : B  + (size_t)(bcol + row) * DM + kt * 32 + part;
            cp16(smem_u32(buf(s, a) + row * GKP + part), g);
        }
    };

    float acc[2][8][4];
#pragma unroll
    for (int mi = 0; mi < 2; mi++)
#pragma unroll
        for (int ni = 0; ni < 8; ni++)
#pragma unroll
            for (int j = 0; j < 4; j++) acc[mi][ni][j] = 0.f;

    const int fr = lane & 15;
    const int fc = (lane >> 4) << 3;

    stage(0, 0); cp_commit();
    stage(1, 1); cp_commit();

    for (int kt = 0; kt < 32; kt++) {
        if (kt < 31) cp_wait<1>(); else cp_wait<0>();
        __syncthreads();
        if (kt < 30) { stage((kt + 2) % 3, kt + 2); cp_commit(); }

        const int cur = kt % 3;
        const __half* pA = buf(cur, 0);
        const __half* pB = buf(cur, 1);

#pragma unroll
        for (int ks = 0; ks < 2; ks++) {
            const int kof = ks * 16 + fc;
            uint32_t a[2][4];
#pragma unroll
            for (int mi = 0; mi < 2; mi++)
                ldmx4(a[mi][0], a[mi][1], a[mi][2], a[mi][3],
                      smem_u32(pA + (wm + mi * 16 + fr) * GKP + kof));
            uint32_t b[8][2];
#pragma unroll
            for (int nq = 0; nq < 4; nq++) {
                uint32_t r0, r1, r2, r3;
                ldmx4(r0, r1, r2, r3, smem_u32(pB + (wn + nq * 16 + fr) * GKP + kof));
                b[nq * 2 + 0][0] = r0; b[nq * 2 + 0][1] = r2;
                b[nq * 2 + 1][0] = r1; b[nq * 2 + 1][1] = r3;
            }
#pragma unroll
            for (int mi = 0; mi < 2; mi++)
#pragma unroll
                for (int ni = 0; ni < 8; ni++)
                    mma16816h(acc[mi][ni], a[mi], b[ni]);
        }
    }

    const int er = lane >> 2;
    const int ec = (lane & 3) * 2;
#pragma unroll
    for (int mi = 0; mi < 2; mi++) {
#pragma unroll
        for (int ni = 0; ni < 8; ni++) {
            float* cp0 = Cf + (size_t)(brow + wm + mi * 16 + er) * DM + bcol + wn + ni * 8 + ec;
            *(float2*)cp0 = make_float2(acc[mi][ni][0], acc[mi][ni][1]);
            float* cp1 = cp0 + 8 * DM;
            *(float2*)cp1 = make_float2(acc[mi][ni][2], acc[mi][ni][3]);
        }
    }
}

// ---------------------------------------------------------------------------
// Witness encoder: fp16 input, register-blocked 4 rows x 4 bits per thread.
// ---------------------------------------------------------------------------
__global__ __launch_bounds__(256) void enc2_kernel(
    const __half* __restrict__ X, const float* __restrict__ Wenc,
    __half* __restrict__ E, float scale)
{
    __shared__ float Ws[HD * MB];          // 8 KB
    __shared__ float Qs[128 * 65];         // 33.3 KB

    const int tid  = threadIdx.x;
    const int h    = blockIdx.y;
    const int row0 = blockIdx.x * 128;

    for (int i = tid; i < HD * MB; i += 256)
        Ws[i] = Wenc[h * HD * MB + i];
#pragma unroll
    for (int i = 0; i < 4; i++) {
        int idx = tid + i * 256;           // 0..1023
        int r = idx >> 3;
        int d = (idx & 7) << 3;
        uint4 v = *(const uint4*)&X[(size_t)(row0 + r) * DM + h * HD + d];
        const __half2* hp = (const __half2*)&v;
#pragma unroll
        for (int j = 0; j < 4; j++) {
            float2 f = __half22float2(hp[j]);
            Qs[r * 65 + d + j * 2 + 0] = f.x;
            Qs[r * 65 + d + j * 2 + 1] = f.y;
        }
    }
    __syncthreads();

    const int r0 = (tid >> 3) * 4;
    const int m0 = (tid & 7) * 4;

    float s[4][4];
#pragma unroll
    for (int i = 0; i < 4; i++)
#pragma unroll
        for (int j = 0; j < 4; j++) s[i][j] = 0.f;

#pragma unroll 8
    for (int d = 0; d < HD; d++) {
        float q0 = Qs[(r0 + 0) * 65 + d];
        float q1 = Qs[(r0 + 1) * 65 + d];
        float q2 = Qs[(r0 + 2) * 65 + d];
        float q3 = Qs[(r0 + 3) * 65 + d];
        float w0 = Ws[d * MB + m0 + 0];
        float w1 = Ws[d * MB + m0 + 1];
        float w2 = Ws[d * MB + m0 + 2];
        float w3 = Ws[d * MB + m0 + 3];
        s[0][0] = fmaf(q0, w0, s[0][0]); s[0][1] = fmaf(q0, w1, s[0][1]);
        s[0][2] = fmaf(q0, w2, s[0][2]); s[0][3] = fmaf(q0, w3, s[0][3]);
        s[1][0] = fmaf(q1, w0, s[1][0]); s[1][1] = fmaf(q1, w1, s[1][1]);
        s[1][2] = fmaf(q1, w2, s[1][2]); s[1][3] = fmaf(q1, w3, s[1][3]);
        s[2][0] = fmaf(q2, w0, s[2][0]); s[2][1] = fmaf(q2, w1, s[2][1]);
        s[2][2] = fmaf(q2, w2, s[2][2]); s[2][3] = fmaf(q2, w3, s[2][3]);
        s[3][0] = fmaf(q3, w0, s[3][0]); s[3][1] = fmaf(q3, w1, s[3][1]);
        s[3][2] = fmaf(q3, w2, s[3][2]); s[3][3] = fmaf(q3, w3, s[3][3]);
    }

#pragma unroll
    for (int i = 0; i < 4; i++) {
        float e0 = tanhf(s[i][0]) * scale;
        float e1 = tanhf(s[i][1]) * scale;
        float e2 = tanhf(s[i][2]) * scale;
        float e3 = tanhf(s[i][3]) * scale;
        size_t off = ((size_t)(row0 + r0 + i) * NH + h) * MB + m0;
        uint2 o;
        o.x = pack2h(e0, e1);
        o.y = pack2h(e2, e3);
        *(uint2*)&E[off] = o;
    }
}

// ---------------------------------------------------------------------------
// Tensor-core flash attention: 1-term fp16 scores + PV, p = exp(s).
// 3-stage cp.async ring for K/V tiles, one barrier per tile.
// grid (SEQ/128, NH, BSZ), 8 warps; warp = 16 q rows; key tiles of 128.
// ---------------------------------------------------------------------------
#define AK 40
#define AV 72
#define ATTN_STAGE ((128 * AK + 128 * AV) * 2)    // 28672 bytes
#define ATTN_SMEM (3 * ATTN_STAGE)                // 86016 bytes

__global__ __launch_bounds__(256, 2) void attn_tc(
    const __half* __restrict__ QEf, const __half* __restrict__ KEf,
    const __half* __restrict__ Vf, __half* __restrict__ AOf)
{
    extern __shared__ __align__(16) char smem[];

    const int tid  = threadIdx.x;
    const int wid  = tid >> 5;
    const int lane = tid & 31;
    const int h = blockIdx.y;
    const int b = blockIdx.z;
    const size_t base = (size_t)b * SEQ;
    const int q0 = blockIdx.x * 128;
    const int wm = wid * 16;
    const int fr = lane & 15;
    const int fc = (lane >> 4) << 3;
    const int gid = lane >> 2;
    const int tig = lane & 3;

    auto bufK = [&](int s) -> __half* {
        return (__half*)(smem + (size_t)s * ATTN_STAGE);
    };
    auto bufV = [&](int s) -> __half* {
        return (__half*)(smem + (size_t)s * ATTN_STAGE) + 128 * AK;
    };
    auto stage = [&](int s, int kt) {
        const int k0 = kt * 128;
        __half* sK = bufK(s);
        __half* sV = bufV(s);
#pragma unroll
        for (int i = 0; i < 2; i++) {
            int c = tid + i * 256;          // 0..511
            int row = c >> 2;
            int part = (c & 3) << 3;
            cp16(smem_u32(sK + row * AK + part),
                 KEf + (base + k0 + row) * (NH * MB) + h * MB + part);
        }
#pragma unroll
        for (int i = 0; i < 4; i++) {
            int c = tid + i * 256;          // 0..1023
            int row = c >> 3;
            int part = (c & 7) << 3;
            cp16(smem_u32(sV + row * AV + part),
                 Vf + (base + k0 + row) * DM + h * HD + part);
        }
    };

    // ---- stage Q into buffer 0's K region, extract fragments ----
    {
        __half* sQ = bufK(0);
#pragma unroll
        for (int i = 0; i < 2; i++) {
            int c = tid + i * 256;
            int row = c >> 2;
            int part = (c & 3) << 3;
            size_t g = (base + q0 + row) * (NH * MB) + h * MB + part;
            *(uint4*)&sQ[row * AK + part] = *(const uint4*)&QEf[g];
        }
    }
    __syncthreads();
    uint32_t qh[2][4];
    {
        __half* sQ = bufK(0);
#pragma unroll
        for (int kc = 0; kc < 2; kc++)
            ldmx4(qh[kc][0], qh[kc][1], qh[kc][2], qh[kc][3],
                  smem_u32(&sQ[(wm + fr) * AK + kc * 16 + fc]));
    }
    __syncthreads();

    float oacc[8][4];
#pragma unroll
    for (int nt = 0; nt < 8; nt++)
#pragma unroll
        for (int j = 0; j < 4; j++) oacc[nt][j] = 0.f;
    float lr = 0.f, lr8 = 0.f;

    stage(0, 0); cp_commit();
    stage(1, 1); cp_commit();

    for (int kt = 0; kt < 16; kt++) {
        if (kt < 15) cp_wait<1>(); else cp_wait<0>();
        __syncthreads();
        if (kt < 14) { stage((kt + 2) % 3, kt + 2); cp_commit(); }

        const int cur = kt % 3;
        __half* sK = bufK(cur);
        __half* sV = bufV(cur);

#pragma unroll
        for (int g8 = 0; g8 < 8; g8++) {
            // ---- scores for 16 keys (2 n-tiles), 1-term fp16 ----
            float sa0[4] = {0.f, 0.f, 0.f, 0.f};
            float sa1[4] = {0.f, 0.f, 0.f, 0.f};
#pragma unroll
            for (int kc = 0; kc < 2; kc++) {
                uint32_t r0, r1, r2, r3;
                uint32_t b0[2], b1[2];
                ldmx4(r0, r1, r2, r3,
                      smem_u32(&sK[(g8 * 16 + fr) * AK + kc * 16 + fc]));
                b0[0] = r0; b0[1] = r2; b1[0] = r1; b1[1] = r3;
                mma16816h(sa0, qh[kc], b0);
                mma16816h(sa1, qh[kc], b1);
            }
            // ---- softmax: p = exp(s) (|s| <= 5.66 -> fp16-normal) ----
            float p0 = __expf(sa0[0]), p1 = __expf(sa0[1]);
            float p2 = __expf(sa0[2]), p3 = __expf(sa0[3]);
            float p4 = __expf(sa1[0]), p5 = __expf(sa1[1]);
            float p6 = __expf(sa1[2]), p7 = __expf(sa1[3]);
            lr  += p0 + p1 + p4 + p5;
            lr8 += p2 + p3 + p6 + p7;
            uint32_t ph[4];
            ph[0] = pack2h(p0, p1);
            ph[1] = pack2h(p2, p3);
            ph[2] = pack2h(p4, p5);
            ph[3] = pack2h(p6, p7);
            // ---- P x V, single-term fp16 ----
#pragma unroll
            for (int nb = 0; nb < 4; nb++) {
                uint32_t r0, r1, r2, r3;
                uint32_t v0[2], v1[2];
                ldmx4t(r0, r1, r2, r3,
                       smem_u32(&sV[(g8 * 16 + fr) * AV + nb * 16 + fc]));
                v0[0] = r0; v0[1] = r1; v1[0] = r2; v1[1] = r3;
                mma16816h(oacc[nb * 2 + 0], ph, v0);
                mma16816h(oacc[nb * 2 + 1], ph, v1);
            }
        }
    }

    lr  += __shfl_xor_sync(0xffffffffu, lr, 1);
    lr  += __shfl_xor_sync(0xffffffffu, lr, 2);
    lr8 += __shfl_xor_sync(0xffffffffu, lr8, 1);
    lr8 += __shfl_xor_sync(0xffffffffu, lr8, 2);
    const float inv  = 1.f / lr;
    const float inv8 = 1.f / lr8;

    const size_t row0 = base + q0 + wm + gid;
#pragma unroll
    for (int nt = 0; nt < 8; nt++) {
        int col = h * HD + nt * 8 + tig * 2;
        *(uint32_t*)&AOf[row0 * DM + col] =
            pack2h(oacc[nt][0] * inv, oacc[nt][1] * inv);
        *(uint32_t*)&AOf[(row0 + 8) * DM + col] =
            pack2h(oacc[nt][2] * inv8, oacc[nt][3] * inv8);
    }
}

// ---------------------------------------------------------------------------
// Launch
// ---------------------------------------------------------------------------
extern "C" void kernel_launch(void* const* d_in, const int* in_sizes, int n_in,
                              void* d_out, int out_size)
{
    const float* x    = (const float*)d_in[0];
    const float* Wq   = (const float*)d_in[1];
    const float* Wk   = (const float*)d_in[2];
    const float* Wv   = (const float*)d_in[3];
    const float* Wenc = (const float*)d_in[4];
    const float* Wo   = (const float*)d_in[5];
    float* out = (float*)d_out;

    __half *Qh, *Kh, *Vf, *xf, *AOf, *QEf, *KEf;
    __half *Wqf, *Wkf, *Wvf, *Wof;
    cudaGetSymbolAddress((void**)&Qh,  g_Qh);
    cudaGetSymbolAddress((void**)&Kh,  g_Kh);
    cudaGetSymbolAddress((void**)&Vf,  g_Vf);
    cudaGetSymbolAddress((void**)&xf,  g_xf);
    cudaGetSymbolAddress((void**)&AOf, g_AOf);
    cudaGetSymbolAddress((void**)&QEf, g_QEf);
    cudaGetSymbolAddress((void**)&KEf, g_KEf);
    cudaGetSymbolAddress((void**)&Wqf, g_Wqf);
    cudaGetSymbolAddress((void**)&Wkf, g_Wkf);
    cudaGetSymbolAddress((void**)&Wvf, g_Wvf);
    cudaGetSymbolAddress((void**)&Wof, g_Wof);

    static bool init = false;
    if (!init) {
        cudaFuncSetAttribute(gemm_qkv, cudaFuncAttributeMaxDynamicSharedMemorySize,
                             QKV_SMEM);
        cudaFuncSetAttribute(gemm_ao, cudaFuncAttributeMaxDynamicSharedMemorySize,
                             QKV_SMEM);
        cudaFuncSetAttribute(attn_tc, cudaFuncAttributeMaxDynamicSharedMemorySize,
                             ATTN_SMEM);
        init = true;
    }

    const int nx4 = ROWS_TOTAL * DM / 4;     // 2097152
    const int nw4 = DM * DM / 4;             // 262144

    conv_half<<<nx4 / 256, 256>>>(x, xf, nx4);
    dim3 gConv(nw4 / 256, 4);
    conv_half4<<<gConv, 256>>>(Wq, Wk, Wv, Wo, Wqf, Wkf, Wvf, Wof, nw4);

    dim3 gQKV(3 * DM / 128, ROWS_TOTAL / 128);   // (24, 64)
    gemm_qkv<<<gQKV, 256, QKV_SMEM>>>(xf, Wqf, Wkf, Wvf, Qh, Kh, Vf);

    dim3 gEnc(ROWS_TOTAL / 128, NH);             // (64, 16)
    enc2_kernel<<<gEnc, 256>>>(Qh, Wenc, QEf, SCALE);
    enc2_kernel<<<gEnc, 256>>>(Kh, Wenc, KEf, 1.0f);

    dim3 gAttn(SEQ / 128, NH, BSZ);              // (16, 16, 4)
    attn_tc<<<gAttn, 256, ATTN_SMEM>>>(QEf, KEf, Vf, AOf);

    dim3 gWo(DM / 128, ROWS_TOTAL / 128);        // (8, 64)
    gemm_ao<<<gWo, 256, QKV_SMEM>>>(AOf, Wof, out);
}

// round 11
// speedup vs baseline: 9.8280x; 1.1475x over previous
#include <cuda_runtime.h>
#include <cuda_bf16.h>
#include <cuda_fp16.h>
#include <math.h>
#include <stdint.h>

// Problem constants
#define BSZ 4
#define SEQ 2048
#define DM 1024
#define NH 16
#define HD 64
#define MB 32
#define ROWS_TOTAL (BSZ * SEQ)          // 8192
#define SCALE 0.17677669529663687f      // 1/sqrt(32)

// ---------------------------------------------------------------------------
// Scratch (no allocations allowed -> __device__ globals)
// ---------------------------------------------------------------------------
__device__ __align__(16) __half g_Qh[ROWS_TOTAL * DM];
__device__ __align__(16) __half g_Kh[ROWS_TOTAL * DM];
__device__ __align__(16) __half g_Vf[ROWS_TOTAL * DM];
__device__ __align__(16) __half g_xf[ROWS_TOTAL * DM];
__device__ __align__(16) __half g_AOf[ROWS_TOTAL * DM];
__device__ __align__(16) __half g_QEf[ROWS_TOTAL * NH * MB];
__device__ __align__(16) __half g_KEf[ROWS_TOTAL * NH * MB];
__device__ __align__(16) __half g_Wqf[DM * DM];
__device__ __align__(16) __half g_Wkf[DM * DM];
__device__ __align__(16) __half g_Wvf[DM * DM];
__device__ __align__(16) __half g_Wof[DM * DM];

// ---------------------------------------------------------------------------
// Helpers
// ---------------------------------------------------------------------------
static __device__ __forceinline__ uint32_t smem_u32(const void* p) {
    return (uint32_t)__cvta_generic_to_shared(p);
}

static __device__ __forceinline__ uint32_t pack2h(float a, float b) {
    __half2 t = __floats2half2_rn(a, b);
    return *(uint32_t*)&t;
}

static __device__ __forceinline__ void ldmx4(uint32_t& r0, uint32_t& r1,
                                             uint32_t& r2, uint32_t& r3,
                                             uint32_t addr) {
    asm volatile("ldmatrix.sync.aligned.m8n8.x4.shared.b16 {%0,%1,%2,%3}, [%4];"
                 : "=r"(r0), "=r"(r1), "=r"(r2), "=r"(r3) : "r"(addr));
}

static __device__ __forceinline__ void ldmx4t(uint32_t& r0, uint32_t& r1,
                                              uint32_t& r2, uint32_t& r3,
                                              uint32_t addr) {
    asm volatile("ldmatrix.sync.aligned.m8n8.x4.trans.shared.b16 {%0,%1,%2,%3}, [%4];"
                 : "=r"(r0), "=r"(r1), "=r"(r2), "=r"(r3) : "r"(addr));
}

static __device__ __forceinline__ void mma16816h(float* d, const uint32_t* a,
                                                 const uint32_t* b) {
    asm volatile(
        "mma.sync.aligned.m16n8k16.row.col.f32.f16.f16.f32 "
        "{%0,%1,%2,%3}, {%4,%5,%6,%7}, {%8,%9}, {%0,%1,%2,%3};"
        : "+f"(d[0]), "+f"(d[1]), "+f"(d[2]), "+f"(d[3])
        : "r"(a[0]), "r"(a[1]), "r"(a[2]), "r"(a[3]), "r"(b[0]), "r"(b[1]));
}

static __device__ __forceinline__ void cp16(uint32_t dst, const void* src) {
    asm volatile("cp.async.cg.shared.global [%0], [%1], 16;" :: "r"(dst), "l"(src));
}
static __device__ __forceinline__ void cp_commit() {
    asm volatile("cp.async.commit_group;");
}
template<int N> static __device__ __forceinline__ void cp_wait() {
    asm volatile("cp.async.wait_group %0;" :: "n"(N));
}

// ---------------------------------------------------------------------------
// fp32 -> fp16 conversions
// ---------------------------------------------------------------------------
__global__ __launch_bounds__(256) void conv_half(
    const float* __restrict__ src, __half* __restrict__ dst, int n4)
{
    int i = blockIdx.x * 256 + threadIdx.x;
    if (i < n4) {
        float4 v = ((const float4*)src)[i];
        uint2 o;
        o.x = pack2h(v.x, v.y);
        o.y = pack2h(v.z, v.w);
        ((uint2*)dst)[i] = o;
    }
}

__global__ __launch_bounds__(256) void conv_half4(
    const float* __restrict__ s0, const float* __restrict__ s1,
    const float* __restrict__ s2, const float* __restrict__ s3,
    __half* __restrict__ d0, __half* __restrict__ d1,
    __half* __restrict__ d2, __half* __restrict__ d3, int n4)
{
    const float* s; __half* d;
    switch (blockIdx.y) {
        case 0: s = s0; d = d0; break;
        case 1: s = s1; d = d1; break;
        case 2: s = s2; d = d2; break;
        default: s = s3; d = d3; break;
    }
    int i = blockIdx.x * 256 + threadIdx.x;
    if (i < n4) {
        float4 v = ((const float4*)s)[i];
        uint2 o;
        o.x = pack2h(v.x, v.y);
        o.y = pack2h(v.z, v.w);
        ((uint2*)d)[i] = o;
    }
}

// ---------------------------------------------------------------------------
// Fused QKV GEMM, 1-term fp16, fp16 outputs. BK=64, 2-stage cp.async ring,
// one barrier per K-iter (16 iters).
// grid (24, 64): blockIdx.x>>3 selects {Wq->Q, Wk->K, Wv->V}.
// ---------------------------------------------------------------------------
#define GKP 72
#define GEMM_SMEM (2 * 2 * 128 * GKP * 2)   // 73728 bytes

__global__ __launch_bounds__(256, 2) void gemm_qkv(
    const __half* __restrict__ Ax,
    const __half* __restrict__ Bq, const __half* __restrict__ Bk,
    const __half* __restrict__ Bv,
    __half* __restrict__ Cq, __half* __restrict__ Ck, __half* __restrict__ Cv)
{
    extern __shared__ __align__(16) char smem[];
    const int tid  = threadIdx.x;
    const int wid  = tid >> 5;
    const int lane = tid & 31;
    const int which = blockIdx.x >> 3;
    const int bcol  = (blockIdx.x & 7) * 128;
    const int brow  = blockIdx.y * 128;
    const int wm   = (wid & 3) * 32;
    const int wn   = (wid >> 2) * 64;

    const __half* B = (which == 0) ? Bq : ((which == 1) ? Bk : Bv);
    __half* Co = (which == 0) ? Cq : ((which == 1) ? Ck : Cv);

    auto buf = [&](int s, int a) -> __half* {
        return (__half*)smem + (size_t)(s * 2 + a) * 128 * GKP;
    };
    auto stage = [&](int s, int kt) {
#pragma unroll
        for (int i = 0; i < 8; i++) {
            int c = tid + i * 256;          // 0..2047
            int a = c >> 10;                // 0..1
            int cc = c & 1023;
            int row = cc >> 3;
            int part = (cc & 7) << 3;
            const __half* g = (a == 0)
                ? Ax + (size_t)(brow + row) * DM + kt * 64 + part
                : B  + (size_t)(bcol + row) * DM + kt * 64 + part;
            cp16(smem_u32(buf(s, a) + row * GKP + part), g);
        }
    };

    float acc[2][8][4];
#pragma unroll
    for (int mi = 0; mi < 2; mi++)
#pragma unroll
        for (int ni = 0; ni < 8; ni++)
#pragma unroll
            for (int j = 0; j < 4; j++) acc[mi][ni][j] = 0.f;

    const int fr = lane & 15;
    const int fc = (lane >> 4) << 3;

    stage(0, 0); cp_commit();

    for (int kt = 0; kt < 16; kt++) {
        cp_wait<0>();
        __syncthreads();
        if (kt < 15) { stage((kt + 1) & 1, kt + 1); cp_commit(); }

        const int cur = kt & 1;
        const __half* pA = buf(cur, 0);
        const __half* pB = buf(cur, 1);

#pragma unroll
        for (int ks = 0; ks < 4; ks++) {
            const int kof = ks * 16 + fc;
            uint32_t a[2][4];
#pragma unroll
            for (int mi = 0; mi < 2; mi++)
                ldmx4(a[mi][0], a[mi][1], a[mi][2], a[mi][3],
                      smem_u32(pA + (wm + mi * 16 + fr) * GKP + kof));
            uint32_t b[8][2];
#pragma unroll
            for (int nq = 0; nq < 4; nq++) {
                uint32_t r0, r1, r2, r3;
                ldmx4(r0, r1, r2, r3, smem_u32(pB + (wn + nq * 16 + fr) * GKP + kof));
                b[nq * 2 + 0][0] = r0; b[nq * 2 + 0][1] = r2;
                b[nq * 2 + 1][0] = r1; b[nq * 2 + 1][1] = r3;
            }
#pragma unroll
            for (int mi = 0; mi < 2; mi++)
#pragma unroll
                for (int ni = 0; ni < 8; ni++)
                    mma16816h(acc[mi][ni], a[mi], b[ni]);
        }
    }

    const int er = lane >> 2;
    const int ec = (lane & 3) * 2;
#pragma unroll
    for (int mi = 0; mi < 2; mi++) {
#pragma unroll
        for (int ni = 0; ni < 8; ni++) {
            __half* cp0 = Co + (size_t)(brow + wm + mi * 16 + er) * DM + bcol + wn + ni * 8 + ec;
            *(uint32_t*)cp0 = pack2h(acc[mi][ni][0], acc[mi][ni][1]);
            __half* cp1 = cp0 + 8 * DM;
            *(uint32_t*)cp1 = pack2h(acc[mi][ni][2], acc[mi][ni][3]);
        }
    }
}

// ---------------------------------------------------------------------------
// AO @ Wo^T GEMM, 1-term fp16, fp32 out. BK=64, 2-stage ring.
// ---------------------------------------------------------------------------
__global__ __launch_bounds__(256, 2) void gemm_ao(
    const __half* __restrict__ Aa, const __half* __restrict__ B,
    float* __restrict__ Cf)
{
    extern __shared__ __align__(16) char smem[];
    const int tid  = threadIdx.x;
    const int wid  = tid >> 5;
    const int lane = tid & 31;
    const int brow = blockIdx.y * 128;
    const int bcol = blockIdx.x * 128;
    const int wm   = (wid & 3) * 32;
    const int wn   = (wid >> 2) * 64;

    auto buf = [&](int s, int a) -> __half* {
        return (__half*)smem + (size_t)(s * 2 + a) * 128 * GKP;
    };
    auto stage = [&](int s, int kt) {
#pragma unroll
        for (int i = 0; i < 8; i++) {
            int c = tid + i * 256;
            int a = c >> 10;
            int cc = c & 1023;
            int row = cc >> 3;
            int part = (cc & 7) << 3;
            const __half* g = (a == 0)
                ? Aa + (size_t)(brow + row) * DM + kt * 64 + part
                : B  + (size_t)(bcol + row) * DM + kt * 64 + part;
            cp16(smem_u32(buf(s, a) + row * GKP + part), g);
        }
    };

    float acc[2][8][4];
#pragma unroll
    for (int mi = 0; mi < 2; mi++)
#pragma unroll
        for (int ni = 0; ni < 8; ni++)
#pragma unroll
            for (int j = 0; j < 4; j++) acc[mi][ni][j] = 0.f;

    const int fr = lane & 15;
    const int fc = (lane >> 4) << 3;

    stage(0, 0); cp_commit();

    for (int kt = 0; kt < 16; kt++) {
        cp_wait<0>();
        __syncthreads();
        if (kt < 15) { stage((kt + 1) & 1, kt + 1); cp_commit(); }

        const int cur = kt & 1;
        const __half* pA = buf(cur, 0);
        const __half* pB = buf(cur, 1);

#pragma unroll
        for (int ks = 0; ks < 4; ks++) {
            const int kof = ks * 16 + fc;
            uint32_t a[2][4];
#pragma unroll
            for (int mi = 0; mi < 2; mi++)
                ldmx4(a[mi][0], a[mi][1], a[mi][2], a[mi][3],
                      smem_u32(pA + (wm + mi * 16 + fr) * GKP + kof));
            uint32_t b[8][2];
#pragma unroll
            for (int nq = 0; nq < 4; nq++) {
                uint32_t r0, r1, r2, r3;
                ldmx4(r0, r1, r2, r3, smem_u32(pB + (wn + nq * 16 + fr) * GKP + kof));
                b[nq * 2 + 0][0] = r0; b[nq * 2 + 0][1] = r2;
                b[nq * 2 + 1][0] = r1; b[nq * 2 + 1][1] = r3;
            }
#pragma unroll
            for (int mi = 0; mi < 2; mi++)
#pragma unroll
                for (int ni = 0; ni < 8; ni++)
                    mma16816h(acc[mi][ni], a[mi], b[ni]);
        }
    }

    const int er = lane >> 2;
    const int ec = (lane & 3) * 2;
#pragma unroll
    for (int mi = 0; mi < 2; mi++) {
#pragma unroll
        for (int ni = 0; ni < 8; ni++) {
            float* cp0 = Cf + (size_t)(brow + wm + mi * 16 + er) * DM + bcol + wn + ni * 8 + ec;
            *(float2*)cp0 = make_float2(acc[mi][ni][0], acc[mi][ni][1]);
            float* cp1 = cp0 + 8 * DM;
            *(float2*)cp1 = make_float2(acc[mi][ni][2], acc[mi][ni][3]);
        }
    }
}

// ---------------------------------------------------------------------------
// Tensor-core witness encoder: E = tanh(X_head @ Wenc_head) * scale.
// grid (ROWS/128, NH, 2): z=0 -> Q path (scale), z=1 -> K path.
// A = X slice [128x64] fp16 (ldmx4); B = Wenc [d][m] fp16 via trans ldmatrix.
// tanh applied on fp32 accumulator fragments. 8 warps, 16 MMAs/warp.
// ---------------------------------------------------------------------------
__global__ __launch_bounds__(256) void enc3_kernel(
    const __half* __restrict__ Qh, const __half* __restrict__ Kh,
    const float* __restrict__ Wenc,
    __half* __restrict__ QE, __half* __restrict__ KE)
{
    __shared__ __align__(16) __half sX[128 * 72];   // 18 KB
    __shared__ __align__(16) __half sW[64 * 40];    // 5 KB

    const int tid  = threadIdx.x;
    const int wid  = tid >> 5;
    const int lane = tid & 31;
    const int h    = blockIdx.y;
    const int row0 = blockIdx.x * 128;
    const int z    = blockIdx.z;

    const __half* X = z ? Kh : Qh;
    __half* E = z ? KE : QE;
    const float scale = z ? 1.0f : SCALE;

    // stage X slice [128 rows][64 cols]
#pragma unroll
    for (int i = 0; i < 4; i++) {
        int idx = tid + i * 256;           // 0..1023
        int r = idx >> 3;
        int c = (idx & 7) << 3;
        *(uint4*)&sX[r * 72 + c] =
            *(const uint4*)&X[(size_t)(row0 + r) * DM + h * HD + c];
    }
    // stage Wenc[h] [64 d][32 m] fp32 -> fp16
#pragma unroll
    for (int i = 0; i < 4; i++) {
        int idx = tid + i * 256;           // 0..1023 (pairs)
        int d = idx >> 4;
        int m = (idx & 15) * 2;
        float2 w = *(const float2*)&Wenc[(size_t)h * HD * MB + d * MB + m];
        *(uint32_t*)&sW[d * 40 + m] = pack2h(w.x, w.y);
    }
    __syncthreads();

    const int wm = wid * 16;
    const int fr = lane & 15;
    const int fc = (lane >> 4) << 3;

    float acc[4][4];
#pragma unroll
    for (int nt = 0; nt < 4; nt++)
#pragma unroll
        for (int j = 0; j < 4; j++) acc[nt][j] = 0.f;

#pragma unroll
    for (int kc = 0; kc < 4; kc++) {
        uint32_t a[4];
        ldmx4(a[0], a[1], a[2], a[3],
              smem_u32(&sX[(wm + fr) * 72 + kc * 16 + fc]));
#pragma unroll
        for (int nb = 0; nb < 2; nb++) {
            uint32_t r0, r1, r2, r3;
            uint32_t b0[2], b1[2];
            ldmx4t(r0, r1, r2, r3,
                   smem_u32(&sW[(kc * 16 + fr) * 40 + nb * 16 + fc]));
            b0[0] = r0; b0[1] = r1; b1[0] = r2; b1[1] = r3;
            mma16816h(acc[nb * 2 + 0], a, b0);
            mma16816h(acc[nb * 2 + 1], a, b1);
        }
    }

    const int er = lane >> 2;
    const int ec = (lane & 3) * 2;
    const size_t r0g = (size_t)(row0 + wm + er);
#pragma unroll
    for (int nt = 0; nt < 4; nt++) {
        int m = nt * 8 + ec;
        *(uint32_t*)&E[(r0g * NH + h) * MB + m] =
            pack2h(tanhf(acc[nt][0]) * scale, tanhf(acc[nt][1]) * scale);
        *(uint32_t*)&E[((r0g + 8) * NH + h) * MB + m] =
            pack2h(tanhf(acc[nt][2]) * scale, tanhf(acc[nt][3]) * scale);
    }
}

// ---------------------------------------------------------------------------
// Tensor-core flash attention: 1-term fp16 scores + PV, p = exp(s).
// 3-stage cp.async ring for K/V tiles, one barrier per tile.
// grid (SEQ/128, NH, BSZ), 8 warps; warp = 16 q rows; key tiles of 128.
// ---------------------------------------------------------------------------
#define AK 40
#define AV 72
#define ATTN_STAGE ((128 * AK + 128 * AV) * 2)    // 28672 bytes
#define ATTN_SMEM (3 * ATTN_STAGE)                // 86016 bytes

__global__ __launch_bounds__(256, 2) void attn_tc(
    const __half* __restrict__ QEf, const __half* __restrict__ KEf,
    const __half* __restrict__ Vf, __half* __restrict__ AOf)
{
    extern __shared__ __align__(16) char smem[];

    const int tid  = threadIdx.x;
    const int wid  = tid >> 5;
    const int lane = tid & 31;
    const int h = blockIdx.y;
    const int b = blockIdx.z;
    const size_t base = (size_t)b * SEQ;
    const int q0 = blockIdx.x * 128;
    const int wm = wid * 16;
    const int fr = lane & 15;
    const int fc = (lane >> 4) << 3;
    const int gid = lane >> 2;
    const int tig = lane & 3;

    auto bufK = [&](int s) -> __half* {
        return (__half*)(smem + (size_t)s * ATTN_STAGE);
    };
    auto bufV = [&](int s) -> __half* {
        return (__half*)(smem + (size_t)s * ATTN_STAGE) + 128 * AK;
    };
    auto stage = [&](int s, int kt) {
        const int k0 = kt * 128;
        __half* sK = bufK(s);
        __half* sV = bufV(s);
#pragma unroll
        for (int i = 0; i < 2; i++) {
            int c = tid + i * 256;
            int row = c >> 2;
            int part = (c & 3) << 3;
            cp16(smem_u32(sK + row * AK + part),
                 KEf + (base + k0 + row) * (NH * MB) + h * MB + part);
        }
#pragma unroll
        for (int i = 0; i < 4; i++) {
            int c = tid + i * 256;
            int row = c >> 3;
            int part = (c & 7) << 3;
            cp16(smem_u32(sV + row * AV + part),
                 Vf + (base + k0 + row) * DM + h * HD + part);
        }
    };

    // ---- stage Q into buffer 0's K region, extract fragments ----
    {
        __half* sQ = bufK(0);
#pragma unroll
        for (int i = 0; i < 2; i++) {
            int c = tid + i * 256;
            int row = c >> 2;
            int part = (c & 3) << 3;
            size_t g = (base + q0 + row) * (NH * MB) + h * MB + part;
            *(uint4*)&sQ[row * AK + part] = *(const uint4*)&QEf[g];
        }
    }
    __syncthreads();
    uint32_t qh[2][4];
    {
        __half* sQ = bufK(0);
#pragma unroll
        for (int kc = 0; kc < 2; kc++)
            ldmx4(qh[kc][0], qh[kc][1], qh[kc][2], qh[kc][3],
                  smem_u32(&sQ[(wm + fr) * AK + kc * 16 + fc]));
    }
    __syncthreads();

    float oacc[8][4];
#pragma unroll
    for (int nt = 0; nt < 8; nt++)
#pragma unroll
        for (int j = 0; j < 4; j++) oacc[nt][j] = 0.f;
    float lr = 0.f, lr8 = 0.f;

    stage(0, 0); cp_commit();
    stage(1, 1); cp_commit();

    for (int kt = 0; kt < 16; kt++) {
        if (kt < 15) cp_wait<1>(); else cp_wait<0>();
        __syncthreads();
        if (kt < 14) { stage((kt + 2) % 3, kt + 2); cp_commit(); }

        const int cur = kt % 3;
        __half* sK = bufK(cur);
        __half* sV = bufV(cur);

#pragma unroll
        for (int g8 = 0; g8 < 8; g8++) {
            float sa0[4] = {0.f, 0.f, 0.f, 0.f};
            float sa1[4] = {0.f, 0.f, 0.f, 0.f};
#pragma unroll
            for (int kc = 0; kc < 2; kc++) {
                uint32_t r0, r1, r2, r3;
                uint32_t b0[2], b1[2];
                ldmx4(r0, r1, r2, r3,
                      smem_u32(&sK[(g8 * 16 + fr) * AK + kc * 16 + fc]));
                b0[0] = r0; b0[1] = r2; b1[0] = r1; b1[1] = r3;
                mma16816h(sa0, qh[kc], b0);
                mma16816h(sa1, qh[kc], b1);
            }
            float p0 = __expf(sa0[0]), p1 = __expf(sa0[1]);
            float p2 = __expf(sa0[2]), p3 = __expf(sa0[3]);
            float p4 = __expf(sa1[0]), p5 = __expf(sa1[1]);
            float p6 = __expf(sa1[2]), p7 = __expf(sa1[3]);
            lr  += p0 + p1 + p4 + p5;
            lr8 += p2 + p3 + p6 + p7;
            uint32_t ph[4];
            ph[0] = pack2h(p0, p1);
            ph[1] = pack2h(p2, p3);
            ph[2] = pack2h(p4, p5);
            ph[3] = pack2h(p6, p7);
#pragma unroll
            for (int nb = 0; nb < 4; nb++) {
                uint32_t r0, r1, r2, r3;
                uint32_t v0[2], v1[2];
                ldmx4t(r0, r1, r2, r3,
                       smem_u32(&sV[(g8 * 16 + fr) * AV + nb * 16 + fc]));
                v0[0] = r0; v0[1] = r1; v1[0] = r2; v1[1] = r3;
                mma16816h(oacc[nb * 2 + 0], ph, v0);
                mma16816h(oacc[nb * 2 + 1], ph, v1);
            }
        }
    }

    lr  += __shfl_xor_sync(0xffffffffu, lr, 1);
    lr  += __shfl_xor_sync(0xffffffffu, lr, 2);
    lr8 += __shfl_xor_sync(0xffffffffu, lr8, 1);
    lr8 += __shfl_xor_sync(0xffffffffu, lr8, 2);
    const float inv  = 1.f / lr;
    const float inv8 = 1.f / lr8;

    const size_t row0 = base + q0 + wm + gid;
#pragma unroll
    for (int nt = 0; nt < 8; nt++) {
        int col = h * HD + nt * 8 + tig * 2;
        *(uint32_t*)&AOf[row0 * DM + col] =
            pack2h(oacc[nt][0] * inv, oacc[nt][1] * inv);
        *(uint32_t*)&AOf[(row0 + 8) * DM + col] =
            pack2h(oacc[nt][2] * inv8, oacc[nt][3] * inv8);
    }
}

// ---------------------------------------------------------------------------
// Launch
// ---------------------------------------------------------------------------
extern "C" void kernel_launch(void* const* d_in, const int* in_sizes, int n_in,
                              void* d_out, int out_size)
{
    const float* x    = (const float*)d_in[0];
    const float* Wq   = (const float*)d_in[1];
    const float* Wk   = (const float*)d_in[2];
    const float* Wv   = (const float*)d_in[3];
    const float* Wenc = (const float*)d_in[4];
    const float* Wo   = (const float*)d_in[5];
    float* out = (float*)d_out;

    __half *Qh, *Kh, *Vf, *xf, *AOf, *QEf, *KEf;
    __half *Wqf, *Wkf, *Wvf, *Wof;
    cudaGetSymbolAddress((void**)&Qh,  g_Qh);
    cudaGetSymbolAddress((void**)&Kh,  g_Kh);
    cudaGetSymbolAddress((void**)&Vf,  g_Vf);
    cudaGetSymbolAddress((void**)&xf,  g_xf);
    cudaGetSymbolAddress((void**)&AOf, g_AOf);
    cudaGetSymbolAddress((void**)&QEf, g_QEf);
    cudaGetSymbolAddress((void**)&KEf, g_KEf);
    cudaGetSymbolAddress((void**)&Wqf, g_Wqf);
    cudaGetSymbolAddress((void**)&Wkf, g_Wkf);
    cudaGetSymbolAddress((void**)&Wvf, g_Wvf);
    cudaGetSymbolAddress((void**)&Wof, g_Wof);

    static bool init = false;
    if (!init) {
        cudaFuncSetAttribute(gemm_qkv, cudaFuncAttributeMaxDynamicSharedMemorySize,
                             GEMM_SMEM);
        cudaFuncSetAttribute(gemm_ao, cudaFuncAttributeMaxDynamicSharedMemorySize,
                             GEMM_SMEM);
        cudaFuncSetAttribute(attn_tc, cudaFuncAttributeMaxDynamicSharedMemorySize,
                             ATTN_SMEM);
        init = true;
    }

    const int nx4 = ROWS_TOTAL * DM / 4;     // 2097152
    const int nw4 = DM * DM / 4;             // 262144

    conv_half<<<nx4 / 256, 256>>>(x, xf, nx4);
    dim3 gConv(nw4 / 256, 4);
    conv_half4<<<gConv, 256>>>(Wq, Wk, Wv, Wo, Wqf, Wkf, Wvf, Wof, nw4);

    dim3 gQKV(3 * DM / 128, ROWS_TOTAL / 128);   // (24, 64)
    gemm_qkv<<<gQKV, 256, GEMM_SMEM>>>(xf, Wqf, Wkf, Wvf, Qh, Kh, Vf);

    dim3 gEnc(ROWS_TOTAL / 128, NH, 2);          // (64, 16, 2)
    enc3_kernel<<<gEnc, 256>>>(Qh, Kh, Wenc, QEf, KEf);

    dim3 gAttn(SEQ / 128, NH, BSZ);              // (16, 16, 4)
    attn_tc<<<gAttn, 256, ATTN_SMEM>>>(QEf, KEf, Vf, AOf);

    dim3 gWo(DM / 128, ROWS_TOTAL / 128);        // (8, 64)
    gemm_ao<<<gWo, 256, GEMM_SMEM>>>(AOf, Wof, out);
}

// round 12
// speedup vs baseline: 10.2963x; 1.0477x over previous
#include <cuda_runtime.h>
#include <cuda_bf16.h>
#include <cuda_fp16.h>
#include <math.h>
#include <stdint.h>

// Problem constants
#define BSZ 4
#define SEQ 2048
#define DM 1024
#define NH 16
#define HD 64
#define MB 32
#define ROWS_TOTAL (BSZ * SEQ)          // 8192
#define SCALE 0.17677669529663687f      // 1/sqrt(32)
#define LOG2E 1.4426950408889634f

// ---------------------------------------------------------------------------
// Scratch (no allocations allowed -> __device__ globals)
// ---------------------------------------------------------------------------
__device__ __align__(16) __half g_Qh[ROWS_TOTAL * DM];
__device__ __align__(16) __half g_Kh[ROWS_TOTAL * DM];
__device__ __align__(16) __half g_Vf[ROWS_TOTAL * DM];
__device__ __align__(16) __half g_xf[ROWS_TOTAL * DM];
__device__ __align__(16) __half g_AOf[ROWS_TOTAL * DM];
__device__ __align__(16) __half g_QEf[ROWS_TOTAL * NH * MB];
__device__ __align__(16) __half g_KEf[ROWS_TOTAL * NH * MB];
__device__ __align__(16) __half g_Wqf[DM * DM];
__device__ __align__(16) __half g_Wkf[DM * DM];
__device__ __align__(16) __half g_Wvf[DM * DM];
__device__ __align__(16) __half g_Wof[DM * DM];

// ---------------------------------------------------------------------------
// Helpers
// ---------------------------------------------------------------------------
static __device__ __forceinline__ uint32_t smem_u32(const void* p) {
    return (uint32_t)__cvta_generic_to_shared(p);
}

static __device__ __forceinline__ uint32_t pack2h(float a, float b) {
    __half2 t = __floats2half2_rn(a, b);
    return *(uint32_t*)&t;
}

static __device__ __forceinline__ uint32_t h2exp2u(uint32_t x) {
    uint32_t r;
    asm volatile("ex2.approx.f16x2 %0, %1;" : "=r"(r) : "r"(x));
    return r;
}

static __device__ __forceinline__ void ldmx4(uint32_t& r0, uint32_t& r1,
                                             uint32_t& r2, uint32_t& r3,
                                             uint32_t addr) {
    asm volatile("ldmatrix.sync.aligned.m8n8.x4.shared.b16 {%0,%1,%2,%3}, [%4];"
                 : "=r"(r0), "=r"(r1), "=r"(r2), "=r"(r3) : "r"(addr));
}

static __device__ __forceinline__ void ldmx4t(uint32_t& r0, uint32_t& r1,
                                              uint32_t& r2, uint32_t& r3,
                                              uint32_t addr) {
    asm volatile("ldmatrix.sync.aligned.m8n8.x4.trans.shared.b16 {%0,%1,%2,%3}, [%4];"
                 : "=r"(r0), "=r"(r1), "=r"(r2), "=r"(r3) : "r"(addr));
}

static __device__ __forceinline__ void ldmx2t(uint32_t& r0, uint32_t& r1,
                                              uint32_t addr) {
    asm volatile("ldmatrix.sync.aligned.m8n8.x2.trans.shared.b16 {%0,%1}, [%2];"
                 : "=r"(r0), "=r"(r1) : "r"(addr));
}

static __device__ __forceinline__ void mma16816h(float* d, const uint32_t* a,
                                                 const uint32_t* b) {
    asm volatile(
        "mma.sync.aligned.m16n8k16.row.col.f32.f16.f16.f32 "
        "{%0,%1,%2,%3}, {%4,%5,%6,%7}, {%8,%9}, {%0,%1,%2,%3};"
        : "+f"(d[0]), "+f"(d[1]), "+f"(d[2]), "+f"(d[3])
        : "r"(a[0]), "r"(a[1]), "r"(a[2]), "r"(a[3]), "r"(b[0]), "r"(b[1]));
}

static __device__ __forceinline__ void cp16(uint32_t dst, const void* src) {
    asm volatile("cp.async.cg.shared.global [%0], [%1], 16;" :: "r"(dst), "l"(src));
}
static __device__ __forceinline__ void cp_commit() {
    asm volatile("cp.async.commit_group;");
}
template<int N> static __device__ __forceinline__ void cp_wait() {
    asm volatile("cp.async.wait_group %0;" :: "n"(N));
}

// ---------------------------------------------------------------------------
// Fused fp32 -> fp16 conversion: 4 weight matrices + x in ONE launch.
// Flat block index: [0, 4096) -> weights (1024 blocks each), rest -> x.
// ---------------------------------------------------------------------------
#define W_N4 (DM * DM / 4)               // 262144 -> 1024 blocks each
#define X_N4 (ROWS_TOTAL * DM / 4)       // 2097152 -> 8192 blocks
#define CONV_BLOCKS (4 * 1024 + 8192)    // 12288

__global__ __launch_bounds__(256) void conv_all(
    const float* __restrict__ x,
    const float* __restrict__ w0, const float* __restrict__ w1,
    const float* __restrict__ w2, const float* __restrict__ w3,
    __half* __restrict__ xf,
    __half* __restrict__ d0, __half* __restrict__ d1,
    __half* __restrict__ d2, __half* __restrict__ d3)
{
    int blk = blockIdx.x;
    const float* s; __half* d; int i;
    if (blk < 4096) {
        int w = blk >> 10;
        s = (w == 0) ? w0 : (w == 1) ? w1 : (w == 2) ? w2 : w3;
        d = (w == 0) ? d0 : (w == 1) ? d1 : (w == 2) ? d2 : d3;
        i = (blk & 1023) * 256 + threadIdx.x;
    } else {
        s = x; d = xf;
        i = (blk - 4096) * 256 + threadIdx.x;
    }
    float4 v = ((const float4*)s)[i];
    uint2 o;
    o.x = pack2h(v.x, v.y);
    o.y = pack2h(v.z, v.w);
    ((uint2*)d)[i] = o;
}

// ---------------------------------------------------------------------------
// Fused QKV GEMM, 1-term fp16, fp16 outputs. BK=64, 2-stage cp.async ring,
// one barrier per K-iter (16 iters).
// grid (24, 64): blockIdx.x>>3 selects {Wq->Q, Wk->K, Wv->V}.
// ---------------------------------------------------------------------------
#define GKP 72
#define GEMM_SMEM (2 * 2 * 128 * GKP * 2)   // 73728 bytes

__global__ __launch_bounds__(256, 2) void gemm_qkv(
    const __half* __restrict__ Ax,
    const __half* __restrict__ Bq, const __half* __restrict__ Bk,
    const __half* __restrict__ Bv,
    __half* __restrict__ Cq, __half* __restrict__ Ck, __half* __restrict__ Cv)
{
    extern __shared__ __align__(16) char smem[];
    const int tid  = threadIdx.x;
    const int wid  = tid >> 5;
    const int lane = tid & 31;
    const int which = blockIdx.x >> 3;
    const int bcol  = (blockIdx.x & 7) * 128;
    const int brow  = blockIdx.y * 128;
    const int wm   = (wid & 3) * 32;
    const int wn   = (wid >> 2) * 64;

    const __half* B = (which == 0) ? Bq : ((which == 1) ? Bk : Bv);
    __half* Co = (which == 0) ? Cq : ((which == 1) ? Ck : Cv);

    auto buf = [&](int s, int a) -> __half* {
        return (__half*)smem + (size_t)(s * 2 + a) * 128 * GKP;
    };
    auto stage = [&](int s, int kt) {
#pragma unroll
        for (int i = 0; i < 8; i++) {
            int c = tid + i * 256;          // 0..2047
            int a = c >> 10;                // 0..1
            int cc = c & 1023;
            int row = cc >> 3;
            int part = (cc & 7) << 3;
            const __half* g = (a == 0)
                ? Ax + (size_t)(brow + row) * DM + kt * 64 + part
                : B  + (size_t)(bcol + row) * DM + kt * 64 + part;
            cp16(smem_u32(buf(s, a) + row * GKP + part), g);
        }
    };

    float acc[2][8][4];
#pragma unroll
    for (int mi = 0; mi < 2; mi++)
#pragma unroll
        for (int ni = 0; ni < 8; ni++)
#pragma unroll
            for (int j = 0; j < 4; j++) acc[mi][ni][j] = 0.f;

    const int fr = lane & 15;
    const int fc = (lane >> 4) << 3;

    stage(0, 0); cp_commit();

    for (int kt = 0; kt < 16; kt++) {
        cp_wait<0>();
        __syncthreads();
        if (kt < 15) { stage((kt + 1) & 1, kt + 1); cp_commit(); }

        const int cur = kt & 1;
        const __half* pA = buf(cur, 0);
        const __half* pB = buf(cur, 1);

#pragma unroll
        for (int ks = 0; ks < 4; ks++) {
            const int kof = ks * 16 + fc;
            uint32_t a[2][4];
#pragma unroll
            for (int mi = 0; mi < 2; mi++)
                ldmx4(a[mi][0], a[mi][1], a[mi][2], a[mi][3],
                      smem_u32(pA + (wm + mi * 16 + fr) * GKP + kof));
            uint32_t b[8][2];
#pragma unroll
            for (int nq = 0; nq < 4; nq++) {
                uint32_t r0, r1, r2, r3;
                ldmx4(r0, r1, r2, r3, smem_u32(pB + (wn + nq * 16 + fr) * GKP + kof));
                b[nq * 2 + 0][0] = r0; b[nq * 2 + 0][1] = r2;
                b[nq * 2 + 1][0] = r1; b[nq * 2 + 1][1] = r3;
            }
#pragma unroll
            for (int mi = 0; mi < 2; mi++)
#pragma unroll
                for (int ni = 0; ni < 8; ni++)
                    mma16816h(acc[mi][ni], a[mi], b[ni]);
        }
    }

    const int er = lane >> 2;
    const int ec = (lane & 3) * 2;
#pragma unroll
    for (int mi = 0; mi < 2; mi++) {
#pragma unroll
        for (int ni = 0; ni < 8; ni++) {
            __half* cp0 = Co + (size_t)(brow + wm + mi * 16 + er) * DM + bcol + wn + ni * 8 + ec;
            *(uint32_t*)cp0 = pack2h(acc[mi][ni][0], acc[mi][ni][1]);
            __half* cp1 = cp0 + 8 * DM;
            *(uint32_t*)cp1 = pack2h(acc[mi][ni][2], acc[mi][ni][3]);
        }
    }
}

// ---------------------------------------------------------------------------
// AO @ Wo^T GEMM, 1-term fp16, fp32 out. BK=64, 2-stage ring.
// ---------------------------------------------------------------------------
__global__ __launch_bounds__(256, 2) void gemm_ao(
    const __half* __restrict__ Aa, const __half* __restrict__ B,
    float* __restrict__ Cf)
{
    extern __shared__ __align__(16) char smem[];
    const int tid  = threadIdx.x;
    const int wid  = tid >> 5;
    const int lane = tid & 31;
    const int brow = blockIdx.y * 128;
    const int bcol = blockIdx.x * 128;
    const int wm   = (wid & 3) * 32;
    const int wn   = (wid >> 2) * 64;

    auto buf = [&](int s, int a) -> __half* {
        return (__half*)smem + (size_t)(s * 2 + a) * 128 * GKP;
    };
    auto stage = [&](int s, int kt) {
#pragma unroll
        for (int i = 0; i < 8; i++) {
            int c = tid + i * 256;
            int a = c >> 10;
            int cc = c & 1023;
            int row = cc >> 3;
            int part = (cc & 7) << 3;
            const __half* g = (a == 0)
                ? Aa + (size_t)(brow + row) * DM + kt * 64 + part
                : B  + (size_t)(bcol + row) * DM + kt * 64 + part;
            cp16(smem_u32(buf(s, a) + row * GKP + part), g);
        }
    };

    float acc[2][8][4];
#pragma unroll
    for (int mi = 0; mi < 2; mi++)
#pragma unroll
        for (int ni = 0; ni < 8; ni++)
#pragma unroll
            for (int j = 0; j < 4; j++) acc[mi][ni][j] = 0.f;

    const int fr = lane & 15;
    const int fc = (lane >> 4) << 3;

    stage(0, 0); cp_commit();

    for (int kt = 0; kt < 16; kt++) {
        cp_wait<0>();
        __syncthreads();
        if (kt < 15) { stage((kt + 1) & 1, kt + 1); cp_commit(); }

        const int cur = kt & 1;
        const __half* pA = buf(cur, 0);
        const __half* pB = buf(cur, 1);

#pragma unroll
        for (int ks = 0; ks < 4; ks++) {
            const int kof = ks * 16 + fc;
            uint32_t a[2][4];
#pragma unroll
            for (int mi = 0; mi < 2; mi++)
                ldmx4(a[mi][0], a[mi][1], a[mi][2], a[mi][3],
                      smem_u32(pA + (wm + mi * 16 + fr) * GKP + kof));
            uint32_t b[8][2];
#pragma unroll
            for (int nq = 0; nq < 4; nq++) {
                uint32_t r0, r1, r2, r3;
                ldmx4(r0, r1, r2, r3, smem_u32(pB + (wn + nq * 16 + fr) * GKP + kof));
                b[nq * 2 + 0][0] = r0; b[nq * 2 + 0][1] = r2;
                b[nq * 2 + 1][0] = r1; b[nq * 2 + 1][1] = r3;
            }
#pragma unroll
            for (int mi = 0; mi < 2; mi++)
#pragma unroll
                for (int ni = 0; ni < 8; ni++)
                    mma16816h(acc[mi][ni], a[mi], b[ni]);
        }
    }

    const int er = lane >> 2;
    const int ec = (lane & 3) * 2;
#pragma unroll
    for (int mi = 0; mi < 2; mi++) {
#pragma unroll
        for (int ni = 0; ni < 8; ni++) {
            float* cp0 = Cf + (size_t)(brow + wm + mi * 16 + er) * DM + bcol + wn + ni * 8 + ec;
            *(float2*)cp0 = make_float2(acc[mi][ni][0], acc[mi][ni][1]);
            float* cp1 = cp0 + 8 * DM;
            *(float2*)cp1 = make_float2(acc[mi][ni][2], acc[mi][ni][3]);
        }
    }
}

// ---------------------------------------------------------------------------
// Tensor-core witness encoder: E = tanh(X_head @ Wenc_head) * scale.
// grid (ROWS/128, NH, 2): z=0 -> Q path (SCALE*LOG2E folded), z=1 -> K path.
// ---------------------------------------------------------------------------
__global__ __launch_bounds__(256) void enc3_kernel(
    const __half* __restrict__ Qh, const __half* __restrict__ Kh,
    const float* __restrict__ Wenc,
    __half* __restrict__ QE, __half* __restrict__ KE)
{
    __shared__ __align__(16) __half sX[128 * 72];   // 18 KB
    __shared__ __align__(16) __half sW[64 * 40];    // 5 KB

    const int tid  = threadIdx.x;
    const int wid  = tid >> 5;
    const int lane = tid & 31;
    const int h    = blockIdx.y;
    const int row0 = blockIdx.x * 128;
    const int z    = blockIdx.z;

    const __half* X = z ? Kh : Qh;
    __half* E = z ? KE : QE;
    const float scale = z ? 1.0f : (SCALE * LOG2E);

#pragma unroll
    for (int i = 0; i < 4; i++) {
        int idx = tid + i * 256;
        int r = idx >> 3;
        int c = (idx & 7) << 3;
        *(uint4*)&sX[r * 72 + c] =
            *(const uint4*)&X[(size_t)(row0 + r) * DM + h * HD + c];
    }
#pragma unroll
    for (int i = 0; i < 4; i++) {
        int idx = tid + i * 256;
        int d = idx >> 4;
        int m = (idx & 15) * 2;
        float2 w = *(const float2*)&Wenc[(size_t)h * HD * MB + d * MB + m];
        *(uint32_t*)&sW[d * 40 + m] = pack2h(w.x, w.y);
    }
    __syncthreads();

    const int wm = wid * 16;
    const int fr = lane & 15;
    const int fc = (lane >> 4) << 3;

    float acc[4][4];
#pragma unroll
    for (int nt = 0; nt < 4; nt++)
#pragma unroll
        for (int j = 0; j < 4; j++) acc[nt][j] = 0.f;

#pragma unroll
    for (int kc = 0; kc < 4; kc++) {
        uint32_t a[4];
        ldmx4(a[0], a[1], a[2], a[3],
              smem_u32(&sX[(wm + fr) * 72 + kc * 16 + fc]));
#pragma unroll
        for (int nb = 0; nb < 2; nb++) {
            uint32_t r0, r1, r2, r3;
            uint32_t b0[2], b1[2];
            ldmx4t(r0, r1, r2, r3,
                   smem_u32(&sW[(kc * 16 + fr) * 40 + nb * 16 + fc]));
            b0[0] = r0; b0[1] = r1; b1[0] = r2; b1[1] = r3;
            mma16816h(acc[nb * 2 + 0], a, b0);
            mma16816h(acc[nb * 2 + 1], a, b1);
        }
    }

    const int er = lane >> 2;
    const int ec = (lane & 3) * 2;
    const size_t r0g = (size_t)(row0 + wm + er);
#pragma unroll
    for (int nt = 0; nt < 4; nt++) {
        int m = nt * 8 + ec;
        *(uint32_t*)&E[(r0g * NH + h) * MB + m] =
            pack2h(tanhf(acc[nt][0]) * scale, tanhf(acc[nt][1]) * scale);
        *(uint32_t*)&E[((r0g + 8) * NH + h) * MB + m] =
            pack2h(tanhf(acc[nt][2]) * scale, tanhf(acc[nt][3]) * scale);
    }
}

// ---------------------------------------------------------------------------
// Tensor-core flash attention.
// scores arrive as s*log2e (folded into Q enc); p = ex2.approx.f16x2.
// Row-sum (softmax denominator) computed BY THE TENSOR CORE via a ones
// column planted at V smem col 64 (padding region untouched by cp.async).
// 3-stage cp.async ring, one barrier per 128-key tile.
// ---------------------------------------------------------------------------
#define AK 40
#define AV 72
#define ATTN_STAGE ((128 * AK + 128 * AV) * 2)    // 28672 bytes
#define ATTN_SMEM (3 * ATTN_STAGE)                // 86016 bytes

__global__ __launch_bounds__(256, 2) void attn_tc(
    const __half* __restrict__ QEf, const __half* __restrict__ KEf,
    const __half* __restrict__ Vf, __half* __restrict__ AOf)
{
    extern __shared__ __align__(16) char smem[];

    const int tid  = threadIdx.x;
    const int wid  = tid >> 5;
    const int lane = tid & 31;
    const int h = blockIdx.y;
    const int b = blockIdx.z;
    const size_t base = (size_t)b * SEQ;
    const int q0 = blockIdx.x * 128;
    const int wm = wid * 16;
    const int fr = lane & 15;
    const int fc = (lane >> 4) << 3;
    const int gid = lane >> 2;
    const int tig = lane & 3;

    auto bufK = [&](int s) -> __half* {
        return (__half*)(smem + (size_t)s * ATTN_STAGE);
    };
    auto bufV = [&](int s) -> __half* {
        return (__half*)(smem + (size_t)s * ATTN_STAGE) + 128 * AK;
    };
    auto stage = [&](int s, int kt) {
        const int k0 = kt * 128;
        __half* sK = bufK(s);
        __half* sV = bufV(s);
#pragma unroll
        for (int i = 0; i < 2; i++) {
            int c = tid + i * 256;
            int row = c >> 2;
            int part = (c & 3) << 3;
            cp16(smem_u32(sK + row * AK + part),
                 KEf + (base + k0 + row) * (NH * MB) + h * MB + part);
        }
#pragma unroll
        for (int i = 0; i < 4; i++) {
            int c = tid + i * 256;
            int row = c >> 3;
            int part = (c & 7) << 3;
            cp16(smem_u32(sV + row * AV + part),
                 Vf + (base + k0 + row) * DM + h * HD + part);
        }
    };

    // ---- stage Q into buffer 0's K region; plant ones column in all V bufs ----
    {
        __half* sQ = bufK(0);
#pragma unroll
        for (int i = 0; i < 2; i++) {
            int c = tid + i * 256;
            int row = c >> 2;
            int part = (c & 3) << 3;
            size_t g = (base + q0 + row) * (NH * MB) + h * MB + part;
            *(uint4*)&sQ[row * AK + part] = *(const uint4*)&QEf[g];
        }
        // ones at col 64, zeros at 65..71 — cp.async never writes cols >= 64
        uint4 ones = make_uint4(0x00003C00u, 0u, 0u, 0u);
#pragma unroll
        for (int i = 0; i < 2; i++) {
            int c = tid + i * 256;          // 0..383 used
            if (c < 3 * 128) {
                int s = c >> 7;
                int row = c & 127;
                *(uint4*)&bufV(s)[row * AV + 64] = ones;
            }
        }
    }
    __syncthreads();
    uint32_t qh[2][4];
    {
        __half* sQ = bufK(0);
#pragma unroll
        for (int kc = 0; kc < 2; kc++)
            ldmx4(qh[kc][0], qh[kc][1], qh[kc][2], qh[kc][3],
                  smem_u32(&sQ[(wm + fr) * AK + kc * 16 + fc]));
    }
    __syncthreads();

    float oacc[8][4];
#pragma unroll
    for (int nt = 0; nt < 8; nt++)
#pragma unroll
        for (int j = 0; j < 4; j++) oacc[nt][j] = 0.f;
    float lacc[4] = {0.f, 0.f, 0.f, 0.f};   // ones-column accumulator (lr)

    stage(0, 0); cp_commit();
    stage(1, 1); cp_commit();

    for (int kt = 0; kt < 16; kt++) {
        if (kt < 15) cp_wait<1>(); else cp_wait<0>();
        __syncthreads();
        if (kt < 14) { stage((kt + 2) % 3, kt + 2); cp_commit(); }

        const int cur = kt % 3;
        __half* sK = bufK(cur);
        __half* sV = bufV(cur);

#pragma unroll
        for (int g8 = 0; g8 < 8; g8++) {
            float sa0[4] = {0.f, 0.f, 0.f, 0.f};
            float sa1[4] = {0.f, 0.f, 0.f, 0.f};
#pragma unroll
            for (int kc = 0; kc < 2; kc++) {
                uint32_t r0, r1, r2, r3;
                uint32_t b0[2], b1[2];
                ldmx4(r0, r1, r2, r3,
                      smem_u32(&sK[(g8 * 16 + fr) * AK + kc * 16 + fc]));
                b0[0] = r0; b0[1] = r2; b1[0] = r1; b1[1] = r3;
                mma16816h(sa0, qh[kc], b0);
                mma16816h(sa1, qh[kc], b1);
            }
            // ---- p = 2^(s*log2e) in fp16x2, already packed for MMA ----
            uint32_t ph[4];
            ph[0] = h2exp2u(pack2h(sa0[0], sa0[1]));
            ph[1] = h2exp2u(pack2h(sa0[2], sa0[3]));
            ph[2] = h2exp2u(pack2h(sa1[0], sa1[1]));
            ph[3] = h2exp2u(pack2h(sa1[2], sa1[3]));
            // ---- P x V ----
#pragma unroll
            for (int nb = 0; nb < 4; nb++) {
                uint32_t r0, r1, r2, r3;
                uint32_t v0[2], v1[2];
                ldmx4t(r0, r1, r2, r3,
                       smem_u32(&sV[(g8 * 16 + fr) * AV + nb * 16 + fc]));
                v0[0] = r0; v0[1] = r1; v1[0] = r2; v1[1] = r3;
                mma16816h(oacc[nb * 2 + 0], ph, v0);
                mma16816h(oacc[nb * 2 + 1], ph, v1);
            }
            // ---- P x ones column -> row sums (exact fp32 accumulate) ----
            {
                uint32_t r0, r1;
                uint32_t bo[2];
                ldmx2t(r0, r1, smem_u32(&sV[(g8 * 16 + fr) * AV + 64]));
                bo[0] = r0; bo[1] = r1;
                mma16816h(lacc, ph, bo);
            }
        }
    }

    // lr lives in tig==0 lanes (col 64); broadcast within each 4-lane group
    const float lr  = __shfl_sync(0xffffffffu, lacc[0], gid * 4);
    const float lr8 = __shfl_sync(0xffffffffu, lacc[2], gid * 4);
    const float inv  = 1.f / lr;
    const float inv8 = 1.f / lr8;

    const size_t row0 = base + q0 + wm + gid;
#pragma unroll
    for (int nt = 0; nt < 8; nt++) {
        int col = h * HD + nt * 8 + tig * 2;
        *(uint32_t*)&AOf[row0 * DM + col] =
            pack2h(oacc[nt][0] * inv, oacc[nt][1] * inv);
        *(uint32_t*)&AOf[(row0 + 8) * DM + col] =
            pack2h(oacc[nt][2] * inv8, oacc[nt][3] * inv8);
    }
}

// ---------------------------------------------------------------------------
// Launch
// ---------------------------------------------------------------------------
extern "C" void kernel_launch(void* const* d_in, const int* in_sizes, int n_in,
                              void* d_out, int out_size)
{
    const float* x    = (const float*)d_in[0];
    const float* Wq   = (const float*)d_in[1];
    const float* Wk   = (const float*)d_in[2];
    const float* Wv   = (const float*)d_in[3];
    const float* Wenc = (const float*)d_in[4];
    const float* Wo   = (const float*)d_in[5];
    float* out = (float*)d_out;

    __half *Qh, *Kh, *Vf, *xf, *AOf, *QEf, *KEf;
    __half *Wqf, *Wkf, *Wvf, *Wof;
    cudaGetSymbolAddress((void**)&Qh,  g_Qh);
    cudaGetSymbolAddress((void**)&Kh,  g_Kh);
    cudaGetSymbolAddress((void**)&Vf,  g_Vf);
    cudaGetSymbolAddress((void**)&xf,  g_xf);
    cudaGetSymbolAddress((void**)&AOf, g_AOf);
    cudaGetSymbolAddress((void**)&QEf, g_QEf);
    cudaGetSymbolAddress((void**)&KEf, g_KEf);
    cudaGetSymbolAddress((void**)&Wqf, g_Wqf);
    cudaGetSymbolAddress((void**)&Wkf, g_Wkf);
    cudaGetSymbolAddress((void**)&Wvf, g_Wvf);
    cudaGetSymbolAddress((void**)&Wof, g_Wof);

    static bool init = false;
    if (!init) {
        cudaFuncSetAttribute(gemm_qkv, cudaFuncAttributeMaxDynamicSharedMemorySize,
                             GEMM_SMEM);
        cudaFuncSetAttribute(gemm_ao, cudaFuncAttributeMaxDynamicSharedMemorySize,
                             GEMM_SMEM);
        cudaFuncSetAttribute(attn_tc, cudaFuncAttributeMaxDynamicSharedMemorySize,
                             ATTN_SMEM);
        init = true;
    }

    conv_all<<<CONV_BLOCKS, 256>>>(x, Wq, Wk, Wv, Wo,
                                   xf, Wqf, Wkf, Wvf, Wof);

    dim3 gQKV(3 * DM / 128, ROWS_TOTAL / 128);   // (24, 64)
    gemm_qkv<<<gQKV, 256, GEMM_SMEM>>>(xf, Wqf, Wkf, Wvf, Qh, Kh, Vf);

    dim3 gEnc(ROWS_TOTAL / 128, NH, 2);          // (64, 16, 2)
    enc3_kernel<<<gEnc, 256>>>(Qh, Kh, Wenc, QEf, KEf);

    dim3 gAttn(SEQ / 128, NH, BSZ);              // (16, 16, 4)
    attn_tc<<<gAttn, 256, ATTN_SMEM>>>(QEf, KEf, Vf, AOf);

    dim3 gWo(DM / 128, ROWS_TOTAL / 128);        // (8, 64)
    gemm_ao<<<gWo, 256, GEMM_SMEM>>>(AOf, Wof, out);
}

// round 13
// speedup vs baseline: 10.5527x; 1.0249x over previous
#include <cuda_runtime.h>
#include <cuda_bf16.h>
#include <cuda_fp16.h>
#include <math.h>
#include <stdint.h>

// Problem constants
#define BSZ 4
#define SEQ 2048
#define DM 1024
#define NH 16
#define HD 64
#define MB 32
#define ROWS_TOTAL (BSZ * SEQ)          // 8192
#define SCALE 0.17677669529663687f      // 1/sqrt(32)
#define LOG2E 1.4426950408889634f

// ---------------------------------------------------------------------------
// Scratch (no allocations allowed -> __device__ globals)
// ---------------------------------------------------------------------------
__device__ __align__(16) __half g_Qh[ROWS_TOTAL * DM];
__device__ __align__(16) __half g_Kh[ROWS_TOTAL * DM];
__device__ __align__(16) __half g_Vf[ROWS_TOTAL * DM];
__device__ __align__(16) __half g_xf[ROWS_TOTAL * DM];
__device__ __align__(16) __half g_AOf[ROWS_TOTAL * DM];
__device__ __align__(16) __half g_QEf[ROWS_TOTAL * NH * MB];
__device__ __align__(16) __half g_KEf[ROWS_TOTAL * NH * MB];
__device__ __align__(16) __half g_Wqf[DM * DM];
__device__ __align__(16) __half g_Wkf[DM * DM];
__device__ __align__(16) __half g_Wvf[DM * DM];
__device__ __align__(16) __half g_Wof[DM * DM];

// ---------------------------------------------------------------------------
// Helpers
// ---------------------------------------------------------------------------
static __device__ __forceinline__ uint32_t smem_u32(const void* p) {
    return (uint32_t)__cvta_generic_to_shared(p);
}

static __device__ __forceinline__ uint32_t pack2h(float a, float b) {
    __half2 t = __floats2half2_rn(a, b);
    return *(uint32_t*)&t;
}

static __device__ __forceinline__ uint32_t h2exp2u(uint32_t x) {
    uint32_t r;
    asm volatile("ex2.approx.f16x2 %0, %1;" : "=r"(r) : "r"(x));
    return r;
}

static __device__ __forceinline__ void ldmx4(uint32_t& r0, uint32_t& r1,
                                             uint32_t& r2, uint32_t& r3,
                                             uint32_t addr) {
    asm volatile("ldmatrix.sync.aligned.m8n8.x4.shared.b16 {%0,%1,%2,%3}, [%4];"
                 : "=r"(r0), "=r"(r1), "=r"(r2), "=r"(r3) : "r"(addr));
}

static __device__ __forceinline__ void ldmx4t(uint32_t& r0, uint32_t& r1,
                                              uint32_t& r2, uint32_t& r3,
                                              uint32_t addr) {
    asm volatile("ldmatrix.sync.aligned.m8n8.x4.trans.shared.b16 {%0,%1,%2,%3}, [%4];"
                 : "=r"(r0), "=r"(r1), "=r"(r2), "=r"(r3) : "r"(addr));
}

static __device__ __forceinline__ void ldmx2t(uint32_t& r0, uint32_t& r1,
                                              uint32_t addr) {
    asm volatile("ldmatrix.sync.aligned.m8n8.x2.trans.shared.b16 {%0,%1}, [%2];"
                 : "=r"(r0), "=r"(r1) : "r"(addr));
}

static __device__ __forceinline__ void mma16816h(float* d, const uint32_t* a,
                                                 const uint32_t* b) {
    asm volatile(
        "mma.sync.aligned.m16n8k16.row.col.f32.f16.f16.f32 "
        "{%0,%1,%2,%3}, {%4,%5,%6,%7}, {%8,%9}, {%0,%1,%2,%3};"
        : "+f"(d[0]), "+f"(d[1]), "+f"(d[2]), "+f"(d[3])
        : "r"(a[0]), "r"(a[1]), "r"(a[2]), "r"(a[3]), "r"(b[0]), "r"(b[1]));
}

static __device__ __forceinline__ void cp16(uint32_t dst, const void* src) {
    asm volatile("cp.async.cg.shared.global [%0], [%1], 16;" :: "r"(dst), "l"(src));
}
static __device__ __forceinline__ void cp_commit() {
    asm volatile("cp.async.commit_group;");
}
template<int N> static __device__ __forceinline__ void cp_wait() {
    asm volatile("cp.async.wait_group %0;" :: "n"(N));
}

// ---------------------------------------------------------------------------
// Fused fp32 -> fp16 conversion: 4 weight matrices + x in ONE launch.
// ---------------------------------------------------------------------------
#define CONV_BLOCKS (4 * 1024 + 8192)    // 12288

__global__ __launch_bounds__(256) void conv_all(
    const float* __restrict__ x,
    const float* __restrict__ w0, const float* __restrict__ w1,
    const float* __restrict__ w2, const float* __restrict__ w3,
    __half* __restrict__ xf,
    __half* __restrict__ d0, __half* __restrict__ d1,
    __half* __restrict__ d2, __half* __restrict__ d3)
{
    int blk = blockIdx.x;
    const float* s; __half* d; int i;
    if (blk < 4096) {
        int w = blk >> 10;
        s = (w == 0) ? w0 : (w == 1) ? w1 : (w == 2) ? w2 : w3;
        d = (w == 0) ? d0 : (w == 1) ? d1 : (w == 2) ? d2 : d3;
        i = (blk & 1023) * 256 + threadIdx.x;
    } else {
        s = x; d = xf;
        i = (blk - 4096) * 256 + threadIdx.x;
    }
    float4 v = ((const float4*)s)[i];
    uint2 o;
    o.x = pack2h(v.x, v.y);
    o.y = pack2h(v.z, v.w);
    ((uint2*)d)[i] = o;
}

// ---------------------------------------------------------------------------
// Fused QKV GEMM, 1-term fp16, fp16 outputs. BK=64, 2-stage cp.async ring.
// grid (24, 64): blockIdx.x>>3 selects {Wq->Q, Wk->K, Wv->V}.
// ---------------------------------------------------------------------------
#define GKP 72
#define GEMM_SMEM (2 * 2 * 128 * GKP * 2)   // 73728 bytes

__global__ __launch_bounds__(256, 2) void gemm_qkv(
    const __half* __restrict__ Ax,
    const __half* __restrict__ Bq, const __half* __restrict__ Bk,
    const __half* __restrict__ Bv,
    __half* __restrict__ Cq, __half* __restrict__ Ck, __half* __restrict__ Cv)
{
    extern __shared__ __align__(16) char smem[];
    const int tid  = threadIdx.x;
    const int wid  = tid >> 5;
    const int lane = tid & 31;
    const int which = blockIdx.x >> 3;
    const int bcol  = (blockIdx.x & 7) * 128;
    const int brow  = blockIdx.y * 128;
    const int wm   = (wid & 3) * 32;
    const int wn   = (wid >> 2) * 64;

    const __half* B = (which == 0) ? Bq : ((which == 1) ? Bk : Bv);
    __half* Co = (which == 0) ? Cq : ((which == 1) ? Ck : Cv);

    auto buf = [&](int s, int a) -> __half* {
        return (__half*)smem + (size_t)(s * 2 + a) * 128 * GKP;
    };
    auto stage = [&](int s, int kt) {
#pragma unroll
        for (int i = 0; i < 8; i++) {
            int c = tid + i * 256;
            int a = c >> 10;
            int cc = c & 1023;
            int row = cc >> 3;
            int part = (cc & 7) << 3;
            const __half* g = (a == 0)
                ? Ax + (size_t)(brow + row) * DM + kt * 64 + part
                : B  + (size_t)(bcol + row) * DM + kt * 64 + part;
            cp16(smem_u32(buf(s, a) + row * GKP + part), g);
        }
    };

    float acc[2][8][4];
#pragma unroll
    for (int mi = 0; mi < 2; mi++)
#pragma unroll
        for (int ni = 0; ni < 8; ni++)
#pragma unroll
            for (int j = 0; j < 4; j++) acc[mi][ni][j] = 0.f;

    const int fr = lane & 15;
    const int fc = (lane >> 4) << 3;

    stage(0, 0); cp_commit();

    for (int kt = 0; kt < 16; kt++) {
        cp_wait<0>();
        __syncthreads();
        if (kt < 15) { stage((kt + 1) & 1, kt + 1); cp_commit(); }

        const int cur = kt & 1;
        const __half* pA = buf(cur, 0);
        const __half* pB = buf(cur, 1);

#pragma unroll
        for (int ks = 0; ks < 4; ks++) {
            const int kof = ks * 16 + fc;
            uint32_t a[2][4];
#pragma unroll
            for (int mi = 0; mi < 2; mi++)
                ldmx4(a[mi][0], a[mi][1], a[mi][2], a[mi][3],
                      smem_u32(pA + (wm + mi * 16 + fr) * GKP + kof));
            uint32_t b[8][2];
#pragma unroll
            for (int nq = 0; nq < 4; nq++) {
                uint32_t r0, r1, r2, r3;
                ldmx4(r0, r1, r2, r3, smem_u32(pB + (wn + nq * 16 + fr) * GKP + kof));
                b[nq * 2 + 0][0] = r0; b[nq * 2 + 0][1] = r2;
                b[nq * 2 + 1][0] = r1; b[nq * 2 + 1][1] = r3;
            }
#pragma unroll
            for (int mi = 0; mi < 2; mi++)
#pragma unroll
                for (int ni = 0; ni < 8; ni++)
                    mma16816h(acc[mi][ni], a[mi], b[ni]);
        }
    }

    const int er = lane >> 2;
    const int ec = (lane & 3) * 2;
#pragma unroll
    for (int mi = 0; mi < 2; mi++) {
#pragma unroll
        for (int ni = 0; ni < 8; ni++) {
            __half* cp0 = Co + (size_t)(brow + wm + mi * 16 + er) * DM + bcol + wn + ni * 8 + ec;
            *(uint32_t*)cp0 = pack2h(acc[mi][ni][0], acc[mi][ni][1]);
            __half* cp1 = cp0 + 8 * DM;
            *(uint32_t*)cp1 = pack2h(acc[mi][ni][2], acc[mi][ni][3]);
        }
    }
}

// ---------------------------------------------------------------------------
// AO @ Wo^T GEMM, 1-term fp16, fp32 out. BK=64, 2-stage ring.
// ---------------------------------------------------------------------------
__global__ __launch_bounds__(256, 2) void gemm_ao(
    const __half* __restrict__ Aa, const __half* __restrict__ B,
    float* __restrict__ Cf)
{
    extern __shared__ __align__(16) char smem[];
    const int tid  = threadIdx.x;
    const int wid  = tid >> 5;
    const int lane = tid & 31;
    const int brow = blockIdx.y * 128;
    const int bcol = blockIdx.x * 128;
    const int wm   = (wid & 3) * 32;
    const int wn   = (wid >> 2) * 64;

    auto buf = [&](int s, int a) -> __half* {
        return (__half*)smem + (size_t)(s * 2 + a) * 128 * GKP;
    };
    auto stage = [&](int s, int kt) {
#pragma unroll
        for (int i = 0; i < 8; i++) {
            int c = tid + i * 256;
            int a = c >> 10;
            int cc = c & 1023;
            int row = cc >> 3;
            int part = (cc & 7) << 3;
            const __half* g = (a == 0)
                ? Aa + (size_t)(brow + row) * DM + kt * 64 + part
                : B  + (size_t)(bcol + row) * DM + kt * 64 + part;
            cp16(smem_u32(buf(s, a) + row * GKP + part), g);
        }
    };

    float acc[2][8][4];
#pragma unroll
    for (int mi = 0; mi < 2; mi++)
#pragma unroll
        for (int ni = 0; ni < 8; ni++)
#pragma unroll
            for (int j = 0; j < 4; j++) acc[mi][ni][j] = 0.f;

    const int fr = lane & 15;
    const int fc = (lane >> 4) << 3;

    stage(0, 0); cp_commit();

    for (int kt = 0; kt < 16; kt++) {
        cp_wait<0>();
        __syncthreads();
        if (kt < 15) { stage((kt + 1) & 1, kt + 1); cp_commit(); }

        const int cur = kt & 1;
        const __half* pA = buf(cur, 0);
        const __half* pB = buf(cur, 1);

#pragma unroll
        for (int ks = 0; ks < 4; ks++) {
            const int kof = ks * 16 + fc;
            uint32_t a[2][4];
#pragma unroll
            for (int mi = 0; mi < 2; mi++)
                ldmx4(a[mi][0], a[mi][1], a[mi][2], a[mi][3],
                      smem_u32(pA + (wm + mi * 16 + fr) * GKP + kof));
            uint32_t b[8][2];
#pragma unroll
            for (int nq = 0; nq < 4; nq++) {
                uint32_t r0, r1, r2, r3;
                ldmx4(r0, r1, r2, r3, smem_u32(pB + (wn + nq * 16 + fr) * GKP + kof));
                b[nq * 2 + 0][0] = r0; b[nq * 2 + 0][1] = r2;
                b[nq * 2 + 1][0] = r1; b[nq * 2 + 1][1] = r3;
            }
#pragma unroll
            for (int mi = 0; mi < 2; mi++)
#pragma unroll
                for (int ni = 0; ni < 8; ni++)
                    mma16816h(acc[mi][ni], a[mi], b[ni]);
        }
    }

    const int er = lane >> 2;
    const int ec = (lane & 3) * 2;
#pragma unroll
    for (int mi = 0; mi < 2; mi++) {
#pragma unroll
        for (int ni = 0; ni < 8; ni++) {
            float* cp0 = Cf + (size_t)(brow + wm + mi * 16 + er) * DM + bcol + wn + ni * 8 + ec;
            *(float2*)cp0 = make_float2(acc[mi][ni][0], acc[mi][ni][1]);
            float* cp1 = cp0 + 8 * DM;
            *(float2*)cp1 = make_float2(acc[mi][ni][2], acc[mi][ni][3]);
        }
    }
}

// ---------------------------------------------------------------------------
// Tensor-core witness encoder: E = tanh(X_head @ Wenc_head) * scale.
// grid (ROWS/128, NH, 2): z=0 -> Q path (SCALE*LOG2E folded), z=1 -> K path.
// ---------------------------------------------------------------------------
__global__ __launch_bounds__(256) void enc3_kernel(
    const __half* __restrict__ Qh, const __half* __restrict__ Kh,
    const float* __restrict__ Wenc,
    __half* __restrict__ QE, __half* __restrict__ KE)
{
    __shared__ __align__(16) __half sX[128 * 72];   // 18 KB
    __shared__ __align__(16) __half sW[64 * 40];    // 5 KB

    const int tid  = threadIdx.x;
    const int wid  = tid >> 5;
    const int lane = tid & 31;
    const int h    = blockIdx.y;
    const int row0 = blockIdx.x * 128;
    const int z    = blockIdx.z;

    const __half* X = z ? Kh : Qh;
    __half* E = z ? KE : QE;
    const float scale = z ? 1.0f : (SCALE * LOG2E);

#pragma unroll
    for (int i = 0; i < 4; i++) {
        int idx = tid + i * 256;
        int r = idx >> 3;
        int c = (idx & 7) << 3;
        *(uint4*)&sX[r * 72 + c] =
            *(const uint4*)&X[(size_t)(row0 + r) * DM + h * HD + c];
    }
#pragma unroll
    for (int i = 0; i < 4; i++) {
        int idx = tid + i * 256;
        int d = idx >> 4;
        int m = (idx & 15) * 2;
        float2 w = *(const float2*)&Wenc[(size_t)h * HD * MB + d * MB + m];
        *(uint32_t*)&sW[d * 40 + m] = pack2h(w.x, w.y);
    }
    __syncthreads();

    const int wm = wid * 16;
    const int fr = lane & 15;
    const int fc = (lane >> 4) << 3;

    float acc[4][4];
#pragma unroll
    for (int nt = 0; nt < 4; nt++)
#pragma unroll
        for (int j = 0; j < 4; j++) acc[nt][j] = 0.f;

#pragma unroll
    for (int kc = 0; kc < 4; kc++) {
        uint32_t a[4];
        ldmx4(a[0], a[1], a[2], a[3],
              smem_u32(&sX[(wm + fr) * 72 + kc * 16 + fc]));
#pragma unroll
        for (int nb = 0; nb < 2; nb++) {
            uint32_t r0, r1, r2, r3;
            uint32_t b0[2], b1[2];
            ldmx4t(r0, r1, r2, r3,
                   smem_u32(&sW[(kc * 16 + fr) * 40 + nb * 16 + fc]));
            b0[0] = r0; b0[1] = r1; b1[0] = r2; b1[1] = r3;
            mma16816h(acc[nb * 2 + 0], a, b0);
            mma16816h(acc[nb * 2 + 1], a, b1);
        }
    }

    const int er = lane >> 2;
    const int ec = (lane & 3) * 2;
    const size_t r0g = (size_t)(row0 + wm + er);
#pragma unroll
    for (int nt = 0; nt < 4; nt++) {
        int m = nt * 8 + ec;
        *(uint32_t*)&E[(r0g * NH + h) * MB + m] =
            pack2h(tanhf(acc[nt][0]) * scale, tanhf(acc[nt][1]) * scale);
        *(uint32_t*)&E[((r0g + 8) * NH + h) * MB + m] =
            pack2h(tanhf(acc[nt][2]) * scale, tanhf(acc[nt][3]) * scale);
    }
}

// ---------------------------------------------------------------------------
// Tensor-core flash attention, 128 threads / 4 warps x 32 q-rows each.
// Doubles MMA work per ldmatrix vs 8x16 layout (L1-pipe was the bottleneck).
// scores arrive as s*log2e; p = ex2.approx.f16x2; row-sums via ones column.
// 3-stage cp.async ring, one barrier per 128-key tile. 2 CTAs/SM.
// ---------------------------------------------------------------------------
#define AK 40
#define AV 72
#define ATTN_STAGE ((128 * AK + 128 * AV) * 2)    // 28672 bytes
#define ATTN_SMEM (3 * ATTN_STAGE)                // 86016 bytes

__global__ __launch_bounds__(128, 2) void attn_tc(
    const __half* __restrict__ QEf, const __half* __restrict__ KEf,
    const __half* __restrict__ Vf, __half* __restrict__ AOf)
{
    extern __shared__ __align__(16) char smem[];

    const int tid  = threadIdx.x;
    const int wid  = tid >> 5;
    const int lane = tid & 31;
    const int h = blockIdx.y;
    const int b = blockIdx.z;
    const size_t base = (size_t)b * SEQ;
    const int q0 = blockIdx.x * 128;
    const int wm = wid * 32;                 // 32 q rows per warp
    const int fr = lane & 15;
    const int fc = (lane >> 4) << 3;
    const int gid = lane >> 2;
    const int tig = lane & 3;

    auto bufK = [&](int s) -> __half* {
        return (__half*)(smem + (size_t)s * ATTN_STAGE);
    };
    auto bufV = [&](int s) -> __half* {
        return (__half*)(smem + (size_t)s * ATTN_STAGE) + 128 * AK;
    };
    auto stage = [&](int s, int kt) {
        const int k0 = kt * 128;
        __half* sK = bufK(s);
        __half* sV = bufV(s);
#pragma unroll
        for (int i = 0; i < 4; i++) {
            int c = tid + i * 128;          // 0..511
            int row = c >> 2;
            int part = (c & 3) << 3;
            cp16(smem_u32(sK + row * AK + part),
                 KEf + (base + k0 + row) * (NH * MB) + h * MB + part);
        }
#pragma unroll
        for (int i = 0; i < 8; i++) {
            int c = tid + i * 128;          // 0..1023
            int row = c >> 3;
            int part = (c & 7) << 3;
            cp16(smem_u32(sV + row * AV + part),
                 Vf + (base + k0 + row) * DM + h * HD + part);
        }
    };

    // ---- stage Q into buffer 0's K region; plant ones column in all V bufs ----
    {
        __half* sQ = bufK(0);
#pragma unroll
        for (int i = 0; i < 4; i++) {
            int c = tid + i * 128;
            int row = c >> 2;
            int part = (c & 3) << 3;
            size_t g = (base + q0 + row) * (NH * MB) + h * MB + part;
            *(uint4*)&sQ[row * AK + part] = *(const uint4*)&QEf[g];
        }
        // ones at col 64, zeros at 65..71 — cp.async never writes cols >= 64
        uint4 ones = make_uint4(0x00003C00u, 0u, 0u, 0u);
#pragma unroll
        for (int i = 0; i < 3; i++) {
            int c = tid + i * 128;          // 0..383
            int s = c >> 7;
            int row = c & 127;
            *(uint4*)&bufV(s)[row * AV + 64] = ones;
        }
    }
    __syncthreads();
    uint32_t qh[2][2][4];                    // [mi][kc]
    {
        __half* sQ = bufK(0);
#pragma unroll
        for (int mi = 0; mi < 2; mi++)
#pragma unroll
            for (int kc = 0; kc < 2; kc++)
                ldmx4(qh[mi][kc][0], qh[mi][kc][1], qh[mi][kc][2], qh[mi][kc][3],
                      smem_u32(&sQ[(wm + mi * 16 + fr) * AK + kc * 16 + fc]));
    }
    __syncthreads();

    float oacc[2][8][4];
#pragma unroll
    for (int mi = 0; mi < 2; mi++)
#pragma unroll
        for (int nt = 0; nt < 8; nt++)
#pragma unroll
            for (int j = 0; j < 4; j++) oacc[mi][nt][j] = 0.f;
    float lacc[2][4];
#pragma unroll
    for (int mi = 0; mi < 2; mi++)
#pragma unroll
        for (int j = 0; j < 4; j++) lacc[mi][j] = 0.f;

    stage(0, 0); cp_commit();
    stage(1, 1); cp_commit();

    for (int kt = 0; kt < 16; kt++) {
        if (kt < 15) cp_wait<1>(); else cp_wait<0>();
        __syncthreads();
        if (kt < 14) { stage((kt + 2) % 3, kt + 2); cp_commit(); }

        const int cur = kt % 3;
        __half* sK = bufK(cur);
        __half* sV = bufV(cur);

#pragma unroll
        for (int g8 = 0; g8 < 8; g8++) {
            // ---- scores: 2 m-frags x 2 n-tiles ----
            float sa[2][2][4];
#pragma unroll
            for (int mi = 0; mi < 2; mi++)
#pragma unroll
                for (int nt = 0; nt < 2; nt++)
#pragma unroll
                    for (int j = 0; j < 4; j++) sa[mi][nt][j] = 0.f;
#pragma unroll
            for (int kc = 0; kc < 2; kc++) {
                uint32_t r0, r1, r2, r3;
                uint32_t b0[2], b1[2];
                ldmx4(r0, r1, r2, r3,
                      smem_u32(&sK[(g8 * 16 + fr) * AK + kc * 16 + fc]));
                b0[0] = r0; b0[1] = r2; b1[0] = r1; b1[1] = r3;
#pragma unroll
                for (int mi = 0; mi < 2; mi++) {
                    mma16816h(sa[mi][0], qh[mi][kc], b0);
                    mma16816h(sa[mi][1], qh[mi][kc], b1);
                }
            }
            // ---- p = 2^(s*log2e) in fp16x2 ----
            uint32_t ph[2][4];
#pragma unroll
            for (int mi = 0; mi < 2; mi++) {
                ph[mi][0] = h2exp2u(pack2h(sa[mi][0][0], sa[mi][0][1]));
                ph[mi][1] = h2exp2u(pack2h(sa[mi][0][2], sa[mi][0][3]));
                ph[mi][2] = h2exp2u(pack2h(sa[mi][1][0], sa[mi][1][1]));
                ph[mi][3] = h2exp2u(pack2h(sa[mi][1][2], sa[mi][1][3]));
            }
            // ---- P x V ----
#pragma unroll
            for (int nb = 0; nb < 4; nb++) {
                uint32_t r0, r1, r2, r3;
                uint32_t v0[2], v1[2];
                ldmx4t(r0, r1, r2, r3,
                       smem_u32(&sV[(g8 * 16 + fr) * AV + nb * 16 + fc]));
                v0[0] = r0; v0[1] = r1; v1[0] = r2; v1[1] = r3;
#pragma unroll
                for (int mi = 0; mi < 2; mi++) {
                    mma16816h(oacc[mi][nb * 2 + 0], ph[mi], v0);
                    mma16816h(oacc[mi][nb * 2 + 1], ph[mi], v1);
                }
            }
            // ---- P x ones column -> row sums ----
            {
                uint32_t r0, r1;
                uint32_t bo[2];
                ldmx2t(r0, r1, smem_u32(&sV[(g8 * 16 + fr) * AV + 64]));
                bo[0] = r0; bo[1] = r1;
#pragma unroll
                for (int mi = 0; mi < 2; mi++)
                    mma16816h(lacc[mi], ph[mi], bo);
            }
        }
    }

#pragma unroll
    for (int mi = 0; mi < 2; mi++) {
        const float lr  = __shfl_sync(0xffffffffu, lacc[mi][0], gid * 4);
        const float lr8 = __shfl_sync(0xffffffffu, lacc[mi][2], gid * 4);
        const float inv  = 1.f / lr;
        const float inv8 = 1.f / lr8;
        const size_t row0 = base + q0 + wm + mi * 16 + gid;
#pragma unroll
        for (int nt = 0; nt < 8; nt++) {
            int col = h * HD + nt * 8 + tig * 2;
            *(uint32_t*)&AOf[row0 * DM + col] =
                pack2h(oacc[mi][nt][0] * inv, oacc[mi][nt][1] * inv);
            *(uint32_t*)&AOf[(row0 + 8) * DM + col] =
                pack2h(oacc[mi][nt][2] * inv8, oacc[mi][nt][3] * inv8);
        }
    }
}

// ---------------------------------------------------------------------------
// Launch
// ---------------------------------------------------------------------------
extern "C" void kernel_launch(void* const* d_in, const int* in_sizes, int n_in,
                              void* d_out, int out_size)
{
    const float* x    = (const float*)d_in[0];
    const float* Wq   = (const float*)d_in[1];
    const float* Wk   = (const float*)d_in[2];
    const float* Wv   = (const float*)d_in[3];
    const float* Wenc = (const float*)d_in[4];
    const float* Wo   = (const float*)d_in[5];
    float* out = (float*)d_out;

    __half *Qh, *Kh, *Vf, *xf, *AOf, *QEf, *KEf;
    __half *Wqf, *Wkf, *Wvf, *Wof;
    cudaGetSymbolAddress((void**)&Qh,  g_Qh);
    cudaGetSymbolAddress((void**)&Kh,  g_Kh);
    cudaGetSymbolAddress((void**)&Vf,  g_Vf);
    cudaGetSymbolAddress((void**)&xf,  g_xf);
    cudaGetSymbolAddress((void**)&AOf, g_AOf);
    cudaGetSymbolAddress((void**)&QEf, g_QEf);
    cudaGetSymbolAddress((void**)&KEf, g_KEf);
    cudaGetSymbolAddress((void**)&Wqf, g_Wqf);
    cudaGetSymbolAddress((void**)&Wkf, g_Wkf);
    cudaGetSymbolAddress((void**)&Wvf, g_Wvf);
    cudaGetSymbolAddress((void**)&Wof, g_Wof);

    static bool init = false;
    if (!init) {
        cudaFuncSetAttribute(gemm_qkv, cudaFuncAttributeMaxDynamicSharedMemorySize,
                             GEMM_SMEM);
        cudaFuncSetAttribute(gemm_ao, cudaFuncAttributeMaxDynamicSharedMemorySize,
                             GEMM_SMEM);
        cudaFuncSetAttribute(attn_tc, cudaFuncAttributeMaxDynamicSharedMemorySize,
                             ATTN_SMEM);
        init = true;
    }

    conv_all<<<CONV_BLOCKS, 256>>>(x, Wq, Wk, Wv, Wo,
                                   xf, Wqf, Wkf, Wvf, Wof);

    dim3 gQKV(3 * DM / 128, ROWS_TOTAL / 128);   // (24, 64)
    gemm_qkv<<<gQKV, 256, GEMM_SMEM>>>(xf, Wqf, Wkf, Wvf, Qh, Kh, Vf);

    dim3 gEnc(ROWS_TOTAL / 128, NH, 2);          // (64, 16, 2)
    enc3_kernel<<<gEnc, 256>>>(Qh, Kh, Wenc, QEf, KEf);

    dim3 gAttn(SEQ / 128, NH, BSZ);              // (16, 16, 4)
    attn_tc<<<gAttn, 128, ATTN_SMEM>>>(QEf, KEf, Vf, AOf);

    dim3 gWo(DM / 128, ROWS_TOTAL / 128);        // (8, 64)
    gemm_ao<<<gWo, 256, GEMM_SMEM>>>(AOf, Wof, out);
}

// round 14
// speedup vs baseline: 10.5958x; 1.0041x over previous
#include <cuda_runtime.h>
#include <cuda_bf16.h>
#include <cuda_fp16.h>
#include <math.h>
#include <stdint.h>

// Problem constants
#define BSZ 4
#define SEQ 2048
#define DM 1024
#define NH 16
#define HD 64
#define MB 32
#define ROWS_TOTAL (BSZ * SEQ)          // 8192
#define SCALE 0.17677669529663687f      // 1/sqrt(32)
#define LOG2E 1.4426950408889634f

// ---------------------------------------------------------------------------
// Scratch (no allocations allowed -> __device__ globals)
// ---------------------------------------------------------------------------
__device__ __align__(16) __half g_Qh[ROWS_TOTAL * DM];
__device__ __align__(16) __half g_Kh[ROWS_TOTAL * DM];
__device__ __align__(16) __half g_Vf[ROWS_TOTAL * DM];
__device__ __align__(16) __half g_xf[ROWS_TOTAL * DM];
__device__ __align__(16) __half g_AOf[ROWS_TOTAL * DM];
__device__ __align__(16) __half g_QEf[ROWS_TOTAL * NH * MB];
__device__ __align__(16) __half g_KEf[ROWS_TOTAL * NH * MB];
__device__ __align__(16) __half g_Wqf[DM * DM];
__device__ __align__(16) __half g_Wkf[DM * DM];
__device__ __align__(16) __half g_Wvf[DM * DM];
__device__ __align__(16) __half g_Wof[DM * DM];

// ---------------------------------------------------------------------------
// Helpers
// ---------------------------------------------------------------------------
static __device__ __forceinline__ uint32_t smem_u32(const void* p) {
    return (uint32_t)__cvta_generic_to_shared(p);
}

static __device__ __forceinline__ uint32_t pack2h(float a, float b) {
    __half2 t = __floats2half2_rn(a, b);
    return *(uint32_t*)&t;
}

static __device__ __forceinline__ uint32_t h2exp2u(uint32_t x) {
    uint32_t r;
    asm volatile("ex2.approx.f16x2 %0, %1;" : "=r"(r) : "r"(x));
    return r;
}

static __device__ __forceinline__ void ldmx4(uint32_t& r0, uint32_t& r1,
                                             uint32_t& r2, uint32_t& r3,
                                             uint32_t addr) {
    asm volatile("ldmatrix.sync.aligned.m8n8.x4.shared.b16 {%0,%1,%2,%3}, [%4];"
                 : "=r"(r0), "=r"(r1), "=r"(r2), "=r"(r3) : "r"(addr));
}

static __device__ __forceinline__ void ldmx4t(uint32_t& r0, uint32_t& r1,
                                              uint32_t& r2, uint32_t& r3,
                                              uint32_t addr) {
    asm volatile("ldmatrix.sync.aligned.m8n8.x4.trans.shared.b16 {%0,%1,%2,%3}, [%4];"
                 : "=r"(r0), "=r"(r1), "=r"(r2), "=r"(r3) : "r"(addr));
}

static __device__ __forceinline__ void ldmx2t(uint32_t& r0, uint32_t& r1,
                                              uint32_t addr) {
    asm volatile("ldmatrix.sync.aligned.m8n8.x2.trans.shared.b16 {%0,%1}, [%2];"
                 : "=r"(r0), "=r"(r1) : "r"(addr));
}

static __device__ __forceinline__ void mma16816h(float* d, const uint32_t* a,
                                                 const uint32_t* b) {
    asm volatile(
        "mma.sync.aligned.m16n8k16.row.col.f32.f16.f16.f32 "
        "{%0,%1,%2,%3}, {%4,%5,%6,%7}, {%8,%9}, {%0,%1,%2,%3};"
        : "+f"(d[0]), "+f"(d[1]), "+f"(d[2]), "+f"(d[3])
        : "r"(a[0]), "r"(a[1]), "r"(a[2]), "r"(a[3]), "r"(b[0]), "r"(b[1]));
}

static __device__ __forceinline__ void cp16(uint32_t dst, const void* src) {
    asm volatile("cp.async.cg.shared.global [%0], [%1], 16;" :: "r"(dst), "l"(src));
}
static __device__ __forceinline__ void cp_commit() {
    asm volatile("cp.async.commit_group;");
}
template<int N> static __device__ __forceinline__ void cp_wait() {
    asm volatile("cp.async.wait_group %0;" :: "n"(N));
}

// ---------------------------------------------------------------------------
// Fused fp32 -> fp16 conversion: 4 weight matrices + x in ONE launch.
// ---------------------------------------------------------------------------
#define CONV_BLOCKS (4 * 1024 + 8192)    // 12288

__global__ __launch_bounds__(256) void conv_all(
    const float* __restrict__ x,
    const float* __restrict__ w0, const float* __restrict__ w1,
    const float* __restrict__ w2, const float* __restrict__ w3,
    __half* __restrict__ xf,
    __half* __restrict__ d0, __half* __restrict__ d1,
    __half* __restrict__ d2, __half* __restrict__ d3)
{
    int blk = blockIdx.x;
    const float* s; __half* d; int i;
    if (blk < 4096) {
        int w = blk >> 10;
        s = (w == 0) ? w0 : (w == 1) ? w1 : (w == 2) ? w2 : w3;
        d = (w == 0) ? d0 : (w == 1) ? d1 : (w == 2) ? d2 : d3;
        i = (blk & 1023) * 256 + threadIdx.x;
    } else {
        s = x; d = xf;
        i = (blk - 4096) * 256 + threadIdx.x;
    }
    float4 v = ((const float4*)s)[i];
    uint2 o;
    o.x = pack2h(v.x, v.y);
    o.y = pack2h(v.z, v.w);
    ((uint2*)d)[i] = o;
}

// ---------------------------------------------------------------------------
// GEMM core: 128 threads / 4 warps, warp tile 32x128, CTA tile 128x128,
// BK=64, 2-stage cp.async ring, one barrier per K-iter.
// C[m,n] = sum_k A[m,k]*B[n,k]; fp16 in; out fp16 (Ch) or fp32 (Cf).
// ---------------------------------------------------------------------------
#define GKP 72
#define GEMM_SMEM (2 * 2 * 128 * GKP * 2)   // 73728 bytes

template <typename OutT>
static __device__ __forceinline__ void gemm_core(
    const __half* __restrict__ A, const __half* __restrict__ B,
    OutT* __restrict__ C, int brow, int bcol, char* smem)
{
    const int tid  = threadIdx.x;
    const int wid  = tid >> 5;
    const int lane = tid & 31;
    const int wm   = wid * 32;

    auto buf = [&](int s, int a) -> __half* {
        return (__half*)smem + (size_t)(s * 2 + a) * 128 * GKP;
    };
    auto stage = [&](int s, int kt) {
#pragma unroll
        for (int i = 0; i < 16; i++) {
            int c = tid + i * 128;          // 0..2047
            int a = c >> 10;                // 0..1
            int cc = c & 1023;
            int row = cc >> 3;
            int part = (cc & 7) << 3;
            const __half* g = (a == 0)
                ? A + (size_t)(brow + row) * DM + kt * 64 + part
                : B + (size_t)(bcol + row) * DM + kt * 64 + part;
            cp16(smem_u32(buf(s, a) + row * GKP + part), g);
        }
    };

    float acc[2][16][4];
#pragma unroll
    for (int mi = 0; mi < 2; mi++)
#pragma unroll
        for (int ni = 0; ni < 16; ni++)
#pragma unroll
            for (int j = 0; j < 4; j++) acc[mi][ni][j] = 0.f;

    const int fr = lane & 15;
    const int fc = (lane >> 4) << 3;

    stage(0, 0); cp_commit();

    for (int kt = 0; kt < 16; kt++) {
        cp_wait<0>();
        __syncthreads();
        if (kt < 15) { stage((kt + 1) & 1, kt + 1); cp_commit(); }

        const int cur = kt & 1;
        const __half* pA = buf(cur, 0);
        const __half* pB = buf(cur, 1);

#pragma unroll
        for (int ks = 0; ks < 4; ks++) {
            const int kof = ks * 16 + fc;
            uint32_t a[2][4];
#pragma unroll
            for (int mi = 0; mi < 2; mi++)
                ldmx4(a[mi][0], a[mi][1], a[mi][2], a[mi][3],
                      smem_u32(pA + (wm + mi * 16 + fr) * GKP + kof));
            uint32_t b[16][2];
#pragma unroll
            for (int nq = 0; nq < 8; nq++) {
                uint32_t r0, r1, r2, r3;
                ldmx4(r0, r1, r2, r3, smem_u32(pB + (nq * 16 + fr) * GKP + kof));
                b[nq * 2 + 0][0] = r0; b[nq * 2 + 0][1] = r2;
                b[nq * 2 + 1][0] = r1; b[nq * 2 + 1][1] = r3;
            }
#pragma unroll
            for (int mi = 0; mi < 2; mi++)
#pragma unroll
                for (int ni = 0; ni < 16; ni++)
                    mma16816h(acc[mi][ni], a[mi], b[ni]);
        }
    }

    const int er = lane >> 2;
    const int ec = (lane & 3) * 2;
#pragma unroll
    for (int mi = 0; mi < 2; mi++) {
#pragma unroll
        for (int ni = 0; ni < 16; ni++) {
            OutT* cp0 = C + (size_t)(brow + wm + mi * 16 + er) * DM + bcol + ni * 8 + ec;
            OutT* cp1 = cp0 + 8 * DM;
            if constexpr (sizeof(OutT) == 2) {
                *(uint32_t*)cp0 = pack2h(acc[mi][ni][0], acc[mi][ni][1]);
                *(uint32_t*)cp1 = pack2h(acc[mi][ni][2], acc[mi][ni][3]);
            } else {
                *(float2*)cp0 = make_float2(acc[mi][ni][0], acc[mi][ni][1]);
                *(float2*)cp1 = make_float2(acc[mi][ni][2], acc[mi][ni][3]);
            }
        }
    }
}

// Fused QKV: grid (24, 64); blockIdx.x>>3 selects matrix.
__global__ __launch_bounds__(128, 2) void gemm_qkv(
    const __half* __restrict__ Ax,
    const __half* __restrict__ Bq, const __half* __restrict__ Bk,
    const __half* __restrict__ Bv,
    __half* __restrict__ Cq, __half* __restrict__ Ck, __half* __restrict__ Cv)
{
    extern __shared__ __align__(16) char smem[];
    const int which = blockIdx.x >> 3;
    const int bcol  = (blockIdx.x & 7) * 128;
    const int brow  = blockIdx.y * 128;
    const __half* B = (which == 0) ? Bq : ((which == 1) ? Bk : Bv);
    __half* Co = (which == 0) ? Cq : ((which == 1) ? Ck : Cv);
    gemm_core<__half>(Ax, B, Co, brow, bcol, smem);
}

// Wo: grid (8, 64), fp32 out.
__global__ __launch_bounds__(128, 2) void gemm_ao(
    const __half* __restrict__ Aa, const __half* __restrict__ B,
    float* __restrict__ Cf)
{
    extern __shared__ __align__(16) char smem[];
    gemm_core<float>(Aa, B, Cf, blockIdx.y * 128, blockIdx.x * 128, smem);
}

// ---------------------------------------------------------------------------
// Tensor-core witness encoder: E = tanh(X_head @ Wenc_head) * scale.
// grid (ROWS/128, NH, 2): z=0 -> Q path (SCALE*LOG2E folded), z=1 -> K path.
// ---------------------------------------------------------------------------
__global__ __launch_bounds__(256) void enc3_kernel(
    const __half* __restrict__ Qh, const __half* __restrict__ Kh,
    const float* __restrict__ Wenc,
    __half* __restrict__ QE, __half* __restrict__ KE)
{
    __shared__ __align__(16) __half sX[128 * 72];   // 18 KB
    __shared__ __align__(16) __half sW[64 * 40];    // 5 KB

    const int tid  = threadIdx.x;
    const int wid  = tid >> 5;
    const int lane = tid & 31;
    const int h    = blockIdx.y;
    const int row0 = blockIdx.x * 128;
    const int z    = blockIdx.z;

    const __half* X = z ? Kh : Qh;
    __half* E = z ? KE : QE;
    const float scale = z ? 1.0f : (SCALE * LOG2E);

#pragma unroll
    for (int i = 0; i < 4; i++) {
        int idx = tid + i * 256;
        int r = idx >> 3;
        int c = (idx & 7) << 3;
        *(uint4*)&sX[r * 72 + c] =
            *(const uint4*)&X[(size_t)(row0 + r) * DM + h * HD + c];
    }
#pragma unroll
    for (int i = 0; i < 4; i++) {
        int idx = tid + i * 256;
        int d = idx >> 4;
        int m = (idx & 15) * 2;
        float2 w = *(const float2*)&Wenc[(size_t)h * HD * MB + d * MB + m];
        *(uint32_t*)&sW[d * 40 + m] = pack2h(w.x, w.y);
    }
    __syncthreads();

    const int wm = wid * 16;
    const int fr = lane & 15;
    const int fc = (lane >> 4) << 3;

    float acc[4][4];
#pragma unroll
    for (int nt = 0; nt < 4; nt++)
#pragma unroll
        for (int j = 0; j < 4; j++) acc[nt][j] = 0.f;

#pragma unroll
    for (int kc = 0; kc < 4; kc++) {
        uint32_t a[4];
        ldmx4(a[0], a[1], a[2], a[3],
              smem_u32(&sX[(wm + fr) * 72 + kc * 16 + fc]));
#pragma unroll
        for (int nb = 0; nb < 2; nb++) {
            uint32_t r0, r1, r2, r3;
            uint32_t b0[2], b1[2];
            ldmx4t(r0, r1, r2, r3,
                   smem_u32(&sW[(kc * 16 + fr) * 40 + nb * 16 + fc]));
            b0[0] = r0; b0[1] = r1; b1[0] = r2; b1[1] = r3;
            mma16816h(acc[nb * 2 + 0], a, b0);
            mma16816h(acc[nb * 2 + 1], a, b1);
        }
    }

    const int er = lane >> 2;
    const int ec = (lane & 3) * 2;
    const size_t r0g = (size_t)(row0 + wm + er);
#pragma unroll
    for (int nt = 0; nt < 4; nt++) {
        int m = nt * 8 + ec;
        *(uint32_t*)&E[(r0g * NH + h) * MB + m] =
            pack2h(tanhf(acc[nt][0]) * scale, tanhf(acc[nt][1]) * scale);
        *(uint32_t*)&E[((r0g + 8) * NH + h) * MB + m] =
            pack2h(tanhf(acc[nt][2]) * scale, tanhf(acc[nt][3]) * scale);
    }
}

// ---------------------------------------------------------------------------
// Tensor-core flash attention, 128 threads / 4 warps x 32 q-rows each.
// scores arrive as s*log2e; p = ex2.approx.f16x2; row-sums via CONSTANT
// ones fragment (hoisted out of the mainloop).
// 3-stage cp.async ring, one barrier per 128-key tile. 2 CTAs/SM.
// ---------------------------------------------------------------------------
#define AK 40
#define AV 72
#define ATTN_STAGE ((128 * AK + 128 * AV) * 2)    // 28672 bytes
#define ATTN_SMEM (3 * ATTN_STAGE)                // 86016 bytes

__global__ __launch_bounds__(128, 2) void attn_tc(
    const __half* __restrict__ QEf, const __half* __restrict__ KEf,
    const __half* __restrict__ Vf, __half* __restrict__ AOf)
{
    extern __shared__ __align__(16) char smem[];

    const int tid  = threadIdx.x;
    const int wid  = tid >> 5;
    const int lane = tid & 31;
    const int h = blockIdx.y;
    const int b = blockIdx.z;
    const size_t base = (size_t)b * SEQ;
    const int q0 = blockIdx.x * 128;
    const int wm = wid * 32;                 // 32 q rows per warp
    const int fr = lane & 15;
    const int fc = (lane >> 4) << 3;
    const int gid = lane >> 2;
    const int tig = lane & 3;

    auto bufK = [&](int s) -> __half* {
        return (__half*)(smem + (size_t)s * ATTN_STAGE);
    };
    auto bufV = [&](int s) -> __half* {
        return (__half*)(smem + (size_t)s * ATTN_STAGE) + 128 * AK;
    };
    auto stage = [&](int s, int kt) {
        const int k0 = kt * 128;
        __half* sK = bufK(s);
        __half* sV = bufV(s);
#pragma unroll
        for (int i = 0; i < 4; i++) {
            int c = tid + i * 128;          // 0..511
            int row = c >> 2;
            int part = (c & 3) << 3;
            cp16(smem_u32(sK + row * AK + part),
                 KEf + (base + k0 + row) * (NH * MB) + h * MB + part);
        }
#pragma unroll
        for (int i = 0; i < 8; i++) {
            int c = tid + i * 128;          // 0..1023
            int row = c >> 3;
            int part = (c & 7) << 3;
            cp16(smem_u32(sV + row * AV + part),
                 Vf + (base + k0 + row) * DM + h * HD + part);
        }
    };

    // ---- stage Q into buffer 0's K region; plant ones rows 0..15 in V buf 0 ----
    {
        __half* sQ = bufK(0);
#pragma unroll
        for (int i = 0; i < 4; i++) {
            int c = tid + i * 128;
            int row = c >> 2;
            int part = (c & 3) << 3;
            size_t g = (base + q0 + row) * (NH * MB) + h * MB + part;
            *(uint4*)&sQ[row * AK + part] = *(const uint4*)&QEf[g];
        }
        if (tid < 16) {
            uint4 ones = make_uint4(0x00003C00u, 0u, 0u, 0u);
            *(uint4*)&bufV(0)[tid * AV + 64] = ones;
        }
    }
    __syncthreads();
    uint32_t qh[2][2][4];                    // [mi][kc]
    uint32_t bo[2];                          // constant ones fragment
    {
        __half* sQ = bufK(0);
#pragma unroll
        for (int mi = 0; mi < 2; mi++)
#pragma unroll
            for (int kc = 0; kc < 2; kc++)
                ldmx4(qh[mi][kc][0], qh[mi][kc][1], qh[mi][kc][2], qh[mi][kc][3],
                      smem_u32(&sQ[(wm + mi * 16 + fr) * AK + kc * 16 + fc]));
        ldmx2t(bo[0], bo[1], smem_u32(&bufV(0)[fr * AV + 64]));
    }
    __syncthreads();

    float oacc[2][8][4];
#pragma unroll
    for (int mi = 0; mi < 2; mi++)
#pragma unroll
        for (int nt = 0; nt < 8; nt++)
#pragma unroll
            for (int j = 0; j < 4; j++) oacc[mi][nt][j] = 0.f;
    float lacc[2][4];
#pragma unroll
    for (int mi = 0; mi < 2; mi++)
#pragma unroll
        for (int j = 0; j < 4; j++) lacc[mi][j] = 0.f;

    stage(0, 0); cp_commit();
    stage(1, 1); cp_commit();

    for (int kt = 0; kt < 16; kt++) {
        if (kt < 15) cp_wait<1>(); else cp_wait<0>();
        __syncthreads();
        if (kt < 14) { stage((kt + 2) % 3, kt + 2); cp_commit(); }

        const int cur = kt % 3;
        __half* sK = bufK(cur);
        __half* sV = bufV(cur);

#pragma unroll
        for (int g8 = 0; g8 < 8; g8++) {
            // ---- scores: 2 m-frags x 2 n-tiles ----
            float sa[2][2][4];
#pragma unroll
            for (int mi = 0; mi < 2; mi++)
#pragma unroll
                for (int nt = 0; nt < 2; nt++)
#pragma unroll
                    for (int j = 0; j < 4; j++) sa[mi][nt][j] = 0.f;
#pragma unroll
            for (int kc = 0; kc < 2; kc++) {
                uint32_t r0, r1, r2, r3;
                uint32_t b0[2], b1[2];
                ldmx4(r0, r1, r2, r3,
                      smem_u32(&sK[(g8 * 16 + fr) * AK + kc * 16 + fc]));
                b0[0] = r0; b0[1] = r2; b1[0] = r1; b1[1] = r3;
#pragma unroll
                for (int mi = 0; mi < 2; mi++) {
                    mma16816h(sa[mi][0], qh[mi][kc], b0);
                    mma16816h(sa[mi][1], qh[mi][kc], b1);
                }
            }
            // ---- p = 2^(s*log2e) in fp16x2 ----
            uint32_t ph[2][4];
#pragma unroll
            for (int mi = 0; mi < 2; mi++) {
                ph[mi][0] = h2exp2u(pack2h(sa[mi][0][0], sa[mi][0][1]));
                ph[mi][1] = h2exp2u(pack2h(sa[mi][0][2], sa[mi][0][3]));
                ph[mi][2] = h2exp2u(pack2h(sa[mi][1][0], sa[mi][1][1]));
                ph[mi][3] = h2exp2u(pack2h(sa[mi][1][2], sa[mi][1][3]));
            }
            // ---- P x V ----
#pragma unroll
            for (int nb = 0; nb < 4; nb++) {
                uint32_t r0, r1, r2, r3;
                uint32_t v0[2], v1[2];
                ldmx4t(r0, r1, r2, r3,
                       smem_u32(&sV[(g8 * 16 + fr) * AV + nb * 16 + fc]));
                v0[0] = r0; v0[1] = r1; v1[0] = r2; v1[1] = r3;
#pragma unroll
                for (int mi = 0; mi < 2; mi++) {
                    mma16816h(oacc[mi][nb * 2 + 0], ph[mi], v0);
                    mma16816h(oacc[mi][nb * 2 + 1], ph[mi], v1);
                }
            }
            // ---- P x constant ones fragment -> row sums ----
#pragma unroll
            for (int mi = 0; mi < 2; mi++)
                mma16816h(lacc[mi], ph[mi], bo);
        }
    }

#pragma unroll
    for (int mi = 0; mi < 2; mi++) {
        const float lr  = __shfl_sync(0xffffffffu, lacc[mi][0], gid * 4);
        const float lr8 = __shfl_sync(0xffffffffu, lacc[mi][2], gid * 4);
        const float inv  = 1.f / lr;
        const float inv8 = 1.f / lr8;
        const size_t row0 = base + q0 + wm + mi * 16 + gid;
#pragma unroll
        for (int nt = 0; nt < 8; nt++) {
            int col = h * HD + nt * 8 + tig * 2;
            *(uint32_t*)&AOf[row0 * DM + col] =
                pack2h(oacc[mi][nt][0] * inv, oacc[mi][nt][1] * inv);
            *(uint32_t*)&AOf[(row0 + 8) * DM + col] =
                pack2h(oacc[mi][nt][2] * inv8, oacc[mi][nt][3] * inv8);
        }
    }
}

// ---------------------------------------------------------------------------
// Launch
// ---------------------------------------------------------------------------
extern "C" void kernel_launch(void* const* d_in, const int* in_sizes, int n_in,
                              void* d_out, int out_size)
{
    const float* x    = (const float*)d_in[0];
    const float* Wq   = (const float*)d_in[1];
    const float* Wk   = (const float*)d_in[2];
    const float* Wv   = (const float*)d_in[3];
    const float* Wenc = (const float*)d_in[4];
    const float* Wo   = (const float*)d_in[5];
    float* out = (float*)d_out;

    __half *Qh, *Kh, *Vf, *xf, *AOf, *QEf, *KEf;
    __half *Wqf, *Wkf, *Wvf, *Wof;
    cudaGetSymbolAddress((void**)&Qh,  g_Qh);
    cudaGetSymbolAddress((void**)&Kh,  g_Kh);
    cudaGetSymbolAddress((void**)&Vf,  g_Vf);
    cudaGetSymbolAddress((void**)&xf,  g_xf);
    cudaGetSymbolAddress((void**)&AOf, g_AOf);
    cudaGetSymbolAddress((void**)&QEf, g_QEf);
    cudaGetSymbolAddress((void**)&KEf, g_KEf);
    cudaGetSymbolAddress((void**)&Wqf, g_Wqf);
    cudaGetSymbolAddress((void**)&Wkf, g_Wkf);
    cudaGetSymbolAddress((void**)&Wvf, g_Wvf);
    cudaGetSymbolAddress((void**)&Wof, g_Wof);

    static bool init = false;
    if (!init) {
        cudaFuncSetAttribute(gemm_qkv, cudaFuncAttributeMaxDynamicSharedMemorySize,
                             GEMM_SMEM);
        cudaFuncSetAttribute(gemm_ao, cudaFuncAttributeMaxDynamicSharedMemorySize,
                             GEMM_SMEM);
        cudaFuncSetAttribute(attn_tc, cudaFuncAttributeMaxDynamicSharedMemorySize,
                             ATTN_SMEM);
        init = true;
    }

    conv_all<<<CONV_BLOCKS, 256>>>(x, Wq, Wk, Wv, Wo,
                                   xf, Wqf, Wkf, Wvf, Wof);

    dim3 gQKV(3 * DM / 128, ROWS_TOTAL / 128);   // (24, 64)
    gemm_qkv<<<gQKV, 128, GEMM_SMEM>>>(xf, Wqf, Wkf, Wvf, Qh, Kh, Vf);

    dim3 gEnc(ROWS_TOTAL / 128, NH, 2);          // (64, 16, 2)
    enc3_kernel<<<gEnc, 256>>>(Qh, Kh, Wenc, QEf, KEf);

    dim3 gAttn(SEQ / 128, NH, BSZ);              // (16, 16, 4)
    attn_tc<<<gAttn, 128, ATTN_SMEM>>>(QEf, KEf, Vf, AOf);

    dim3 gWo(DM / 128, ROWS_TOTAL / 128);        // (8, 64)
    gemm_ao<<<gWo, 128, GEMM_SMEM>>>(AOf, Wof, out);
}

// round 15
// speedup vs baseline: 10.7675x; 1.0162x over previous
#include <cuda_runtime.h>
#include <cuda_bf16.h>
#include <cuda_fp16.h>
#include <math.h>
#include <stdint.h>

// Problem constants
#define BSZ 4
#define SEQ 2048
#define DM 1024
#define NH 16
#define HD 64
#define MB 32
#define ROWS_TOTAL (BSZ * SEQ)          // 8192
#define SCALE 0.17677669529663687f      // 1/sqrt(32)
#define LOG2E 1.4426950408889634f

// ---------------------------------------------------------------------------
// Scratch (no allocations allowed -> __device__ globals)
// ---------------------------------------------------------------------------
__device__ __align__(16) __half g_Vf[ROWS_TOTAL * DM];
__device__ __align__(16) __half g_xf[ROWS_TOTAL * DM];
__device__ __align__(16) __half g_AOf[ROWS_TOTAL * DM];
__device__ __align__(16) __half g_QEf[ROWS_TOTAL * NH * MB];
__device__ __align__(16) __half g_KEf[ROWS_TOTAL * NH * MB];
__device__ __align__(16) __half g_Wqf[DM * DM];
__device__ __align__(16) __half g_Wkf[DM * DM];
__device__ __align__(16) __half g_Wvf[DM * DM];
__device__ __align__(16) __half g_Wof[DM * DM];

// ---------------------------------------------------------------------------
// Helpers
// ---------------------------------------------------------------------------
static __device__ __forceinline__ uint32_t smem_u32(const void* p) {
    return (uint32_t)__cvta_generic_to_shared(p);
}

static __device__ __forceinline__ uint32_t pack2h(float a, float b) {
    __half2 t = __floats2half2_rn(a, b);
    return *(uint32_t*)&t;
}

static __device__ __forceinline__ uint32_t h2exp2u(uint32_t x) {
    uint32_t r;
    asm volatile("ex2.approx.f16x2 %0, %1;" : "=r"(r) : "r"(x));
    return r;
}

static __device__ __forceinline__ void ldmx4(uint32_t& r0, uint32_t& r1,
                                             uint32_t& r2, uint32_t& r3,
                                             uint32_t addr) {
    asm volatile("ldmatrix.sync.aligned.m8n8.x4.shared.b16 {%0,%1,%2,%3}, [%4];"
                 : "=r"(r0), "=r"(r1), "=r"(r2), "=r"(r3) : "r"(addr));
}

static __device__ __forceinline__ void ldmx4t(uint32_t& r0, uint32_t& r1,
                                              uint32_t& r2, uint32_t& r3,
                                              uint32_t addr) {
    asm volatile("ldmatrix.sync.aligned.m8n8.x4.trans.shared.b16 {%0,%1,%2,%3}, [%4];"
                 : "=r"(r0), "=r"(r1), "=r"(r2), "=r"(r3) : "r"(addr));
}

static __device__ __forceinline__ void ldmx2t(uint32_t& r0, uint32_t& r1,
                                              uint32_t addr) {
    asm volatile("ldmatrix.sync.aligned.m8n8.x2.trans.shared.b16 {%0,%1}, [%2];"
                 : "=r"(r0), "=r"(r1) : "r"(addr));
}

static __device__ __forceinline__ void mma16816h(float* d, const uint32_t* a,
                                                 const uint32_t* b) {
    asm volatile(
        "mma.sync.aligned.m16n8k16.row.col.f32.f16.f16.f32 "
        "{%0,%1,%2,%3}, {%4,%5,%6,%7}, {%8,%9}, {%0,%1,%2,%3};"
        : "+f"(d[0]), "+f"(d[1]), "+f"(d[2]), "+f"(d[3])
        : "r"(a[0]), "r"(a[1]), "r"(a[2]), "r"(a[3]), "r"(b[0]), "r"(b[1]));
}

static __device__ __forceinline__ void cp16(uint32_t dst, const void* src) {
    asm volatile("cp.async.cg.shared.global [%0], [%1], 16;" :: "r"(dst), "l"(src));
}
static __device__ __forceinline__ void cp_commit() {
    asm volatile("cp.async.commit_group;");
}
template<int N> static __device__ __forceinline__ void cp_wait() {
    asm volatile("cp.async.wait_group %0;" :: "n"(N));
}

// ---------------------------------------------------------------------------
// Fused fp32 -> fp16 conversion: 4 weight matrices + x in ONE launch.
// ---------------------------------------------------------------------------
#define CONV_BLOCKS (4 * 1024 + 8192)    // 12288

__global__ __launch_bounds__(256) void conv_all(
    const float* __restrict__ x,
    const float* __restrict__ w0, const float* __restrict__ w1,
    const float* __restrict__ w2, const float* __restrict__ w3,
    __half* __restrict__ xf,
    __half* __restrict__ d0, __half* __restrict__ d1,
    __half* __restrict__ d2, __half* __restrict__ d3)
{
    int blk = blockIdx.x;
    const float* s; __half* d; int i;
    if (blk < 4096) {
        int w = blk >> 10;
        s = (w == 0) ? w0 : (w == 1) ? w1 : (w == 2) ? w2 : w3;
        d = (w == 0) ? d0 : (w == 1) ? d1 : (w == 2) ? d2 : d3;
        i = (blk & 1023) * 256 + threadIdx.x;
    } else {
        s = x; d = xf;
        i = (blk - 4096) * 256 + threadIdx.x;
    }
    float4 v = ((const float4*)s)[i];
    uint2 o;
    o.x = pack2h(v.x, v.y);
    o.y = pack2h(v.z, v.w);
    ((uint2*)d)[i] = o;
}

// ---------------------------------------------------------------------------
// GEMM geometry: 128 threads / 4 warps, warp tile 32x128, CTA tile 128x128,
// BK=64, 2-stage cp.async ring, one barrier per K-iter.
// ---------------------------------------------------------------------------
#define GKP 72
#define GEMM_SMEM (2 * 2 * 128 * GKP * 2)   // 73728 bytes

// ---------------------------------------------------------------------------
// Fused QKV GEMM + witness encoder.
// grid (24, 64): which = blockIdx.x>>3 selects {Q, K, V}.
//   which==2: write V tile (fp16) to gmem.
//   which<2 : tile covers 2 complete heads -> run encoder in-epilogue,
//             write QE/KE directly (Q/K never touch gmem).
// ---------------------------------------------------------------------------
__global__ __launch_bounds__(128, 2) void gemm_qkv_enc(
    const __half* __restrict__ Ax,
    const __half* __restrict__ Bq, const __half* __restrict__ Bk,
    const __half* __restrict__ Bv,
    const float* __restrict__ Wenc,
    __half* __restrict__ QE, __half* __restrict__ KE, __half* __restrict__ Cv)
{
    extern __shared__ __align__(16) char smem[];
    const int tid  = threadIdx.x;
    const int wid  = tid >> 5;
    const int lane = tid & 31;
    const int which = blockIdx.x >> 3;
    const int bcol  = (blockIdx.x & 7) * 128;
    const int brow  = blockIdx.y * 128;
    const int wm   = wid * 32;

    const __half* B = (which == 0) ? Bq : ((which == 1) ? Bk : Bv);

    auto buf = [&](int s, int a) -> __half* {
        return (__half*)smem + (size_t)(s * 2 + a) * 128 * GKP;
    };
    auto stage = [&](int s, int kt) {
#pragma unroll
        for (int i = 0; i < 16; i++) {
            int c = tid + i * 128;          // 0..2047
            int a = c >> 10;                // 0..1
            int cc = c & 1023;
            int row = cc >> 3;
            int part = (cc & 7) << 3;
            const __half* g = (a == 0)
                ? Ax + (size_t)(brow + row) * DM + kt * 64 + part
                : B  + (size_t)(bcol + row) * DM + kt * 64 + part;
            cp16(smem_u32(buf(s, a) + row * GKP + part), g);
        }
    };

    float acc[2][16][4];
#pragma unroll
    for (int mi = 0; mi < 2; mi++)
#pragma unroll
        for (int ni = 0; ni < 16; ni++)
#pragma unroll
            for (int j = 0; j < 4; j++) acc[mi][ni][j] = 0.f;

    const int fr = lane & 15;
    const int fc = (lane >> 4) << 3;

    stage(0, 0); cp_commit();

    for (int kt = 0; kt < 16; kt++) {
        cp_wait<0>();
        __syncthreads();
        if (kt < 15) { stage((kt + 1) & 1, kt + 1); cp_commit(); }

        const int cur = kt & 1;
        const __half* pA = buf(cur, 0);
        const __half* pB = buf(cur, 1);

#pragma unroll
        for (int ks = 0; ks < 4; ks++) {
            const int kof = ks * 16 + fc;
            uint32_t a[2][4];
#pragma unroll
            for (int mi = 0; mi < 2; mi++)
                ldmx4(a[mi][0], a[mi][1], a[mi][2], a[mi][3],
                      smem_u32(pA + (wm + mi * 16 + fr) * GKP + kof));
            uint32_t b[16][2];
#pragma unroll
            for (int nq = 0; nq < 8; nq++) {
                uint32_t r0, r1, r2, r3;
                ldmx4(r0, r1, r2, r3, smem_u32(pB + (nq * 16 + fr) * GKP + kof));
                b[nq * 2 + 0][0] = r0; b[nq * 2 + 0][1] = r2;
                b[nq * 2 + 1][0] = r1; b[nq * 2 + 1][1] = r3;
            }
#pragma unroll
            for (int mi = 0; mi < 2; mi++)
#pragma unroll
                for (int ni = 0; ni < 16; ni++)
                    mma16816h(acc[mi][ni], a[mi], b[ni]);
        }
    }

    const int er = lane >> 2;
    const int ec = (lane & 3) * 2;

    if (which == 2) {
        // ---- V epilogue: direct fp16 store ----
#pragma unroll
        for (int mi = 0; mi < 2; mi++) {
#pragma unroll
            for (int ni = 0; ni < 16; ni++) {
                __half* cp0 = Cv + (size_t)(brow + wm + mi * 16 + er) * DM + bcol + ni * 8 + ec;
                *(uint32_t*)cp0 = pack2h(acc[mi][ni][0], acc[mi][ni][1]);
                __half* cp1 = cp0 + 8 * DM;
                *(uint32_t*)cp1 = pack2h(acc[mi][ni][2], acc[mi][ni][3]);
            }
        }
        return;
    }

    // ---- Q/K epilogue: fused encoder, tile = heads hA, hA+1 ----
    __half* E = (which == 0) ? QE : KE;
    const float scale = (which == 0) ? (SCALE * LOG2E) : 1.0f;
    const int hA = bcol >> 6;

    __half* sX = (__half*)smem;                   // 128 x 136 (34816 B)
    __half* sW = (__half*)smem + 128 * 136;       // 2 x 64 x 40 (10240 B)

    __syncthreads();    // stage buffers dead; about to overwrite

    // store acc -> sX (fp16), stride 136 halves (conflict-free)
#pragma unroll
    for (int mi = 0; mi < 2; mi++) {
#pragma unroll
        for (int ni = 0; ni < 16; ni++) {
            int col = ni * 8 + ec;
            *(uint32_t*)&sX[(wm + mi * 16 + er) * 136 + col] =
                pack2h(acc[mi][ni][0], acc[mi][ni][1]);
            *(uint32_t*)&sX[(wm + mi * 16 + er + 8) * 136 + col] =
                pack2h(acc[mi][ni][2], acc[mi][ni][3]);
        }
    }
    // load Wenc for the 2 heads -> sW (fp32 -> fp16)
#pragma unroll
    for (int i = 0; i < 16; i++) {
        int idx = tid + i * 128;        // 0..2047
        int hh = idx >> 10;
        int rem = idx & 1023;
        int d = rem >> 4;
        int m = (rem & 15) * 2;
        float2 w = *(const float2*)&Wenc[(size_t)(hA + hh) * HD * MB + d * MB + m];
        *(uint32_t*)&sW[hh * 2560 + d * 40 + m] = pack2h(w.x, w.y);
    }
    __syncthreads();

#pragma unroll
    for (int hh = 0; hh < 2; hh++) {
        float eacc[2][4][4];
#pragma unroll
        for (int mi = 0; mi < 2; mi++)
#pragma unroll
            for (int nt = 0; nt < 4; nt++)
#pragma unroll
                for (int j = 0; j < 4; j++) eacc[mi][nt][j] = 0.f;

#pragma unroll
        for (int kc = 0; kc < 4; kc++) {
            uint32_t a[2][4];
#pragma unroll
            for (int mi = 0; mi < 2; mi++)
                ldmx4(a[mi][0], a[mi][1], a[mi][2], a[mi][3],
                      smem_u32(&sX[(wm + mi * 16 + fr) * 136 + hh * 64 + kc * 16 + fc]));
#pragma unroll
            for (int nb = 0; nb < 2; nb++) {
                uint32_t r0, r1, r2, r3;
                uint32_t b0[2], b1[2];
                ldmx4t(r0, r1, r2, r3,
                       smem_u32(&sW[hh * 2560 + (kc * 16 + fr) * 40 + nb * 16 + fc]));
                b0[0] = r0; b0[1] = r1; b1[0] = r2; b1[1] = r3;
#pragma unroll
                for (int mi = 0; mi < 2; mi++) {
                    mma16816h(eacc[mi][nb * 2 + 0], a[mi], b0);
                    mma16816h(eacc[mi][nb * 2 + 1], a[mi], b1);
                }
            }
        }

        const int h = hA + hh;
#pragma unroll
        for (int mi = 0; mi < 2; mi++) {
            const size_t r0g = (size_t)(brow + wm + mi * 16 + er);
#pragma unroll
            for (int nt = 0; nt < 4; nt++) {
                int m = nt * 8 + ec;
                *(uint32_t*)&E[(r0g * NH + h) * MB + m] =
                    pack2h(tanhf(eacc[mi][nt][0]) * scale,
                           tanhf(eacc[mi][nt][1]) * scale);
                *(uint32_t*)&E[((r0g + 8) * NH + h) * MB + m] =
                    pack2h(tanhf(eacc[mi][nt][2]) * scale,
                           tanhf(eacc[mi][nt][3]) * scale);
            }
        }
    }
}

// ---------------------------------------------------------------------------
// AO @ Wo^T GEMM, 1-term fp16, fp32 out. Same mainloop, plain epilogue.
// ---------------------------------------------------------------------------
__global__ __launch_bounds__(128, 2) void gemm_ao(
    const __half* __restrict__ Aa, const __half* __restrict__ B,
    float* __restrict__ Cf)
{
    extern __shared__ __align__(16) char smem[];
    const int tid  = threadIdx.x;
    const int wid  = tid >> 5;
    const int lane = tid & 31;
    const int brow = blockIdx.y * 128;
    const int bcol = blockIdx.x * 128;
    const int wm   = wid * 32;

    auto buf = [&](int s, int a) -> __half* {
        return (__half*)smem + (size_t)(s * 2 + a) * 128 * GKP;
    };
    auto stage = [&](int s, int kt) {
#pragma unroll
        for (int i = 0; i < 16; i++) {
            int c = tid + i * 128;
            int a = c >> 10;
            int cc = c & 1023;
            int row = cc >> 3;
            int part = (cc & 7) << 3;
            const __half* g = (a == 0)
                ? Aa + (size_t)(brow + row) * DM + kt * 64 + part
                : B  + (size_t)(bcol + row) * DM + kt * 64 + part;
            cp16(smem_u32(buf(s, a) + row * GKP + part), g);
        }
    };

    float acc[2][16][4];
#pragma unroll
    for (int mi = 0; mi < 2; mi++)
#pragma unroll
        for (int ni = 0; ni < 16; ni++)
#pragma unroll
            for (int j = 0; j < 4; j++) acc[mi][ni][j] = 0.f;

    const int fr = lane & 15;
    const int fc = (lane >> 4) << 3;

    stage(0, 0); cp_commit();

    for (int kt = 0; kt < 16; kt++) {
        cp_wait<0>();
        __syncthreads();
        if (kt < 15) { stage((kt + 1) & 1, kt + 1); cp_commit(); }

        const int cur = kt & 1;
        const __half* pA = buf(cur, 0);
        const __half* pB = buf(cur, 1);

#pragma unroll
        for (int ks = 0; ks < 4; ks++) {
            const int kof = ks * 16 + fc;
            uint32_t a[2][4];
#pragma unroll
            for (int mi = 0; mi < 2; mi++)
                ldmx4(a[mi][0], a[mi][1], a[mi][2], a[mi][3],
                      smem_u32(pA + (wm + mi * 16 + fr) * GKP + kof));
            uint32_t b[16][2];
#pragma unroll
            for (int nq = 0; nq < 8; nq++) {
                uint32_t r0, r1, r2, r3;
                ldmx4(r0, r1, r2, r3, smem_u32(pB + (nq * 16 + fr) * GKP + kof));
                b[nq * 2 + 0][0] = r0; b[nq * 2 + 0][1] = r2;
                b[nq * 2 + 1][0] = r1; b[nq * 2 + 1][1] = r3;
            }
#pragma unroll
            for (int mi = 0; mi < 2; mi++)
#pragma unroll
                for (int ni = 0; ni < 16; ni++)
                    mma16816h(acc[mi][ni], a[mi], b[ni]);
        }
    }

    const int er = lane >> 2;
    const int ec = (lane & 3) * 2;
#pragma unroll
    for (int mi = 0; mi < 2; mi++) {
#pragma unroll
        for (int ni = 0; ni < 16; ni++) {
            float* cp0 = Cf + (size_t)(brow + wm + mi * 16 + er) * DM + bcol + ni * 8 + ec;
            *(float2*)cp0 = make_float2(acc[mi][ni][0], acc[mi][ni][1]);
            float* cp1 = cp0 + 8 * DM;
            *(float2*)cp1 = make_float2(acc[mi][ni][2], acc[mi][ni][3]);
        }
    }
}

// ---------------------------------------------------------------------------
// Tensor-core flash attention, 128 threads / 4 warps x 32 q-rows each.
// scores arrive as s*log2e; p = ex2.approx.f16x2; row-sums via CONSTANT
// ones fragment. 3-stage cp.async ring, one barrier per 128-key tile.
// ---------------------------------------------------------------------------
#define AK 40
#define AV 72
#define ATTN_STAGE ((128 * AK + 128 * AV) * 2)    // 28672 bytes
#define ATTN_SMEM (3 * ATTN_STAGE)                // 86016 bytes

__global__ __launch_bounds__(128, 2) void attn_tc(
    const __half* __restrict__ QEf, const __half* __restrict__ KEf,
    const __half* __restrict__ Vf, __half* __restrict__ AOf)
{
    extern __shared__ __align__(16) char smem[];

    const int tid  = threadIdx.x;
    const int wid  = tid >> 5;
    const int lane = tid & 31;
    const int h = blockIdx.y;
    const int b = blockIdx.z;
    const size_t base = (size_t)b * SEQ;
    const int q0 = blockIdx.x * 128;
    const int wm = wid * 32;
    const int fr = lane & 15;
    const int fc = (lane >> 4) << 3;
    const int gid = lane >> 2;
    const int tig = lane & 3;

    auto bufK = [&](int s) -> __half* {
        return (__half*)(smem + (size_t)s * ATTN_STAGE);
    };
    auto bufV = [&](int s) -> __half* {
        return (__half*)(smem + (size_t)s * ATTN_STAGE) + 128 * AK;
    };
    auto stage = [&](int s, int kt) {
        const int k0 = kt * 128;
        __half* sK = bufK(s);
        __half* sV = bufV(s);
#pragma unroll
        for (int i = 0; i < 4; i++) {
            int c = tid + i * 128;
            int row = c >> 2;
            int part = (c & 3) << 3;
            cp16(smem_u32(sK + row * AK + part),
                 KEf + (base + k0 + row) * (NH * MB) + h * MB + part);
        }
#pragma unroll
        for (int i = 0; i < 8; i++) {
            int c = tid + i * 128;
            int row = c >> 3;
            int part = (c & 7) << 3;
            cp16(smem_u32(sV + row * AV + part),
                 Vf + (base + k0 + row) * DM + h * HD + part);
        }
    };

    // ---- stage Q into buffer 0's K region; plant ones rows 0..15 in V buf 0 ----
    {
        __half* sQ = bufK(0);
#pragma unroll
        for (int i = 0; i < 4; i++) {
            int c = tid + i * 128;
            int row = c >> 2;
            int part = (c & 3) << 3;
            size_t g = (base + q0 + row) * (NH * MB) + h * MB + part;
            *(uint4*)&sQ[row * AK + part] = *(const uint4*)&QEf[g];
        }
        if (tid < 16) {
            uint4 ones = make_uint4(0x00003C00u, 0u, 0u, 0u);
            *(uint4*)&bufV(0)[tid * AV + 64] = ones;
        }
    }
    __syncthreads();
    uint32_t qh[2][2][4];
    uint32_t bo[2];
    {
        __half* sQ = bufK(0);
#pragma unroll
        for (int mi = 0; mi < 2; mi++)
#pragma unroll
            for (int kc = 0; kc < 2; kc++)
                ldmx4(qh[mi][kc][0], qh[mi][kc][1], qh[mi][kc][2], qh[mi][kc][3],
                      smem_u32(&sQ[(wm + mi * 16 + fr) * AK + kc * 16 + fc]));
        ldmx2t(bo[0], bo[1], smem_u32(&bufV(0)[fr * AV + 64]));
    }
    __syncthreads();

    float oacc[2][8][4];
#pragma unroll
    for (int mi = 0; mi < 2; mi++)
#pragma unroll
        for (int nt = 0; nt < 8; nt++)
#pragma unroll
            for (int j = 0; j < 4; j++) oacc[mi][nt][j] = 0.f;
    float lacc[2][4];
#pragma unroll
    for (int mi = 0; mi < 2; mi++)
#pragma unroll
        for (int j = 0; j < 4; j++) lacc[mi][j] = 0.f;

    stage(0, 0); cp_commit();
    stage(1, 1); cp_commit();

    for (int kt = 0; kt < 16; kt++) {
        if (kt < 15) cp_wait<1>(); else cp_wait<0>();
        __syncthreads();
        if (kt < 14) { stage((kt + 2) % 3, kt + 2); cp_commit(); }

        const int cur = kt % 3;
        __half* sK = bufK(cur);
        __half* sV = bufV(cur);

#pragma unroll
        for (int g8 = 0; g8 < 8; g8++) {
            float sa[2][2][4];
#pragma unroll
            for (int mi = 0; mi < 2; mi++)
#pragma unroll
                for (int nt = 0; nt < 2; nt++)
#pragma unroll
                    for (int j = 0; j < 4; j++) sa[mi][nt][j] = 0.f;
#pragma unroll
            for (int kc = 0; kc < 2; kc++) {
                uint32_t r0, r1, r2, r3;
                uint32_t b0[2], b1[2];
                ldmx4(r0, r1, r2, r3,
                      smem_u32(&sK[(g8 * 16 + fr) * AK + kc * 16 + fc]));
                b0[0] = r0; b0[1] = r2; b1[0] = r1; b1[1] = r3;
#pragma unroll
                for (int mi = 0; mi < 2; mi++) {
                    mma16816h(sa[mi][0], qh[mi][kc], b0);
                    mma16816h(sa[mi][1], qh[mi][kc], b1);
                }
            }
            uint32_t ph[2][4];
#pragma unroll
            for (int mi = 0; mi < 2; mi++) {
                ph[mi][0] = h2exp2u(pack2h(sa[mi][0][0], sa[mi][0][1]));
                ph[mi][1] = h2exp2u(pack2h(sa[mi][0][2], sa[mi][0][3]));
                ph[mi][2] = h2exp2u(pack2h(sa[mi][1][0], sa[mi][1][1]));
                ph[mi][3] = h2exp2u(pack2h(sa[mi][1][2], sa[mi][1][3]));
            }
#pragma unroll
            for (int nb = 0; nb < 4; nb++) {
                uint32_t r0, r1, r2, r3;
                uint32_t v0[2], v1[2];
                ldmx4t(r0, r1, r2, r3,
                       smem_u32(&sV[(g8 * 16 + fr) * AV + nb * 16 + fc]));
                v0[0] = r0; v0[1] = r1; v1[0] = r2; v1[1] = r3;
#pragma unroll
                for (int mi = 0; mi < 2; mi++) {
                    mma16816h(oacc[mi][nb * 2 + 0], ph[mi], v0);
                    mma16816h(oacc[mi][nb * 2 + 1], ph[mi], v1);
                }
            }
#pragma unroll
            for (int mi = 0; mi < 2; mi++)
                mma16816h(lacc[mi], ph[mi], bo);
        }
    }

#pragma unroll
    for (int mi = 0; mi < 2; mi++) {
        const float lr  = __shfl_sync(0xffffffffu, lacc[mi][0], gid * 4);
        const float lr8 = __shfl_sync(0xffffffffu, lacc[mi][2], gid * 4);
        const float inv  = 1.f / lr;
        const float inv8 = 1.f / lr8;
        const size_t row0 = base + q0 + wm + mi * 16 + gid;
#pragma unroll
        for (int nt = 0; nt < 8; nt++) {
            int col = h * HD + nt * 8 + tig * 2;
            *(uint32_t*)&AOf[row0 * DM + col] =
                pack2h(oacc[mi][nt][0] * inv, oacc[mi][nt][1] * inv);
            *(uint32_t*)&AOf[(row0 + 8) * DM + col] =
                pack2h(oacc[mi][nt][2] * inv8, oacc[mi][nt][3] * inv8);
        }
    }
}

// ---------------------------------------------------------------------------
// Launch
// ---------------------------------------------------------------------------
extern "C" void kernel_launch(void* const* d_in, const int* in_sizes, int n_in,
                              void* d_out, int out_size)
{
    const float* x    = (const float*)d_in[0];
    const float* Wq   = (const float*)d_in[1];
    const float* Wk   = (const float*)d_in[2];
    const float* Wv   = (const float*)d_in[3];
    const float* Wenc = (const float*)d_in[4];
    const float* Wo   = (const float*)d_in[5];
    float* out = (float*)d_out;

    __half *Vf, *xf, *AOf, *QEf, *KEf;
    __half *Wqf, *Wkf, *Wvf, *Wof;
    cudaGetSymbolAddress((void**)&Vf,  g_Vf);
    cudaGetSymbolAddress((void**)&xf,  g_xf);
    cudaGetSymbolAddress((void**)&AOf, g_AOf);
    cudaGetSymbolAddress((void**)&QEf, g_QEf);
    cudaGetSymbolAddress((void**)&KEf, g_KEf);
    cudaGetSymbolAddress((void**)&Wqf, g_Wqf);
    cudaGetSymbolAddress((void**)&Wkf, g_Wkf);
    cudaGetSymbolAddress((void**)&Wvf, g_Wvf);
    cudaGetSymbolAddress((void**)&Wof, g_Wof);

    static bool init = false;
    if (!init) {
        cudaFuncSetAttribute(gemm_qkv_enc, cudaFuncAttributeMaxDynamicSharedMemorySize,
                             GEMM_SMEM);
        cudaFuncSetAttribute(gemm_ao, cudaFuncAttributeMaxDynamicSharedMemorySize,
                             GEMM_SMEM);
        cudaFuncSetAttribute(attn_tc, cudaFuncAttributeMaxDynamicSharedMemorySize,
                             ATTN_SMEM);
        init = true;
    }

    conv_all<<<CONV_BLOCKS, 256>>>(x, Wq, Wk, Wv, Wo,
                                   xf, Wqf, Wkf, Wvf, Wof);

    dim3 gQKV(3 * DM / 128, ROWS_TOTAL / 128);   // (24, 64)
    gemm_qkv_enc<<<gQKV, 128, GEMM_SMEM>>>(xf, Wqf, Wkf, Wvf, Wenc,
                                           QEf, KEf, Vf);

    dim3 gAttn(SEQ / 128, NH, BSZ);              // (16, 16, 4)
    attn_tc<<<gAttn, 128, ATTN_SMEM>>>(QEf, KEf, Vf, AOf);

    dim3 gWo(DM / 128, ROWS_TOTAL / 128);        // (8, 64)
    gemm_ao<<<gWo, 128, GEMM_SMEM>>>(AOf, Wof, out);
}